// round 3
// baseline (speedup 1.0000x reference)
#include <cuda_runtime.h>
#include <math.h>

#define NN      50000
#define NE      1600000
#define IN_DIM  512
#define HID_DIM 256
#define OUT_DIM 64
#define ALPHA   0.1f

// ---------------- static device scratch (no allocations allowed) ----------------
__device__ float g_hidden[(size_t)NN * HID_DIM];   // 51.2 MB
__device__ float g_feat0 [(size_t)NN * OUT_DIM];   // 12.8 MB
__device__ float g_featA [(size_t)NN * OUT_DIM];
__device__ float g_featB [(size_t)NN * OUT_DIM];
__device__ int   g_deg_out[NN];
__device__ int   g_deg_in [NN];
__device__ float g_norm_src[NN];
__device__ float g_norm_dst[NN];
__device__ int   g_ptr [NN + 1];
__device__ int   g_fill[NN];
__device__ int   g_bsum[256];
__device__ int   g_csr_src[NE];
__device__ int   g_csr_eid[NE];
__device__ float g_s[NN];
__device__ float g_d[NN];
__device__ float g_e[NE];

// ---------------- init ----------------
__global__ void init_zero_kernel() {
    int i = blockIdx.x * blockDim.x + threadIdx.x;
    if (i < NN) {
        g_deg_out[i] = 0;
        g_deg_in[i]  = 0;
        g_fill[i]    = 0;
    }
}

// ---------------- degrees ----------------
__global__ void degree_kernel(const int* __restrict__ src, const int* __restrict__ dst) {
    int e = blockIdx.x * blockDim.x + threadIdx.x;
    if (e < NE) {
        atomicAdd(&g_deg_out[src[e]], 1);
        atomicAdd(&g_deg_in [dst[e]], 1);
    }
}

__global__ void norm_kernel() {
    int i = blockIdx.x * blockDim.x + threadIdx.x;
    if (i < NN) {
        g_norm_src[i] = rsqrtf((float)max(g_deg_out[i], 1));
        g_norm_dst[i] = rsqrtf((float)max(g_deg_in [i], 1));
    }
}

// ---------------- exclusive scan of deg_in -> g_ptr (3 kernels) ----------------
__global__ void scan_block_kernel() {
    __shared__ int s[512];
    int tid = threadIdx.x;
    int i = blockIdx.x * 512 + tid;
    int v = (i < NN) ? g_deg_in[i] : 0;
    s[tid] = v;
    __syncthreads();
    #pragma unroll
    for (int off = 1; off < 512; off <<= 1) {
        int t = (tid >= off) ? s[tid - off] : 0;
        __syncthreads();
        s[tid] += t;
        __syncthreads();
    }
    if (i < NN) g_ptr[i] = s[tid] - v;            // block-local exclusive
    if (tid == 511) g_bsum[blockIdx.x] = s[511];  // block total
}

__global__ void scan_bsum_kernel(int nb) {
    __shared__ int s[128];
    int tid = threadIdx.x;
    int v = (tid < nb) ? g_bsum[tid] : 0;
    s[tid] = v;
    __syncthreads();
    #pragma unroll
    for (int off = 1; off < 128; off <<= 1) {
        int t = (tid >= off) ? s[tid - off] : 0;
        __syncthreads();
        s[tid] += t;
        __syncthreads();
    }
    if (tid < nb) g_bsum[tid] = s[tid] - v;       // exclusive in place
}

__global__ void scan_add_kernel() {
    int i = blockIdx.x * blockDim.x + threadIdx.x;
    if (i < NN)       g_ptr[i] += g_bsum[i >> 9];
    else if (i == NN) g_ptr[NN] = NE;
}

// ---------------- CSR fill (dst-sorted edge list) ----------------
__global__ void csr_fill_kernel(const int* __restrict__ src, const int* __restrict__ dst) {
    int e = blockIdx.x * blockDim.x + threadIdx.x;
    if (e < NE) {
        int d = dst[e];
        int pos = g_ptr[d] + atomicAdd(&g_fill[d], 1);
        g_csr_src[pos] = src[e];
        g_csr_eid[pos] = e;
    }
}

// ---------------- SGEMM: C = op(A@B + bias), optional second output ----------------
template <int BM, int BN, int BK, int TM, int TN, bool RELU>
__global__ void sgemm_kernel(const float* __restrict__ A, const float* __restrict__ B,
                             const float* __restrict__ bias,
                             float* __restrict__ C, float* __restrict__ C2,
                             int M, int N, int K) {
    constexpr int THREADS = (BM / TM) * (BN / TN);
    __shared__ float As[BK][BM];
    __shared__ float Bs[BK][BN];

    const int tid  = threadIdx.x;
    const int tcol = tid % (BN / TN);
    const int trow = tid / (BN / TN);
    const int aBase = blockIdx.y * BM;
    const int bBase = blockIdx.x * BN;

    float acc[TM][TN];
    #pragma unroll
    for (int i = 0; i < TM; i++)
        #pragma unroll
        for (int j = 0; j < TN; j++) acc[i][j] = 0.0f;

    for (int k0 = 0; k0 < K; k0 += BK) {
        // A tile (transposed into smem)
        #pragma unroll
        for (int i = tid * 4; i < BM * BK; i += THREADS * 4) {
            int m = i / BK, k = i % BK;
            int gm = aBase + m;
            float4 v = make_float4(0.f, 0.f, 0.f, 0.f);
            if (gm < M) v = *reinterpret_cast<const float4*>(&A[(size_t)gm * K + k0 + k]);
            As[k + 0][m] = v.x; As[k + 1][m] = v.y; As[k + 2][m] = v.z; As[k + 3][m] = v.w;
        }
        // B tile
        #pragma unroll
        for (int i = tid * 4; i < BK * BN; i += THREADS * 4) {
            int k = i / BN, n = i % BN;
            *reinterpret_cast<float4*>(&Bs[k][n]) =
                *reinterpret_cast<const float4*>(&B[(size_t)(k0 + k) * N + bBase + n]);
        }
        __syncthreads();

        #pragma unroll
        for (int k = 0; k < BK; ++k) {
            float areg[TM], breg[TN];
            #pragma unroll
            for (int i = 0; i < TM; i++) areg[i] = As[k][trow * TM + i];
            #pragma unroll
            for (int j = 0; j < TN; j++) breg[j] = Bs[k][tcol * TN + j];
            #pragma unroll
            for (int i = 0; i < TM; i++)
                #pragma unroll
                for (int j = 0; j < TN; j++) acc[i][j] += areg[i] * breg[j];
        }
        __syncthreads();
    }

    #pragma unroll
    for (int i = 0; i < TM; i++) {
        int gm = aBase + trow * TM + i;
        if (gm >= M) continue;
        #pragma unroll
        for (int j = 0; j < TN; j += 4) {
            int gn = bBase + tcol * TN + j;
            float4 r;
            r.x = acc[i][j + 0] + bias[gn + 0];
            r.y = acc[i][j + 1] + bias[gn + 1];
            r.z = acc[i][j + 2] + bias[gn + 2];
            r.w = acc[i][j + 3] + bias[gn + 3];
            if (RELU) {
                r.x = fmaxf(r.x, 0.f); r.y = fmaxf(r.y, 0.f);
                r.z = fmaxf(r.z, 0.f); r.w = fmaxf(r.w, 0.f);
            }
            *reinterpret_cast<float4*>(&C[(size_t)gm * N + gn]) = r;
            if (C2) *reinterpret_cast<float4*>(&C2[(size_t)gm * N + gn]) = r;
        }
    }
}

// ---------------- propagation hop: warp per dst node, CSR gather ----------------
__global__ void prop_kernel(int dir) {
    const float* __restrict__ fin  = dir ? g_featB : g_featA;
    float*       __restrict__ fout = dir ? g_featA : g_featB;

    int wid  = (blockIdx.x * blockDim.x + threadIdx.x) >> 5;
    int lane = threadIdx.x & 31;
    if (wid >= NN) return;

    int beg = g_ptr[wid], end = g_ptr[wid + 1];
    float acc0 = 0.f, acc1 = 0.f;

    int j = beg;
    for (; j + 4 <= end; j += 4) {
        int s0 = g_csr_src[j + 0], s1 = g_csr_src[j + 1];
        int s2 = g_csr_src[j + 2], s3 = g_csr_src[j + 3];
        float w0 = g_norm_src[s0], w1 = g_norm_src[s1];
        float w2 = g_norm_src[s2], w3 = g_norm_src[s3];
        const float* p0 = &fin[(size_t)s0 * OUT_DIM];
        const float* p1 = &fin[(size_t)s1 * OUT_DIM];
        const float* p2 = &fin[(size_t)s2 * OUT_DIM];
        const float* p3 = &fin[(size_t)s3 * OUT_DIM];
        acc0 += w0 * p0[lane]      + w1 * p1[lane]      + w2 * p2[lane]      + w3 * p3[lane];
        acc1 += w0 * p0[lane + 32] + w1 * p1[lane + 32] + w2 * p2[lane + 32] + w3 * p3[lane + 32];
    }
    for (; j < end; ++j) {
        int s = g_csr_src[j];
        float w = g_norm_src[s];
        const float* p = &fin[(size_t)s * OUT_DIM];
        acc0 += w * p[lane];
        acc1 += w * p[lane + 32];
    }

    float nd = g_norm_dst[wid];
    size_t o = (size_t)wid * OUT_DIM;
    fout[o + lane]      = (1.0f - ALPHA) * nd * acc0 + ALPHA * g_feat0[o + lane];
    fout[o + 32 + lane] = (1.0f - ALPHA) * nd * acc1 + ALPHA * g_feat0[o + 32 + lane];
}

// ---------------- per-node attention dot products ----------------
__global__ void sd_kernel(const float* __restrict__ w_src, const float* __restrict__ w_dst) {
    int wid  = (blockIdx.x * blockDim.x + threadIdx.x) >> 5;
    int lane = threadIdx.x & 31;
    if (wid >= NN) return;
    size_t o = (size_t)wid * OUT_DIM;
    float f0 = g_featA[o + lane], f1 = g_featA[o + 32 + lane];
    float s = f0 * w_src[lane] + f1 * w_src[lane + 32];
    float d = f0 * w_dst[lane] + f1 * w_dst[lane + 32];
    #pragma unroll
    for (int off = 16; off; off >>= 1) {
        s += __shfl_xor_sync(0xFFFFFFFFu, s, off);
        d += __shfl_xor_sync(0xFFFFFFFFu, d, off);
    }
    if (lane == 0) { g_s[wid] = s; g_d[wid] = d; }
}

// ---------------- edge-softmax per dst node ----------------
__global__ void attn_kernel(float* __restrict__ attn_out) {
    int wid  = (blockIdx.x * blockDim.x + threadIdx.x) >> 5;
    int lane = threadIdx.x & 31;
    if (wid >= NN) return;
    int beg = g_ptr[wid], end = g_ptr[wid + 1];
    if (beg == end) return;
    float dn = g_d[wid];

    float m = -2.0f;  // tanh >= -1
    for (int j = beg + lane; j < end; j += 32) {
        float e = tanhf(g_s[g_csr_src[j]] + dn);
        g_e[j] = e;
        m = fmaxf(m, e);
    }
    #pragma unroll
    for (int off = 16; off; off >>= 1)
        m = fmaxf(m, __shfl_xor_sync(0xFFFFFFFFu, m, off));

    float sum = 0.f;
    for (int j = beg + lane; j < end; j += 32)
        sum += __expf(g_e[j] - m);
    #pragma unroll
    for (int off = 16; off; off >>= 1)
        sum += __shfl_xor_sync(0xFFFFFFFFu, sum, off);

    float inv = 1.0f / sum;
    for (int j = beg + lane; j < end; j += 32)
        attn_out[g_csr_eid[j]] = __expf(g_e[j] - m) * inv;
}

// ---------------- log_softmax over 64 features ----------------
__global__ void logsoftmax_kernel(float* __restrict__ out) {
    int wid  = (blockIdx.x * blockDim.x + threadIdx.x) >> 5;
    int lane = threadIdx.x & 31;
    if (wid >= NN) return;
    size_t o = (size_t)wid * OUT_DIM;
    float f0 = g_featA[o + lane], f1 = g_featA[o + 32 + lane];
    float m = fmaxf(f0, f1);
    #pragma unroll
    for (int off = 16; off; off >>= 1)
        m = fmaxf(m, __shfl_xor_sync(0xFFFFFFFFu, m, off));
    float sum = __expf(f0 - m) + __expf(f1 - m);
    #pragma unroll
    for (int off = 16; off; off >>= 1)
        sum += __shfl_xor_sync(0xFFFFFFFFu, sum, off);
    float ls = m + logf(sum);
    out[o + lane]      = f0 - ls;
    out[o + 32 + lane] = f1 - ls;
}

// ---------------- launch ----------------
extern "C" void kernel_launch(void* const* d_in, const int* in_sizes, int n_in,
                              void* d_out, int out_size) {
    const float* h     = (const float*)d_in[0];
    const int*   src   = (const int*)  d_in[1];
    const int*   dst   = (const int*)  d_in[2];
    const float* W1    = (const float*)d_in[3];
    const float* b1    = (const float*)d_in[4];
    const float* W2    = (const float*)d_in[5];
    const float* b2    = (const float*)d_in[6];
    const float* w_src = (const float*)d_in[7];
    const float* w_dst = (const float*)d_in[8];
    float* out = (float*)d_out;

    float *p_hidden, *p_feat0, *p_featA;
    cudaGetSymbolAddress((void**)&p_hidden, g_hidden);
    cudaGetSymbolAddress((void**)&p_feat0,  g_feat0);
    cudaGetSymbolAddress((void**)&p_featA,  g_featA);

    const int nodeBlocks = (NN + 255) / 256;
    const int edgeBlocks = (NE + 255) / 256;
    const int warpNodeBlocks = (NN + 7) / 8;  // 256 threads = 8 warps, warp per node
    const int nbScan = (NN + 511) / 512;      // 98

    init_zero_kernel<<<nodeBlocks, 256>>>();
    degree_kernel<<<edgeBlocks, 256>>>(src, dst);
    norm_kernel<<<nodeBlocks, 256>>>();
    scan_block_kernel<<<nbScan, 512>>>();
    scan_bsum_kernel<<<1, 128>>>(nbScan);
    scan_add_kernel<<<(NN + 1 + 255) / 256, 256>>>();
    csr_fill_kernel<<<edgeBlocks, 256>>>(src, dst);

    // GEMM1: hidden = relu(h @ W1 + b1)   [50000x512] @ [512x256]
    {
        dim3 grid(HID_DIM / 128, (NN + 127) / 128);
        sgemm_kernel<128, 128, 8, 8, 8, true><<<grid, 256>>>(
            h, W1, b1, p_hidden, nullptr, NN, HID_DIM, IN_DIM);
    }
    // GEMM2: feat0 = hidden @ W2 + b2     [50000x256] @ [256x64]  (also writes featA)
    {
        dim3 grid(OUT_DIM / 64, (NN + 127) / 128);
        sgemm_kernel<128, 64, 16, 8, 4, false><<<grid, 256>>>(
            p_hidden, W2, b2, p_feat0, p_featA, NN, OUT_DIM, HID_DIM);
    }

    // 4 propagation hops (ping-pong, ends in g_featA)
    prop_kernel<<<warpNodeBlocks, 256>>>(0);
    prop_kernel<<<warpNodeBlocks, 256>>>(1);
    prop_kernel<<<warpNodeBlocks, 256>>>(0);
    prop_kernel<<<warpNodeBlocks, 256>>>(1);

    sd_kernel<<<warpNodeBlocks, 256>>>(w_src, w_dst);
    attn_kernel<<<warpNodeBlocks, 256>>>(out + (size_t)NN * OUT_DIM);
    logsoftmax_kernel<<<warpNodeBlocks, 256>>>(out);
}

// round 4
// speedup vs baseline: 1.0453x; 1.0453x over previous
#include <cuda_runtime.h>
#include <math.h>

#define NN      50000
#define NE      1600000
#define IN_DIM  512
#define HID_DIM 256
#define OUT_DIM 64
#define ALPHA   0.1f

// ---------------- static device scratch (no allocations allowed) ----------------
__device__ float g_hidden[(size_t)NN * HID_DIM];   // 51.2 MB
__device__ float g_feat0 [(size_t)NN * OUT_DIM];   // 12.8 MB
__device__ float g_featA [(size_t)NN * OUT_DIM];
__device__ float g_featB [(size_t)NN * OUT_DIM];
__device__ int   g_deg_out[NN];
__device__ int   g_deg_in [NN];
__device__ float g_norm_src[NN];
__device__ float g_norm_dst[NN];
__device__ int   g_ptr [NN + 1];
__device__ int   g_fill[NN];
__device__ int   g_bsum[256];
__device__ int   g_csr_src[NE];
__device__ int   g_csr_eid[NE];
__device__ float g_s[NN];
__device__ float g_d[NN];
__device__ float g_e[NE];

// ---------------- packed f32x2 helpers (Blackwell FFMA2 path) ----------------
typedef unsigned long long u64;

__device__ __forceinline__ u64 pk2(float lo, float hi) {
    u64 r;
    asm("mov.b64 %0, {%1, %2};" : "=l"(r) : "f"(lo), "f"(hi));
    return r;
}
__device__ __forceinline__ void upk2(u64 v, float& lo, float& hi) {
    asm("mov.b64 {%0, %1}, %2;" : "=f"(lo), "=f"(hi) : "l"(v));
}
__device__ __forceinline__ void ffma2(u64& acc, u64 a, u64 b) {
    asm("fma.rn.f32x2 %0, %1, %2, %0;" : "+l"(acc) : "l"(a), "l"(b));
}

// ---------------- init ----------------
__global__ void init_zero_kernel() {
    int i = blockIdx.x * blockDim.x + threadIdx.x;
    if (i < NN) {
        g_deg_out[i] = 0;
        g_deg_in[i]  = 0;
        g_fill[i]    = 0;
    }
}

// ---------------- degrees ----------------
__global__ void degree_kernel(const int* __restrict__ src, const int* __restrict__ dst) {
    int e = blockIdx.x * blockDim.x + threadIdx.x;
    if (e < NE) {
        atomicAdd(&g_deg_out[src[e]], 1);
        atomicAdd(&g_deg_in [dst[e]], 1);
    }
}

__global__ void norm_kernel() {
    int i = blockIdx.x * blockDim.x + threadIdx.x;
    if (i < NN) {
        g_norm_src[i] = rsqrtf((float)max(g_deg_out[i], 1));
        g_norm_dst[i] = rsqrtf((float)max(g_deg_in [i], 1));
    }
}

// ---------------- exclusive scan of deg_in -> g_ptr (3 kernels) ----------------
__global__ void scan_block_kernel() {
    __shared__ int s[512];
    int tid = threadIdx.x;
    int i = blockIdx.x * 512 + tid;
    int v = (i < NN) ? g_deg_in[i] : 0;
    s[tid] = v;
    __syncthreads();
    #pragma unroll
    for (int off = 1; off < 512; off <<= 1) {
        int t = (tid >= off) ? s[tid - off] : 0;
        __syncthreads();
        s[tid] += t;
        __syncthreads();
    }
    if (i < NN) g_ptr[i] = s[tid] - v;            // block-local exclusive
    if (tid == 511) g_bsum[blockIdx.x] = s[511];  // block total
}

__global__ void scan_bsum_kernel(int nb) {
    __shared__ int s[128];
    int tid = threadIdx.x;
    int v = (tid < nb) ? g_bsum[tid] : 0;
    s[tid] = v;
    __syncthreads();
    #pragma unroll
    for (int off = 1; off < 128; off <<= 1) {
        int t = (tid >= off) ? s[tid - off] : 0;
        __syncthreads();
        s[tid] += t;
        __syncthreads();
    }
    if (tid < nb) g_bsum[tid] = s[tid] - v;       // exclusive in place
}

__global__ void scan_add_kernel() {
    int i = blockIdx.x * blockDim.x + threadIdx.x;
    if (i < NN)       g_ptr[i] += g_bsum[i >> 9];
    else if (i == NN) g_ptr[NN] = NE;
}

// ---------------- CSR fill (dst-sorted edge list) ----------------
__global__ void csr_fill_kernel(const int* __restrict__ src, const int* __restrict__ dst) {
    int e = blockIdx.x * blockDim.x + threadIdx.x;
    if (e < NE) {
        int d = dst[e];
        int pos = g_ptr[d] + atomicAdd(&g_fill[d], 1);
        g_csr_src[pos] = src[e];
        g_csr_eid[pos] = e;
    }
}

// ---------------- SGEMM with packed f32x2 accumulation ----------------
// acc2[i2][j] holds {C[2*i2][j], C[2*i2+1][j]} packed in one 64-bit reg.
// A-pairs (adjacent M rows) load directly as 8B from the transposed As tile;
// B values are duplicated into both halves with one mov.b64.
template <int BM, int BN, int BK, int TM, int TN, bool RELU>
__global__ void sgemm_kernel(const float* __restrict__ A, const float* __restrict__ B,
                             const float* __restrict__ bias,
                             float* __restrict__ C, float* __restrict__ C2,
                             int M, int N, int K) {
    constexpr int THREADS = (BM / TM) * (BN / TN);
    __shared__ __align__(16) float As[BK][BM];
    __shared__ __align__(16) float Bs[BK][BN];

    const int tid  = threadIdx.x;
    const int tcol = tid % (BN / TN);
    const int trow = tid / (BN / TN);
    const int aBase = blockIdx.y * BM;
    const int bBase = blockIdx.x * BN;

    u64 acc2[TM / 2][TN];
    #pragma unroll
    for (int i = 0; i < TM / 2; i++)
        #pragma unroll
        for (int j = 0; j < TN; j++) acc2[i][j] = 0ULL;

    for (int k0 = 0; k0 < K; k0 += BK) {
        // A tile (transposed into smem: As[k][m])
        #pragma unroll
        for (int i = tid * 4; i < BM * BK; i += THREADS * 4) {
            int m = i / BK, k = i % BK;
            int gm = aBase + m;
            float4 v = make_float4(0.f, 0.f, 0.f, 0.f);
            if (gm < M) v = *reinterpret_cast<const float4*>(&A[(size_t)gm * K + k0 + k]);
            As[k + 0][m] = v.x; As[k + 1][m] = v.y; As[k + 2][m] = v.z; As[k + 3][m] = v.w;
        }
        // B tile
        #pragma unroll
        for (int i = tid * 4; i < BK * BN; i += THREADS * 4) {
            int k = i / BN, n = i % BN;
            *reinterpret_cast<float4*>(&Bs[k][n]) =
                *reinterpret_cast<const float4*>(&B[(size_t)(k0 + k) * N + bBase + n]);
        }
        __syncthreads();

        #pragma unroll
        for (int k = 0; k < BK; ++k) {
            // A pairs: contiguous adjacent-row floats in As[k], 8B-aligned (TM even)
            u64 a2[TM / 2];
            #pragma unroll
            for (int i = 0; i < TM / 2; i++)
                a2[i] = *reinterpret_cast<const u64*>(&As[k][trow * TM + 2 * i]);
            // B duplicated into both packed halves
            u64 b2[TN];
            #pragma unroll
            for (int j = 0; j < TN; j++) {
                float b = Bs[k][tcol * TN + j];
                b2[j] = pk2(b, b);
            }
            #pragma unroll
            for (int i = 0; i < TM / 2; i++)
                #pragma unroll
                for (int j = 0; j < TN; j++) ffma2(acc2[i][j], a2[i], b2[j]);
        }
        __syncthreads();
    }

    #pragma unroll
    for (int i2 = 0; i2 < TM / 2; i2++) {
        float r0[TN], r1[TN];
        #pragma unroll
        for (int j = 0; j < TN; j++) upk2(acc2[i2][j], r0[j], r1[j]);

        #pragma unroll
        for (int half = 0; half < 2; half++) {
            int gm = aBase + trow * TM + 2 * i2 + half;
            if (gm >= M) continue;
            const float* rr = half ? r1 : r0;
            #pragma unroll
            for (int j = 0; j < TN; j += 4) {
                int gn = bBase + tcol * TN + j;
                float4 r;
                r.x = rr[j + 0] + bias[gn + 0];
                r.y = rr[j + 1] + bias[gn + 1];
                r.z = rr[j + 2] + bias[gn + 2];
                r.w = rr[j + 3] + bias[gn + 3];
                if (RELU) {
                    r.x = fmaxf(r.x, 0.f); r.y = fmaxf(r.y, 0.f);
                    r.z = fmaxf(r.z, 0.f); r.w = fmaxf(r.w, 0.f);
                }
                *reinterpret_cast<float4*>(&C[(size_t)gm * N + gn]) = r;
                if (C2) *reinterpret_cast<float4*>(&C2[(size_t)gm * N + gn]) = r;
            }
        }
    }
}

// ---------------- propagation hop: warp per dst node, CSR gather ----------------
__global__ void prop_kernel(int dir) {
    const float* __restrict__ fin  = dir ? g_featB : g_featA;
    float*       __restrict__ fout = dir ? g_featA : g_featB;

    int wid  = (blockIdx.x * blockDim.x + threadIdx.x) >> 5;
    int lane = threadIdx.x & 31;
    if (wid >= NN) return;

    int beg = g_ptr[wid], end = g_ptr[wid + 1];
    float acc0 = 0.f, acc1 = 0.f;

    int j = beg;
    for (; j + 4 <= end; j += 4) {
        int s0 = g_csr_src[j + 0], s1 = g_csr_src[j + 1];
        int s2 = g_csr_src[j + 2], s3 = g_csr_src[j + 3];
        float w0 = g_norm_src[s0], w1 = g_norm_src[s1];
        float w2 = g_norm_src[s2], w3 = g_norm_src[s3];
        const float* p0 = &fin[(size_t)s0 * OUT_DIM];
        const float* p1 = &fin[(size_t)s1 * OUT_DIM];
        const float* p2 = &fin[(size_t)s2 * OUT_DIM];
        const float* p3 = &fin[(size_t)s3 * OUT_DIM];
        acc0 += w0 * p0[lane]      + w1 * p1[lane]      + w2 * p2[lane]      + w3 * p3[lane];
        acc1 += w0 * p0[lane + 32] + w1 * p1[lane + 32] + w2 * p2[lane + 32] + w3 * p3[lane + 32];
    }
    for (; j < end; ++j) {
        int s = g_csr_src[j];
        float w = g_norm_src[s];
        const float* p = &fin[(size_t)s * OUT_DIM];
        acc0 += w * p[lane];
        acc1 += w * p[lane + 32];
    }

    float nd = g_norm_dst[wid];
    size_t o = (size_t)wid * OUT_DIM;
    fout[o + lane]      = (1.0f - ALPHA) * nd * acc0 + ALPHA * g_feat0[o + lane];
    fout[o + 32 + lane] = (1.0f - ALPHA) * nd * acc1 + ALPHA * g_feat0[o + 32 + lane];
}

// ---------------- per-node attention dot products ----------------
__global__ void sd_kernel(const float* __restrict__ w_src, const float* __restrict__ w_dst) {
    int wid  = (blockIdx.x * blockDim.x + threadIdx.x) >> 5;
    int lane = threadIdx.x & 31;
    if (wid >= NN) return;
    size_t o = (size_t)wid * OUT_DIM;
    float f0 = g_featA[o + lane], f1 = g_featA[o + 32 + lane];
    float s = f0 * w_src[lane] + f1 * w_src[lane + 32];
    float d = f0 * w_dst[lane] + f1 * w_dst[lane + 32];
    #pragma unroll
    for (int off = 16; off; off >>= 1) {
        s += __shfl_xor_sync(0xFFFFFFFFu, s, off);
        d += __shfl_xor_sync(0xFFFFFFFFu, d, off);
    }
    if (lane == 0) { g_s[wid] = s; g_d[wid] = d; }
}

// ---------------- edge-softmax per dst node ----------------
__global__ void attn_kernel(float* __restrict__ attn_out) {
    int wid  = (blockIdx.x * blockDim.x + threadIdx.x) >> 5;
    int lane = threadIdx.x & 31;
    if (wid >= NN) return;
    int beg = g_ptr[wid], end = g_ptr[wid + 1];
    if (beg == end) return;
    float dn = g_d[wid];

    float m = -2.0f;  // tanh >= -1
    for (int j = beg + lane; j < end; j += 32) {
        float e = tanhf(g_s[g_csr_src[j]] + dn);
        g_e[j] = e;
        m = fmaxf(m, e);
    }
    #pragma unroll
    for (int off = 16; off; off >>= 1)
        m = fmaxf(m, __shfl_xor_sync(0xFFFFFFFFu, m, off));

    float sum = 0.f;
    for (int j = beg + lane; j < end; j += 32)
        sum += __expf(g_e[j] - m);
    #pragma unroll
    for (int off = 16; off; off >>= 1)
        sum += __shfl_xor_sync(0xFFFFFFFFu, sum, off);

    float inv = 1.0f / sum;
    for (int j = beg + lane; j < end; j += 32)
        attn_out[g_csr_eid[j]] = __expf(g_e[j] - m) * inv;
}

// ---------------- log_softmax over 64 features ----------------
__global__ void logsoftmax_kernel(float* __restrict__ out) {
    int wid  = (blockIdx.x * blockDim.x + threadIdx.x) >> 5;
    int lane = threadIdx.x & 31;
    if (wid >= NN) return;
    size_t o = (size_t)wid * OUT_DIM;
    float f0 = g_featA[o + lane], f1 = g_featA[o + 32 + lane];
    float m = fmaxf(f0, f1);
    #pragma unroll
    for (int off = 16; off; off >>= 1)
        m = fmaxf(m, __shfl_xor_sync(0xFFFFFFFFu, m, off));
    float sum = __expf(f0 - m) + __expf(f1 - m);
    #pragma unroll
    for (int off = 16; off; off >>= 1)
        sum += __shfl_xor_sync(0xFFFFFFFFu, sum, off);
    float ls = m + logf(sum);
    out[o + lane]      = f0 - ls;
    out[o + 32 + lane] = f1 - ls;
}

// ---------------- launch ----------------
extern "C" void kernel_launch(void* const* d_in, const int* in_sizes, int n_in,
                              void* d_out, int out_size) {
    const float* h     = (const float*)d_in[0];
    const int*   src   = (const int*)  d_in[1];
    const int*   dst   = (const int*)  d_in[2];
    const float* W1    = (const float*)d_in[3];
    const float* b1    = (const float*)d_in[4];
    const float* W2    = (const float*)d_in[5];
    const float* b2    = (const float*)d_in[6];
    const float* w_src = (const float*)d_in[7];
    const float* w_dst = (const float*)d_in[8];
    float* out = (float*)d_out;

    float *p_hidden, *p_feat0, *p_featA;
    cudaGetSymbolAddress((void**)&p_hidden, g_hidden);
    cudaGetSymbolAddress((void**)&p_feat0,  g_feat0);
    cudaGetSymbolAddress((void**)&p_featA,  g_featA);

    const int nodeBlocks = (NN + 255) / 256;
    const int edgeBlocks = (NE + 255) / 256;
    const int warpNodeBlocks = (NN + 7) / 8;  // 256 threads = 8 warps, warp per node
    const int nbScan = (NN + 511) / 512;      // 98

    init_zero_kernel<<<nodeBlocks, 256>>>();
    degree_kernel<<<edgeBlocks, 256>>>(src, dst);
    norm_kernel<<<nodeBlocks, 256>>>();
    scan_block_kernel<<<nbScan, 512>>>();
    scan_bsum_kernel<<<1, 128>>>(nbScan);
    scan_add_kernel<<<(NN + 1 + 255) / 256, 256>>>();
    csr_fill_kernel<<<edgeBlocks, 256>>>(src, dst);

    // GEMM1: hidden = relu(h @ W1 + b1)   [50000x512] @ [512x256]
    {
        dim3 grid(HID_DIM / 128, (NN + 127) / 128);
        sgemm_kernel<128, 128, 8, 8, 8, true><<<grid, 256>>>(
            h, W1, b1, p_hidden, nullptr, NN, HID_DIM, IN_DIM);
    }
    // GEMM2: feat0 = hidden @ W2 + b2     [50000x256] @ [256x64]  (also writes featA)
    {
        dim3 grid(OUT_DIM / 64, (NN + 127) / 128);
        sgemm_kernel<128, 64, 16, 8, 4, false><<<grid, 256>>>(
            p_hidden, W2, b2, p_feat0, p_featA, NN, OUT_DIM, HID_DIM);
    }

    // 4 propagation hops (ping-pong, ends in g_featA)
    prop_kernel<<<warpNodeBlocks, 256>>>(0);
    prop_kernel<<<warpNodeBlocks, 256>>>(1);
    prop_kernel<<<warpNodeBlocks, 256>>>(0);
    prop_kernel<<<warpNodeBlocks, 256>>>(1);

    sd_kernel<<<warpNodeBlocks, 256>>>(w_src, w_dst);
    attn_kernel<<<warpNodeBlocks, 256>>>(out + (size_t)NN * OUT_DIM);
    logsoftmax_kernel<<<warpNodeBlocks, 256>>>(out);
}

// round 5
// speedup vs baseline: 1.0555x; 1.0097x over previous
#include <cuda_runtime.h>
#include <math.h>

#define NN      50000
#define NE      1600000
#define IN_DIM  512
#define HID_DIM 256
#define OUT_DIM 64
#define ALPHA   0.1f

// ---------------- static device scratch (no allocations allowed) ----------------
__device__ float g_hidden[(size_t)NN * HID_DIM];   // 51.2 MB
__device__ float g_feat0 [(size_t)NN * OUT_DIM];   // 12.8 MB
__device__ float g_featA [(size_t)NN * OUT_DIM];
__device__ float g_featB [(size_t)NN * OUT_DIM];
__device__ int   g_deg_out[NN];
__device__ int   g_deg_in [NN];
__device__ float g_norm_src[NN];
__device__ float g_norm_dst[NN];
__device__ int   g_ptr [NN + 1];
__device__ int   g_fill[NN];
__device__ int   g_bsum[256];
__device__ int   g_csr_src[NE];
__device__ int   g_csr_eid[NE];
__device__ float g_s[NN];
__device__ float g_d[NN];
__device__ float g_e[NE];

// ---------------- packed f32x2 helpers (Blackwell FFMA2 path) ----------------
typedef unsigned long long u64;

__device__ __forceinline__ u64 pk2(float lo, float hi) {
    u64 r;
    asm("mov.b64 %0, {%1, %2};" : "=l"(r) : "f"(lo), "f"(hi));
    return r;
}
__device__ __forceinline__ void upk2(u64 v, float& lo, float& hi) {
    asm("mov.b64 {%0, %1}, %2;" : "=f"(lo), "=f"(hi) : "l"(v));
}
__device__ __forceinline__ void ffma2(u64& acc, u64 a, u64 b) {
    asm("fma.rn.f32x2 %0, %1, %2, %0;" : "+l"(acc) : "l"(a), "l"(b));
}

// ---------------- init ----------------
__global__ void init_zero_kernel() {
    int i = blockIdx.x * blockDim.x + threadIdx.x;
    if (i < NN) {
        g_deg_out[i] = 0;
        g_deg_in[i]  = 0;
        g_fill[i]    = 0;
    }
}

// ---------------- degrees ----------------
__global__ void degree_kernel(const int* __restrict__ src, const int* __restrict__ dst) {
    int e = blockIdx.x * blockDim.x + threadIdx.x;
    if (e < NE) {
        atomicAdd(&g_deg_out[src[e]], 1);
        atomicAdd(&g_deg_in [dst[e]], 1);
    }
}

__global__ void norm_kernel() {
    int i = blockIdx.x * blockDim.x + threadIdx.x;
    if (i < NN) {
        g_norm_src[i] = rsqrtf((float)max(g_deg_out[i], 1));
        g_norm_dst[i] = rsqrtf((float)max(g_deg_in [i], 1));
    }
}

// ---------------- exclusive scan of deg_in -> g_ptr (3 kernels) ----------------
__global__ void scan_block_kernel() {
    __shared__ int s[512];
    int tid = threadIdx.x;
    int i = blockIdx.x * 512 + tid;
    int v = (i < NN) ? g_deg_in[i] : 0;
    s[tid] = v;
    __syncthreads();
    #pragma unroll
    for (int off = 1; off < 512; off <<= 1) {
        int t = (tid >= off) ? s[tid - off] : 0;
        __syncthreads();
        s[tid] += t;
        __syncthreads();
    }
    if (i < NN) g_ptr[i] = s[tid] - v;            // block-local exclusive
    if (tid == 511) g_bsum[blockIdx.x] = s[511];  // block total
}

__global__ void scan_bsum_kernel(int nb) {
    __shared__ int s[128];
    int tid = threadIdx.x;
    int v = (tid < nb) ? g_bsum[tid] : 0;
    s[tid] = v;
    __syncthreads();
    #pragma unroll
    for (int off = 1; off < 128; off <<= 1) {
        int t = (tid >= off) ? s[tid - off] : 0;
        __syncthreads();
        s[tid] += t;
        __syncthreads();
    }
    if (tid < nb) g_bsum[tid] = s[tid] - v;       // exclusive in place
}

__global__ void scan_add_kernel() {
    int i = blockIdx.x * blockDim.x + threadIdx.x;
    if (i < NN)       g_ptr[i] += g_bsum[i >> 9];
    else if (i == NN) g_ptr[NN] = NE;
}

// ---------------- CSR fill (dst-sorted edge list) ----------------
__global__ void csr_fill_kernel(const int* __restrict__ src, const int* __restrict__ dst) {
    int e = blockIdx.x * blockDim.x + threadIdx.x;
    if (e < NE) {
        int d = dst[e];
        int pos = g_ptr[d] + atomicAdd(&g_fill[d], 1);
        g_csr_src[pos] = src[e];
        g_csr_eid[pos] = e;
    }
}

// ---------------- SGEMM with packed f32x2 accumulation ----------------
// acc2[i2][j] holds {C[2*i2][j], C[2*i2+1][j]} packed in one 64-bit reg.
// A-pairs (adjacent M rows) load directly as 8B from the transposed As tile;
// B values are duplicated into both halves with one mov.b64.
template <int BM, int BN, int BK, int TM, int TN, bool RELU>
__global__ void sgemm_kernel(const float* __restrict__ A, const float* __restrict__ B,
                             const float* __restrict__ bias,
                             float* __restrict__ C, float* __restrict__ C2,
                             int M, int N, int K) {
    constexpr int THREADS = (BM / TM) * (BN / TN);
    __shared__ __align__(16) float As[BK][BM];
    __shared__ __align__(16) float Bs[BK][BN];

    const int tid  = threadIdx.x;
    const int tcol = tid % (BN / TN);
    const int trow = tid / (BN / TN);
    const int aBase = blockIdx.y * BM;
    const int bBase = blockIdx.x * BN;

    u64 acc2[TM / 2][TN];
    #pragma unroll
    for (int i = 0; i < TM / 2; i++)
        #pragma unroll
        for (int j = 0; j < TN; j++) acc2[i][j] = 0ULL;

    for (int k0 = 0; k0 < K; k0 += BK) {
        // A tile (transposed into smem: As[k][m])
        #pragma unroll
        for (int i = tid * 4; i < BM * BK; i += THREADS * 4) {
            int m = i / BK, k = i % BK;
            int gm = aBase + m;
            float4 v = make_float4(0.f, 0.f, 0.f, 0.f);
            if (gm < M) v = *reinterpret_cast<const float4*>(&A[(size_t)gm * K + k0 + k]);
            As[k + 0][m] = v.x; As[k + 1][m] = v.y; As[k + 2][m] = v.z; As[k + 3][m] = v.w;
        }
        // B tile
        #pragma unroll
        for (int i = tid * 4; i < BK * BN; i += THREADS * 4) {
            int k = i / BN, n = i % BN;
            *reinterpret_cast<float4*>(&Bs[k][n]) =
                *reinterpret_cast<const float4*>(&B[(size_t)(k0 + k) * N + bBase + n]);
        }
        __syncthreads();

        #pragma unroll
        for (int k = 0; k < BK; ++k) {
            // A pairs: contiguous adjacent-row floats in As[k], 8B-aligned (TM even)
            u64 a2[TM / 2];
            #pragma unroll
            for (int i = 0; i < TM / 2; i++)
                a2[i] = *reinterpret_cast<const u64*>(&As[k][trow * TM + 2 * i]);
            // B duplicated into both packed halves
            u64 b2[TN];
            #pragma unroll
            for (int j = 0; j < TN; j++) {
                float b = Bs[k][tcol * TN + j];
                b2[j] = pk2(b, b);
            }
            #pragma unroll
            for (int i = 0; i < TM / 2; i++)
                #pragma unroll
                for (int j = 0; j < TN; j++) ffma2(acc2[i][j], a2[i], b2[j]);
        }
        __syncthreads();
    }

    #pragma unroll
    for (int i2 = 0; i2 < TM / 2; i2++) {
        float r0[TN], r1[TN];
        #pragma unroll
        for (int j = 0; j < TN; j++) upk2(acc2[i2][j], r0[j], r1[j]);

        #pragma unroll
        for (int half = 0; half < 2; half++) {
            int gm = aBase + trow * TM + 2 * i2 + half;
            if (gm >= M) continue;
            const float* rr = half ? r1 : r0;
            #pragma unroll
            for (int j = 0; j < TN; j += 4) {
                int gn = bBase + tcol * TN + j;
                float4 r;
                r.x = rr[j + 0] + bias[gn + 0];
                r.y = rr[j + 1] + bias[gn + 1];
                r.z = rr[j + 2] + bias[gn + 2];
                r.w = rr[j + 3] + bias[gn + 3];
                if (RELU) {
                    r.x = fmaxf(r.x, 0.f); r.y = fmaxf(r.y, 0.f);
                    r.z = fmaxf(r.z, 0.f); r.w = fmaxf(r.w, 0.f);
                }
                *reinterpret_cast<float4*>(&C[(size_t)gm * N + gn]) = r;
                if (C2) *reinterpret_cast<float4*>(&C2[(size_t)gm * N + gn]) = r;
            }
        }
    }
}

// ---------------- propagation hop: warp per dst node, CSR gather ----------------
__global__ void prop_kernel(int dir) {
    const float* __restrict__ fin  = dir ? g_featB : g_featA;
    float*       __restrict__ fout = dir ? g_featA : g_featB;

    int wid  = (blockIdx.x * blockDim.x + threadIdx.x) >> 5;
    int lane = threadIdx.x & 31;
    if (wid >= NN) return;

    int beg = g_ptr[wid], end = g_ptr[wid + 1];
    float acc0 = 0.f, acc1 = 0.f;

    int j = beg;
    for (; j + 4 <= end; j += 4) {
        int s0 = g_csr_src[j + 0], s1 = g_csr_src[j + 1];
        int s2 = g_csr_src[j + 2], s3 = g_csr_src[j + 3];
        float w0 = g_norm_src[s0], w1 = g_norm_src[s1];
        float w2 = g_norm_src[s2], w3 = g_norm_src[s3];
        const float* p0 = &fin[(size_t)s0 * OUT_DIM];
        const float* p1 = &fin[(size_t)s1 * OUT_DIM];
        const float* p2 = &fin[(size_t)s2 * OUT_DIM];
        const float* p3 = &fin[(size_t)s3 * OUT_DIM];
        acc0 += w0 * p0[lane]      + w1 * p1[lane]      + w2 * p2[lane]      + w3 * p3[lane];
        acc1 += w0 * p0[lane + 32] + w1 * p1[lane + 32] + w2 * p2[lane + 32] + w3 * p3[lane + 32];
    }
    for (; j < end; ++j) {
        int s = g_csr_src[j];
        float w = g_norm_src[s];
        const float* p = &fin[(size_t)s * OUT_DIM];
        acc0 += w * p[lane];
        acc1 += w * p[lane + 32];
    }

    float nd = g_norm_dst[wid];
    size_t o = (size_t)wid * OUT_DIM;
    fout[o + lane]      = (1.0f - ALPHA) * nd * acc0 + ALPHA * g_feat0[o + lane];
    fout[o + 32 + lane] = (1.0f - ALPHA) * nd * acc1 + ALPHA * g_feat0[o + 32 + lane];
}

// ---------------- per-node attention dot products ----------------
__global__ void sd_kernel(const float* __restrict__ w_src, const float* __restrict__ w_dst) {
    int wid  = (blockIdx.x * blockDim.x + threadIdx.x) >> 5;
    int lane = threadIdx.x & 31;
    if (wid >= NN) return;
    size_t o = (size_t)wid * OUT_DIM;
    float f0 = g_featA[o + lane], f1 = g_featA[o + 32 + lane];
    float s = f0 * w_src[lane] + f1 * w_src[lane + 32];
    float d = f0 * w_dst[lane] + f1 * w_dst[lane + 32];
    #pragma unroll
    for (int off = 16; off; off >>= 1) {
        s += __shfl_xor_sync(0xFFFFFFFFu, s, off);
        d += __shfl_xor_sync(0xFFFFFFFFu, d, off);
    }
    if (lane == 0) { g_s[wid] = s; g_d[wid] = d; }
}

// ---------------- edge-softmax per dst node ----------------
__global__ void attn_kernel(float* __restrict__ attn_out) {
    int wid  = (blockIdx.x * blockDim.x + threadIdx.x) >> 5;
    int lane = threadIdx.x & 31;
    if (wid >= NN) return;
    int beg = g_ptr[wid], end = g_ptr[wid + 1];
    if (beg == end) return;
    float dn = g_d[wid];

    float m = -2.0f;  // tanh >= -1
    for (int j = beg + lane; j < end; j += 32) {
        float e = tanhf(g_s[g_csr_src[j]] + dn);
        g_e[j] = e;
        m = fmaxf(m, e);
    }
    #pragma unroll
    for (int off = 16; off; off >>= 1)
        m = fmaxf(m, __shfl_xor_sync(0xFFFFFFFFu, m, off));

    float sum = 0.f;
    for (int j = beg + lane; j < end; j += 32)
        sum += __expf(g_e[j] - m);
    #pragma unroll
    for (int off = 16; off; off >>= 1)
        sum += __shfl_xor_sync(0xFFFFFFFFu, sum, off);

    float inv = 1.0f / sum;
    for (int j = beg + lane; j < end; j += 32)
        attn_out[g_csr_eid[j]] = __expf(g_e[j] - m) * inv;
}

// ---------------- log_softmax over 64 features ----------------
__global__ void logsoftmax_kernel(float* __restrict__ out) {
    int wid  = (blockIdx.x * blockDim.x + threadIdx.x) >> 5;
    int lane = threadIdx.x & 31;
    if (wid >= NN) return;
    size_t o = (size_t)wid * OUT_DIM;
    float f0 = g_featA[o + lane], f1 = g_featA[o + 32 + lane];
    float m = fmaxf(f0, f1);
    #pragma unroll
    for (int off = 16; off; off >>= 1)
        m = fmaxf(m, __shfl_xor_sync(0xFFFFFFFFu, m, off));
    float sum = __expf(f0 - m) + __expf(f1 - m);
    #pragma unroll
    for (int off = 16; off; off >>= 1)
        sum += __shfl_xor_sync(0xFFFFFFFFu, sum, off);
    float ls = m + logf(sum);
    out[o + lane]      = f0 - ls;
    out[o + 32 + lane] = f1 - ls;
}

// ---------------- launch ----------------
extern "C" void kernel_launch(void* const* d_in, const int* in_sizes, int n_in,
                              void* d_out, int out_size) {
    const float* h     = (const float*)d_in[0];
    const int*   src   = (const int*)  d_in[1];
    const int*   dst   = (const int*)  d_in[2];
    const float* W1    = (const float*)d_in[3];
    const float* b1    = (const float*)d_in[4];
    const float* W2    = (const float*)d_in[5];
    const float* b2    = (const float*)d_in[6];
    const float* w_src = (const float*)d_in[7];
    const float* w_dst = (const float*)d_in[8];
    float* out = (float*)d_out;

    float *p_hidden, *p_feat0, *p_featA;
    cudaGetSymbolAddress((void**)&p_hidden, g_hidden);
    cudaGetSymbolAddress((void**)&p_feat0,  g_feat0);
    cudaGetSymbolAddress((void**)&p_featA,  g_featA);

    const int nodeBlocks = (NN + 255) / 256;
    const int edgeBlocks = (NE + 255) / 256;
    const int warpNodeBlocks = (NN + 7) / 8;  // 256 threads = 8 warps, warp per node
    const int nbScan = (NN + 511) / 512;      // 98

    init_zero_kernel<<<nodeBlocks, 256>>>();
    degree_kernel<<<edgeBlocks, 256>>>(src, dst);
    norm_kernel<<<nodeBlocks, 256>>>();
    scan_block_kernel<<<nbScan, 512>>>();
    scan_bsum_kernel<<<1, 128>>>(nbScan);
    scan_add_kernel<<<(NN + 1 + 255) / 256, 256>>>();
    csr_fill_kernel<<<edgeBlocks, 256>>>(src, dst);

    // GEMM1: hidden = relu(h @ W1 + b1)   [50000x512] @ [512x256]
    {
        dim3 grid(HID_DIM / 128, (NN + 127) / 128);
        sgemm_kernel<128, 128, 8, 8, 8, true><<<grid, 256>>>(
            h, W1, b1, p_hidden, nullptr, NN, HID_DIM, IN_DIM);
    }
    // GEMM2: feat0 = hidden @ W2 + b2     [50000x256] @ [256x64]  (also writes featA)
    {
        dim3 grid(OUT_DIM / 64, (NN + 127) / 128);
        sgemm_kernel<128, 64, 16, 8, 4, false><<<grid, 256>>>(
            p_hidden, W2, b2, p_feat0, p_featA, NN, OUT_DIM, HID_DIM);
    }

    // 4 propagation hops (ping-pong, ends in g_featA)
    prop_kernel<<<warpNodeBlocks, 256>>>(0);
    prop_kernel<<<warpNodeBlocks, 256>>>(1);
    prop_kernel<<<warpNodeBlocks, 256>>>(0);
    prop_kernel<<<warpNodeBlocks, 256>>>(1);

    sd_kernel<<<warpNodeBlocks, 256>>>(w_src, w_dst);
    attn_kernel<<<warpNodeBlocks, 256>>>(out + (size_t)NN * OUT_DIM);
    logsoftmax_kernel<<<warpNodeBlocks, 256>>>(out);
}

// round 6
// speedup vs baseline: 1.2605x; 1.1943x over previous
#include <cuda_runtime.h>
#include <cuda_bf16.h>
#include <math.h>

#define NN      50000
#define NE      1600000
#define IN_DIM  512
#define HID_DIM 256
#define OUT_DIM 64
#define ALPHA   0.1f

// ---------------- static device scratch (no allocations allowed) ----------------
__device__ float g_hidden[(size_t)NN * HID_DIM];   // 51.2 MB
__device__ float g_feat0 [(size_t)NN * OUT_DIM];   // 12.8 MB
__device__ float g_featA [(size_t)NN * OUT_DIM];
__device__ float g_featB [(size_t)NN * OUT_DIM];
__device__ int   g_deg_out[NN];
__device__ int   g_deg_in [NN];
__device__ float g_norm_src[NN];
__device__ float g_norm_dst[NN];
__device__ int   g_ptr [NN + 1];
__device__ int   g_fill[NN];
__device__ int   g_bsum[256];
__device__ int   g_csr_src[NE];
__device__ int   g_csr_eid[NE];
__device__ float g_s[NN];
__device__ float g_d[NN];
__device__ float g_e[NE];

// bf16 split operands for tensor-core GEMM1
__device__ __nv_bfloat16 g_h_hi [(size_t)NN * IN_DIM];   // 51.2 MB
__device__ __nv_bfloat16 g_h_lo [(size_t)NN * IN_DIM];   // 51.2 MB
__device__ __nv_bfloat16 g_W1t_hi[(size_t)HID_DIM * IN_DIM];  // [N][K] transposed
__device__ __nv_bfloat16 g_W1t_lo[(size_t)HID_DIM * IN_DIM];

// ---------------- packed f32x2 helpers ----------------
typedef unsigned long long u64;

__device__ __forceinline__ u64 pk2(float lo, float hi) {
    u64 r;
    asm("mov.b64 %0, {%1, %2};" : "=l"(r) : "f"(lo), "f"(hi));
    return r;
}
__device__ __forceinline__ void upk2(u64 v, float& lo, float& hi) {
    asm("mov.b64 {%0, %1}, %2;" : "=f"(lo), "=f"(hi) : "l"(v));
}
__device__ __forceinline__ void ffma2(u64& acc, u64 a, u64 b) {
    asm("fma.rn.f32x2 %0, %1, %2, %0;" : "+l"(acc) : "l"(a), "l"(b));
}

// ---------------- tensor-core helpers ----------------
__device__ __forceinline__ void ldsm4(unsigned& r0, unsigned& r1, unsigned& r2, unsigned& r3,
                                      unsigned addr) {
    asm volatile("ldmatrix.sync.aligned.m8n8.x4.shared.b16 {%0,%1,%2,%3}, [%4];"
                 : "=r"(r0), "=r"(r1), "=r"(r2), "=r"(r3) : "r"(addr));
}
__device__ __forceinline__ void mma_bf16(float* c, const unsigned* a, const unsigned* b) {
    asm volatile("mma.sync.aligned.m16n8k16.row.col.f32.bf16.bf16.f32 "
                 "{%0,%1,%2,%3}, {%4,%5,%6,%7}, {%8,%9}, {%0,%1,%2,%3};"
                 : "+f"(c[0]), "+f"(c[1]), "+f"(c[2]), "+f"(c[3])
                 : "r"(a[0]), "r"(a[1]), "r"(a[2]), "r"(a[3]), "r"(b[0]), "r"(b[1]));
}

// ---------------- bf16 split conversion pre-passes ----------------
__global__ void convert_h_kernel(const float* __restrict__ h) {
    size_t i = ((size_t)blockIdx.x * blockDim.x + threadIdx.x) * 4;
    if (i >= (size_t)NN * IN_DIM) return;
    float4 v = *reinterpret_cast<const float4*>(&h[i]);
    __nv_bfloat16 hx = __float2bfloat16(v.x);
    __nv_bfloat16 hy = __float2bfloat16(v.y);
    __nv_bfloat16 hz = __float2bfloat16(v.z);
    __nv_bfloat16 hw = __float2bfloat16(v.w);
    __nv_bfloat16 lx = __float2bfloat16(v.x - __bfloat162float(hx));
    __nv_bfloat16 ly = __float2bfloat16(v.y - __bfloat162float(hy));
    __nv_bfloat16 lz = __float2bfloat16(v.z - __bfloat162float(hz));
    __nv_bfloat16 lw = __float2bfloat16(v.w - __bfloat162float(hw));
    *reinterpret_cast<__nv_bfloat162*>(&g_h_hi[i])     = __nv_bfloat162(hx, hy);
    *reinterpret_cast<__nv_bfloat162*>(&g_h_hi[i + 2]) = __nv_bfloat162(hz, hw);
    *reinterpret_cast<__nv_bfloat162*>(&g_h_lo[i])     = __nv_bfloat162(lx, ly);
    *reinterpret_cast<__nv_bfloat162*>(&g_h_lo[i + 2]) = __nv_bfloat162(lz, lw);
}

__global__ void convert_W1_kernel(const float* __restrict__ W1) {
    int idx = blockIdx.x * blockDim.x + threadIdx.x;   // over 512*256
    if (idx >= IN_DIM * HID_DIM) return;
    int k = idx >> 8;           // /HID_DIM
    int n = idx & 255;
    float v = W1[idx];
    __nv_bfloat16 hi = __float2bfloat16(v);
    __nv_bfloat16 lo = __float2bfloat16(v - __bfloat162float(hi));
    g_W1t_hi[(size_t)n * IN_DIM + k] = hi;
    g_W1t_lo[(size_t)n * IN_DIM + k] = lo;
}

// ---------------- GEMM1: bf16 split-3 tensor-core MMA ----------------
// C[M,256] = relu( A[M,512] @ W1 + b1 ), A,B pre-split to bf16 hi/lo.
// BM=128, BN=128, BK=32; 8 warps (4x2); warp tile 32x64.
#define SP 40   // smem row stride (bf16 elems), conflict-free for ldmatrix

__global__ __launch_bounds__(256, 1) void mma_gemm1_kernel(
    const __nv_bfloat16* __restrict__ Ahi, const __nv_bfloat16* __restrict__ Alo,
    const __nv_bfloat16* __restrict__ Bhi, const __nv_bfloat16* __restrict__ Blo,  // [N][K]
    const float* __restrict__ bias, float* __restrict__ C, int M) {
    __shared__ __align__(16) __nv_bfloat16 sAhi[128 * SP];
    __shared__ __align__(16) __nv_bfloat16 sAlo[128 * SP];
    __shared__ __align__(16) __nv_bfloat16 sBhi[128 * SP];
    __shared__ __align__(16) __nv_bfloat16 sBlo[128 * SP];

    const int tid = threadIdx.x;
    const int lane = tid & 31;
    const int warp = tid >> 5;
    const int warpM = warp >> 1;        // 0..3 -> 32 rows each
    const int warpN = warp & 1;         // 0..1 -> 64 cols each
    const int aBase = blockIdx.y * 128;
    const int bBase = blockIdx.x * 128;

    float acc[2][8][4] = {};

    const unsigned uAhi = (unsigned)__cvta_generic_to_shared(sAhi);
    const unsigned uAlo = (unsigned)__cvta_generic_to_shared(sAlo);
    const unsigned uBhi = (unsigned)__cvta_generic_to_shared(sBhi);
    const unsigned uBlo = (unsigned)__cvta_generic_to_shared(sBlo);

    // ldmatrix per-lane byte offsets
    const int aoff0 = ((warpM * 32 + (lane & 15)) * SP + (lane >> 4) * 8) * 2;
    const int aoff1 = aoff0 + 16 * SP * 2;
    const int g = lane >> 3, r = lane & 7;
    const int boff = ((warpN * 64 + r + ((g & 2) ? 8 : 0)) * SP + ((g & 1) ? 8 : 0)) * 2;

    for (int k0 = 0; k0 < IN_DIM; k0 += 32) {
        // A tiles: 128 rows x 32 cols bf16 = 512 uint4 per array; 2 per thread per array
        #pragma unroll
        for (int i = 0; i < 2; i++) {
            int f = tid + i * 256;
            int row = f >> 2, seg = f & 3;
            int gm = aBase + row;
            uint4 vh = make_uint4(0, 0, 0, 0), vl = make_uint4(0, 0, 0, 0);
            if (gm < M) {
                size_t go = (size_t)gm * IN_DIM + k0 + seg * 8;
                vh = *reinterpret_cast<const uint4*>(&Ahi[go]);
                vl = *reinterpret_cast<const uint4*>(&Alo[go]);
            }
            int so = row * SP + seg * 8;
            *reinterpret_cast<uint4*>(&sAhi[so]) = vh;
            *reinterpret_cast<uint4*>(&sAlo[so]) = vl;
        }
        // B tiles: 128 n-rows x 32 k cols (already [N][K] in global)
        #pragma unroll
        for (int i = 0; i < 2; i++) {
            int f = tid + i * 256;
            int row = f >> 2, seg = f & 3;
            size_t go = (size_t)(bBase + row) * IN_DIM + k0 + seg * 8;
            int so = row * SP + seg * 8;
            *reinterpret_cast<uint4*>(&sBhi[so]) = *reinterpret_cast<const uint4*>(&Bhi[go]);
            *reinterpret_cast<uint4*>(&sBlo[so]) = *reinterpret_cast<const uint4*>(&Blo[go]);
        }
        __syncthreads();

        #pragma unroll
        for (int kk = 0; kk < 32; kk += 16) {
            unsigned ahi[2][4], alo[2][4], bhi[8][2], blo[8][2];
            ldsm4(ahi[0][0], ahi[0][1], ahi[0][2], ahi[0][3], uAhi + aoff0 + kk * 2);
            ldsm4(ahi[1][0], ahi[1][1], ahi[1][2], ahi[1][3], uAhi + aoff1 + kk * 2);
            ldsm4(alo[0][0], alo[0][1], alo[0][2], alo[0][3], uAlo + aoff0 + kk * 2);
            ldsm4(alo[1][0], alo[1][1], alo[1][2], alo[1][3], uAlo + aoff1 + kk * 2);
            #pragma unroll
            for (int n2 = 0; n2 < 4; n2++) {
                int off = boff + n2 * 16 * SP * 2 + kk * 2;
                ldsm4(bhi[2 * n2][0], bhi[2 * n2][1], bhi[2 * n2 + 1][0], bhi[2 * n2 + 1][1],
                      uBhi + off);
                ldsm4(blo[2 * n2][0], blo[2 * n2][1], blo[2 * n2 + 1][0], blo[2 * n2 + 1][1],
                      uBlo + off);
            }
            #pragma unroll
            for (int mi = 0; mi < 2; mi++)
                #pragma unroll
                for (int ni = 0; ni < 8; ni++) {
                    mma_bf16(acc[mi][ni], ahi[mi], bhi[ni]);   // hi*hi
                    mma_bf16(acc[mi][ni], ahi[mi], blo[ni]);   // hi*lo
                    mma_bf16(acc[mi][ni], alo[mi], bhi[ni]);   // lo*hi
                }
        }
        __syncthreads();
    }

    // epilogue: bias + relu, fp32 out
    #pragma unroll
    for (int mi = 0; mi < 2; mi++) {
        #pragma unroll
        for (int ni = 0; ni < 8; ni++) {
            int gn = bBase + warpN * 64 + ni * 8 + (lane & 3) * 2;
            float2 bs = *reinterpret_cast<const float2*>(&bias[gn]);
            int gm0 = aBase + warpM * 32 + mi * 16 + (lane >> 2);
            int gm1 = gm0 + 8;
            if (gm0 < M) {
                float2 v;
                v.x = fmaxf(acc[mi][ni][0] + bs.x, 0.f);
                v.y = fmaxf(acc[mi][ni][1] + bs.y, 0.f);
                *reinterpret_cast<float2*>(&C[(size_t)gm0 * HID_DIM + gn]) = v;
            }
            if (gm1 < M) {
                float2 v;
                v.x = fmaxf(acc[mi][ni][2] + bs.x, 0.f);
                v.y = fmaxf(acc[mi][ni][3] + bs.y, 0.f);
                *reinterpret_cast<float2*>(&C[(size_t)gm1 * HID_DIM + gn]) = v;
            }
        }
    }
}

// ---------------- init ----------------
__global__ void init_zero_kernel() {
    int i = blockIdx.x * blockDim.x + threadIdx.x;
    if (i < NN) {
        g_deg_out[i] = 0;
        g_deg_in[i]  = 0;
        g_fill[i]    = 0;
    }
}

// ---------------- degrees ----------------
__global__ void degree_kernel(const int* __restrict__ src, const int* __restrict__ dst) {
    int e = blockIdx.x * blockDim.x + threadIdx.x;
    if (e < NE) {
        atomicAdd(&g_deg_out[src[e]], 1);
        atomicAdd(&g_deg_in [dst[e]], 1);
    }
}

__global__ void norm_kernel() {
    int i = blockIdx.x * blockDim.x + threadIdx.x;
    if (i < NN) {
        g_norm_src[i] = rsqrtf((float)max(g_deg_out[i], 1));
        g_norm_dst[i] = rsqrtf((float)max(g_deg_in [i], 1));
    }
}

// ---------------- exclusive scan of deg_in -> g_ptr (3 kernels) ----------------
__global__ void scan_block_kernel() {
    __shared__ int s[512];
    int tid = threadIdx.x;
    int i = blockIdx.x * 512 + tid;
    int v = (i < NN) ? g_deg_in[i] : 0;
    s[tid] = v;
    __syncthreads();
    #pragma unroll
    for (int off = 1; off < 512; off <<= 1) {
        int t = (tid >= off) ? s[tid - off] : 0;
        __syncthreads();
        s[tid] += t;
        __syncthreads();
    }
    if (i < NN) g_ptr[i] = s[tid] - v;            // block-local exclusive
    if (tid == 511) g_bsum[blockIdx.x] = s[511];  // block total
}

__global__ void scan_bsum_kernel(int nb) {
    __shared__ int s[128];
    int tid = threadIdx.x;
    int v = (tid < nb) ? g_bsum[tid] : 0;
    s[tid] = v;
    __syncthreads();
    #pragma unroll
    for (int off = 1; off < 128; off <<= 1) {
        int t = (tid >= off) ? s[tid - off] : 0;
        __syncthreads();
        s[tid] += t;
        __syncthreads();
    }
    if (tid < nb) g_bsum[tid] = s[tid] - v;       // exclusive in place
}

__global__ void scan_add_kernel() {
    int i = blockIdx.x * blockDim.x + threadIdx.x;
    if (i < NN)       g_ptr[i] += g_bsum[i >> 9];
    else if (i == NN) g_ptr[NN] = NE;
}

// ---------------- CSR fill (dst-sorted edge list) ----------------
__global__ void csr_fill_kernel(const int* __restrict__ src, const int* __restrict__ dst) {
    int e = blockIdx.x * blockDim.x + threadIdx.x;
    if (e < NE) {
        int d = dst[e];
        int pos = g_ptr[d] + atomicAdd(&g_fill[d], 1);
        g_csr_src[pos] = src[e];
        g_csr_eid[pos] = e;
    }
}

// ---------------- SGEMM with packed f32x2 accumulation (GEMM2) ----------------
template <int BM, int BN, int BK, int TM, int TN, bool RELU>
__global__ void sgemm_kernel(const float* __restrict__ A, const float* __restrict__ B,
                             const float* __restrict__ bias,
                             float* __restrict__ C, float* __restrict__ C2,
                             int M, int N, int K) {
    constexpr int THREADS = (BM / TM) * (BN / TN);
    __shared__ __align__(16) float As[BK][BM];
    __shared__ __align__(16) float Bs[BK][BN];

    const int tid  = threadIdx.x;
    const int tcol = tid % (BN / TN);
    const int trow = tid / (BN / TN);
    const int aBase = blockIdx.y * BM;
    const int bBase = blockIdx.x * BN;

    u64 acc2[TM / 2][TN];
    #pragma unroll
    for (int i = 0; i < TM / 2; i++)
        #pragma unroll
        for (int j = 0; j < TN; j++) acc2[i][j] = 0ULL;

    for (int k0 = 0; k0 < K; k0 += BK) {
        #pragma unroll
        for (int i = tid * 4; i < BM * BK; i += THREADS * 4) {
            int m = i / BK, k = i % BK;
            int gm = aBase + m;
            float4 v = make_float4(0.f, 0.f, 0.f, 0.f);
            if (gm < M) v = *reinterpret_cast<const float4*>(&A[(size_t)gm * K + k0 + k]);
            As[k + 0][m] = v.x; As[k + 1][m] = v.y; As[k + 2][m] = v.z; As[k + 3][m] = v.w;
        }
        #pragma unroll
        for (int i = tid * 4; i < BK * BN; i += THREADS * 4) {
            int k = i / BN, n = i % BN;
            *reinterpret_cast<float4*>(&Bs[k][n]) =
                *reinterpret_cast<const float4*>(&B[(size_t)(k0 + k) * N + bBase + n]);
        }
        __syncthreads();

        #pragma unroll
        for (int k = 0; k < BK; ++k) {
            u64 a2[TM / 2];
            #pragma unroll
            for (int i = 0; i < TM / 2; i++)
                a2[i] = *reinterpret_cast<const u64*>(&As[k][trow * TM + 2 * i]);
            u64 b2[TN];
            #pragma unroll
            for (int j = 0; j < TN; j++) {
                float b = Bs[k][tcol * TN + j];
                b2[j] = pk2(b, b);
            }
            #pragma unroll
            for (int i = 0; i < TM / 2; i++)
                #pragma unroll
                for (int j = 0; j < TN; j++) ffma2(acc2[i][j], a2[i], b2[j]);
        }
        __syncthreads();
    }

    #pragma unroll
    for (int i2 = 0; i2 < TM / 2; i2++) {
        float r0[TN], r1[TN];
        #pragma unroll
        for (int j = 0; j < TN; j++) upk2(acc2[i2][j], r0[j], r1[j]);

        #pragma unroll
        for (int half = 0; half < 2; half++) {
            int gm = aBase + trow * TM + 2 * i2 + half;
            if (gm >= M) continue;
            const float* rr = half ? r1 : r0;
            #pragma unroll
            for (int j = 0; j < TN; j += 4) {
                int gn = bBase + tcol * TN + j;
                float4 r;
                r.x = rr[j + 0] + bias[gn + 0];
                r.y = rr[j + 1] + bias[gn + 1];
                r.z = rr[j + 2] + bias[gn + 2];
                r.w = rr[j + 3] + bias[gn + 3];
                if (RELU) {
                    r.x = fmaxf(r.x, 0.f); r.y = fmaxf(r.y, 0.f);
                    r.z = fmaxf(r.z, 0.f); r.w = fmaxf(r.w, 0.f);
                }
                *reinterpret_cast<float4*>(&C[(size_t)gm * N + gn]) = r;
                if (C2) *reinterpret_cast<float4*>(&C2[(size_t)gm * N + gn]) = r;
            }
        }
    }
}

// ---------------- propagation hop: warp per dst node, CSR gather ----------------
__global__ void prop_kernel(int dir) {
    const float* __restrict__ fin  = dir ? g_featB : g_featA;
    float*       __restrict__ fout = dir ? g_featA : g_featB;

    int wid  = (blockIdx.x * blockDim.x + threadIdx.x) >> 5;
    int lane = threadIdx.x & 31;
    if (wid >= NN) return;

    int beg = g_ptr[wid], end = g_ptr[wid + 1];
    float acc0 = 0.f, acc1 = 0.f;

    int j = beg;
    for (; j + 4 <= end; j += 4) {
        int s0 = g_csr_src[j + 0], s1 = g_csr_src[j + 1];
        int s2 = g_csr_src[j + 2], s3 = g_csr_src[j + 3];
        float w0 = g_norm_src[s0], w1 = g_norm_src[s1];
        float w2 = g_norm_src[s2], w3 = g_norm_src[s3];
        const float* p0 = &fin[(size_t)s0 * OUT_DIM];
        const float* p1 = &fin[(size_t)s1 * OUT_DIM];
        const float* p2 = &fin[(size_t)s2 * OUT_DIM];
        const float* p3 = &fin[(size_t)s3 * OUT_DIM];
        acc0 += w0 * p0[lane]      + w1 * p1[lane]      + w2 * p2[lane]      + w3 * p3[lane];
        acc1 += w0 * p0[lane + 32] + w1 * p1[lane + 32] + w2 * p2[lane + 32] + w3 * p3[lane + 32];
    }
    for (; j < end; ++j) {
        int s = g_csr_src[j];
        float w = g_norm_src[s];
        const float* p = &fin[(size_t)s * OUT_DIM];
        acc0 += w * p[lane];
        acc1 += w * p[lane + 32];
    }

    float nd = g_norm_dst[wid];
    size_t o = (size_t)wid * OUT_DIM;
    fout[o + lane]      = (1.0f - ALPHA) * nd * acc0 + ALPHA * g_feat0[o + lane];
    fout[o + 32 + lane] = (1.0f - ALPHA) * nd * acc1 + ALPHA * g_feat0[o + 32 + lane];
}

// ---------------- per-node attention dot products ----------------
__global__ void sd_kernel(const float* __restrict__ w_src, const float* __restrict__ w_dst) {
    int wid  = (blockIdx.x * blockDim.x + threadIdx.x) >> 5;
    int lane = threadIdx.x & 31;
    if (wid >= NN) return;
    size_t o = (size_t)wid * OUT_DIM;
    float f0 = g_featA[o + lane], f1 = g_featA[o + 32 + lane];
    float s = f0 * w_src[lane] + f1 * w_src[lane + 32];
    float d = f0 * w_dst[lane] + f1 * w_dst[lane + 32];
    #pragma unroll
    for (int off = 16; off; off >>= 1) {
        s += __shfl_xor_sync(0xFFFFFFFFu, s, off);
        d += __shfl_xor_sync(0xFFFFFFFFu, d, off);
    }
    if (lane == 0) { g_s[wid] = s; g_d[wid] = d; }
}

// ---------------- edge-softmax per dst node ----------------
__global__ void attn_kernel(float* __restrict__ attn_out) {
    int wid  = (blockIdx.x * blockDim.x + threadIdx.x) >> 5;
    int lane = threadIdx.x & 31;
    if (wid >= NN) return;
    int beg = g_ptr[wid], end = g_ptr[wid + 1];
    if (beg == end) return;
    float dn = g_d[wid];

    float m = -2.0f;  // tanh >= -1
    for (int j = beg + lane; j < end; j += 32) {
        float e = tanhf(g_s[g_csr_src[j]] + dn);
        g_e[j] = e;
        m = fmaxf(m, e);
    }
    #pragma unroll
    for (int off = 16; off; off >>= 1)
        m = fmaxf(m, __shfl_xor_sync(0xFFFFFFFFu, m, off));

    float sum = 0.f;
    for (int j = beg + lane; j < end; j += 32)
        sum += __expf(g_e[j] - m);
    #pragma unroll
    for (int off = 16; off; off >>= 1)
        sum += __shfl_xor_sync(0xFFFFFFFFu, sum, off);

    float inv = 1.0f / sum;
    for (int j = beg + lane; j < end; j += 32)
        attn_out[g_csr_eid[j]] = __expf(g_e[j] - m) * inv;
}

// ---------------- log_softmax over 64 features ----------------
__global__ void logsoftmax_kernel(float* __restrict__ out) {
    int wid  = (blockIdx.x * blockDim.x + threadIdx.x) >> 5;
    int lane = threadIdx.x & 31;
    if (wid >= NN) return;
    size_t o = (size_t)wid * OUT_DIM;
    float f0 = g_featA[o + lane], f1 = g_featA[o + 32 + lane];
    float m = fmaxf(f0, f1);
    #pragma unroll
    for (int off = 16; off; off >>= 1)
        m = fmaxf(m, __shfl_xor_sync(0xFFFFFFFFu, m, off));
    float sum = __expf(f0 - m) + __expf(f1 - m);
    #pragma unroll
    for (int off = 16; off; off >>= 1)
        sum += __shfl_xor_sync(0xFFFFFFFFu, sum, off);
    float ls = m + logf(sum);
    out[o + lane]      = f0 - ls;
    out[o + 32 + lane] = f1 - ls;
}

// ---------------- launch ----------------
extern "C" void kernel_launch(void* const* d_in, const int* in_sizes, int n_in,
                              void* d_out, int out_size) {
    const float* h     = (const float*)d_in[0];
    const int*   src   = (const int*)  d_in[1];
    const int*   dst   = (const int*)  d_in[2];
    const float* W1    = (const float*)d_in[3];
    const float* b1    = (const float*)d_in[4];
    const float* W2    = (const float*)d_in[5];
    const float* b2    = (const float*)d_in[6];
    const float* w_src = (const float*)d_in[7];
    const float* w_dst = (const float*)d_in[8];
    float* out = (float*)d_out;

    float *p_hidden, *p_feat0, *p_featA;
    cudaGetSymbolAddress((void**)&p_hidden, g_hidden);
    cudaGetSymbolAddress((void**)&p_feat0,  g_feat0);
    cudaGetSymbolAddress((void**)&p_featA,  g_featA);
    __nv_bfloat16 *p_hhi, *p_hlo, *p_w1hi, *p_w1lo;
    cudaGetSymbolAddress((void**)&p_hhi,  g_h_hi);
    cudaGetSymbolAddress((void**)&p_hlo,  g_h_lo);
    cudaGetSymbolAddress((void**)&p_w1hi, g_W1t_hi);
    cudaGetSymbolAddress((void**)&p_w1lo, g_W1t_lo);

    const int nodeBlocks = (NN + 255) / 256;
    const int edgeBlocks = (NE + 255) / 256;
    const int warpNodeBlocks = (NN + 7) / 8;  // 256 threads = 8 warps, warp per node
    const int nbScan = (NN + 511) / 512;      // 98

    // bf16 split conversions (independent of graph prep)
    convert_h_kernel<<<((NN * (size_t)IN_DIM / 4) + 255) / 256, 256>>>(h);
    convert_W1_kernel<<<(IN_DIM * HID_DIM + 255) / 256, 256>>>(W1);

    init_zero_kernel<<<nodeBlocks, 256>>>();
    degree_kernel<<<edgeBlocks, 256>>>(src, dst);
    norm_kernel<<<nodeBlocks, 256>>>();
    scan_block_kernel<<<nbScan, 512>>>();
    scan_bsum_kernel<<<1, 128>>>(nbScan);
    scan_add_kernel<<<(NN + 1 + 255) / 256, 256>>>();
    csr_fill_kernel<<<edgeBlocks, 256>>>(src, dst);

    // GEMM1 (tensor core): hidden = relu(h @ W1 + b1)   [50000x512]@[512x256]
    {
        dim3 grid(HID_DIM / 128, (NN + 127) / 128);
        mma_gemm1_kernel<<<grid, 256>>>(p_hhi, p_hlo, p_w1hi, p_w1lo, b1, p_hidden, NN);
    }
    // GEMM2: feat0 = hidden @ W2 + b2     [50000x256] @ [256x64]  (also writes featA)
    {
        dim3 grid(OUT_DIM / 64, (NN + 127) / 128);
        sgemm_kernel<128, 64, 16, 8, 4, false><<<grid, 256>>>(
            p_hidden, W2, b2, p_feat0, p_featA, NN, OUT_DIM, HID_DIM);
    }

    // 4 propagation hops (ping-pong, ends in g_featA)
    prop_kernel<<<warpNodeBlocks, 256>>>(0);
    prop_kernel<<<warpNodeBlocks, 256>>>(1);
    prop_kernel<<<warpNodeBlocks, 256>>>(0);
    prop_kernel<<<warpNodeBlocks, 256>>>(1);

    sd_kernel<<<warpNodeBlocks, 256>>>(w_src, w_dst);
    attn_kernel<<<warpNodeBlocks, 256>>>(out + (size_t)NN * OUT_DIM);
    logsoftmax_kernel<<<warpNodeBlocks, 256>>>(out);
}

// round 8
// speedup vs baseline: 1.3234x; 1.0499x over previous
#include <cuda_runtime.h>
#include <cuda_bf16.h>
#include <math.h>

#define NN      50000
#define NE      1600000
#define IN_DIM  512
#define HID_DIM 256
#define OUT_DIM 64
#define ALPHA   0.1f

// ---------------- static device scratch (no allocations allowed) ----------------
__device__ float g_hidden[(size_t)NN * HID_DIM];   // 51.2 MB
__device__ float g_feat0 [(size_t)NN * OUT_DIM];   // 12.8 MB
__device__ float g_featA [(size_t)NN * OUT_DIM];
__device__ float g_featB [(size_t)NN * OUT_DIM];
__device__ int   g_deg_out[NN];
__device__ int   g_deg_in [NN];
__device__ float g_norm_src[NN];
__device__ float g_norm_dst[NN];
__device__ int   g_ptr [NN + 1];
__device__ int   g_fill[NN];
__device__ int   g_bsum[256];
__device__ int   g_csr_src[NE];
__device__ int   g_csr_eid[NE];
__device__ float g_s[NN];
__device__ float g_d[NN];
__device__ float g_e[NE];

// bf16 split operands for tensor-core GEMM1
__device__ __nv_bfloat16 g_h_hi [(size_t)NN * IN_DIM];
__device__ __nv_bfloat16 g_h_lo [(size_t)NN * IN_DIM];
__device__ __nv_bfloat16 g_W1t_hi[(size_t)HID_DIM * IN_DIM];  // [N][K] transposed
__device__ __nv_bfloat16 g_W1t_lo[(size_t)HID_DIM * IN_DIM];

// ---------------- packed f32x2 helpers ----------------
typedef unsigned long long u64;

__device__ __forceinline__ u64 pk2(float lo, float hi) {
    u64 r;
    asm("mov.b64 %0, {%1, %2};" : "=l"(r) : "f"(lo), "f"(hi));
    return r;
}
__device__ __forceinline__ void upk2(u64 v, float& lo, float& hi) {
    asm("mov.b64 {%0, %1}, %2;" : "=f"(lo), "=f"(hi) : "l"(v));
}
__device__ __forceinline__ void ffma2(u64& acc, u64 a, u64 b) {
    asm("fma.rn.f32x2 %0, %1, %2, %0;" : "+l"(acc) : "l"(a), "l"(b));
}

// ---------------- tensor-core helpers ----------------
__device__ __forceinline__ void ldsm4(unsigned& r0, unsigned& r1, unsigned& r2, unsigned& r3,
                                      unsigned addr) {
    asm volatile("ldmatrix.sync.aligned.m8n8.x4.shared.b16 {%0,%1,%2,%3}, [%4];"
                 : "=r"(r0), "=r"(r1), "=r"(r2), "=r"(r3) : "r"(addr));
}
__device__ __forceinline__ void mma_bf16(float* c, const unsigned* a, const unsigned* b) {
    asm volatile("mma.sync.aligned.m16n8k16.row.col.f32.bf16.bf16.f32 "
                 "{%0,%1,%2,%3}, {%4,%5,%6,%7}, {%8,%9}, {%0,%1,%2,%3};"
                 : "+f"(c[0]), "+f"(c[1]), "+f"(c[2]), "+f"(c[3])
                 : "r"(a[0]), "r"(a[1]), "r"(a[2]), "r"(a[3]), "r"(b[0]), "r"(b[1]));
}

// ---------------- bf16 split conversion pre-passes ----------------
__global__ void convert_h_kernel(const float* __restrict__ h) {
    size_t i = ((size_t)blockIdx.x * blockDim.x + threadIdx.x) * 4;
    if (i >= (size_t)NN * IN_DIM) return;
    float4 v = *reinterpret_cast<const float4*>(&h[i]);
    __nv_bfloat16 hx = __float2bfloat16(v.x);
    __nv_bfloat16 hy = __float2bfloat16(v.y);
    __nv_bfloat16 hz = __float2bfloat16(v.z);
    __nv_bfloat16 hw = __float2bfloat16(v.w);
    __nv_bfloat16 lx = __float2bfloat16(v.x - __bfloat162float(hx));
    __nv_bfloat16 ly = __float2bfloat16(v.y - __bfloat162float(hy));
    __nv_bfloat16 lz = __float2bfloat16(v.z - __bfloat162float(hz));
    __nv_bfloat16 lw = __float2bfloat16(v.w - __bfloat162float(hw));
    *reinterpret_cast<__nv_bfloat162*>(&g_h_hi[i])     = __nv_bfloat162(hx, hy);
    *reinterpret_cast<__nv_bfloat162*>(&g_h_hi[i + 2]) = __nv_bfloat162(hz, hw);
    *reinterpret_cast<__nv_bfloat162*>(&g_h_lo[i])     = __nv_bfloat162(lx, ly);
    *reinterpret_cast<__nv_bfloat162*>(&g_h_lo[i + 2]) = __nv_bfloat162(lz, lw);
}

__global__ void convert_W1_kernel(const float* __restrict__ W1) {
    int idx = blockIdx.x * blockDim.x + threadIdx.x;   // over 512*256
    if (idx >= IN_DIM * HID_DIM) return;
    int k = idx >> 8;           // /HID_DIM
    int n = idx & 255;
    float v = W1[idx];
    __nv_bfloat16 hi = __float2bfloat16(v);
    __nv_bfloat16 lo = __float2bfloat16(v - __bfloat162float(hi));
    g_W1t_hi[(size_t)n * IN_DIM + k] = hi;
    g_W1t_lo[(size_t)n * IN_DIM + k] = lo;
}

// ---------------- GEMM1: bf16 split-3 tensor-core MMA ----------------
#define SP 40   // smem row stride (bf16 elems), conflict-free for ldmatrix

__global__ __launch_bounds__(256, 1) void mma_gemm1_kernel(
    const __nv_bfloat16* __restrict__ Ahi, const __nv_bfloat16* __restrict__ Alo,
    const __nv_bfloat16* __restrict__ Bhi, const __nv_bfloat16* __restrict__ Blo,  // [N][K]
    const float* __restrict__ bias, float* __restrict__ C, int M) {
    __shared__ __align__(16) __nv_bfloat16 sAhi[128 * SP];
    __shared__ __align__(16) __nv_bfloat16 sAlo[128 * SP];
    __shared__ __align__(16) __nv_bfloat16 sBhi[128 * SP];
    __shared__ __align__(16) __nv_bfloat16 sBlo[128 * SP];

    const int tid = threadIdx.x;
    const int lane = tid & 31;
    const int warp = tid >> 5;
    const int warpM = warp >> 1;        // 0..3 -> 32 rows each
    const int warpN = warp & 1;         // 0..1 -> 64 cols each
    const int aBase = blockIdx.y * 128;
    const int bBase = blockIdx.x * 128;

    float acc[2][8][4] = {};

    const unsigned uAhi = (unsigned)__cvta_generic_to_shared(sAhi);
    const unsigned uAlo = (unsigned)__cvta_generic_to_shared(sAlo);
    const unsigned uBhi = (unsigned)__cvta_generic_to_shared(sBhi);
    const unsigned uBlo = (unsigned)__cvta_generic_to_shared(sBlo);

    const int aoff0 = ((warpM * 32 + (lane & 15)) * SP + (lane >> 4) * 8) * 2;
    const int aoff1 = aoff0 + 16 * SP * 2;
    const int g = lane >> 3, r = lane & 7;
    const int boff = ((warpN * 64 + r + ((g & 2) ? 8 : 0)) * SP + ((g & 1) ? 8 : 0)) * 2;

    for (int k0 = 0; k0 < IN_DIM; k0 += 32) {
        #pragma unroll
        for (int i = 0; i < 2; i++) {
            int f = tid + i * 256;
            int row = f >> 2, seg = f & 3;
            int gm = aBase + row;
            uint4 vh = make_uint4(0, 0, 0, 0), vl = make_uint4(0, 0, 0, 0);
            if (gm < M) {
                size_t go = (size_t)gm * IN_DIM + k0 + seg * 8;
                vh = *reinterpret_cast<const uint4*>(&Ahi[go]);
                vl = *reinterpret_cast<const uint4*>(&Alo[go]);
            }
            int so = row * SP + seg * 8;
            *reinterpret_cast<uint4*>(&sAhi[so]) = vh;
            *reinterpret_cast<uint4*>(&sAlo[so]) = vl;
        }
        #pragma unroll
        for (int i = 0; i < 2; i++) {
            int f = tid + i * 256;
            int row = f >> 2, seg = f & 3;
            size_t go = (size_t)(bBase + row) * IN_DIM + k0 + seg * 8;
            int so = row * SP + seg * 8;
            *reinterpret_cast<uint4*>(&sBhi[so]) = *reinterpret_cast<const uint4*>(&Bhi[go]);
            *reinterpret_cast<uint4*>(&sBlo[so]) = *reinterpret_cast<const uint4*>(&Blo[go]);
        }
        __syncthreads();

        #pragma unroll
        for (int kk = 0; kk < 32; kk += 16) {
            unsigned ahi[2][4], alo[2][4], bhi[8][2], blo[8][2];
            ldsm4(ahi[0][0], ahi[0][1], ahi[0][2], ahi[0][3], uAhi + aoff0 + kk * 2);
            ldsm4(ahi[1][0], ahi[1][1], ahi[1][2], ahi[1][3], uAhi + aoff1 + kk * 2);
            ldsm4(alo[0][0], alo[0][1], alo[0][2], alo[0][3], uAlo + aoff0 + kk * 2);
            ldsm4(alo[1][0], alo[1][1], alo[1][2], alo[1][3], uAlo + aoff1 + kk * 2);
            #pragma unroll
            for (int n2 = 0; n2 < 4; n2++) {
                int off = boff + n2 * 16 * SP * 2 + kk * 2;
                ldsm4(bhi[2 * n2][0], bhi[2 * n2][1], bhi[2 * n2 + 1][0], bhi[2 * n2 + 1][1],
                      uBhi + off);
                ldsm4(blo[2 * n2][0], blo[2 * n2][1], blo[2 * n2 + 1][0], blo[2 * n2 + 1][1],
                      uBlo + off);
            }
            #pragma unroll
            for (int mi = 0; mi < 2; mi++)
                #pragma unroll
                for (int ni = 0; ni < 8; ni++) {
                    mma_bf16(acc[mi][ni], ahi[mi], bhi[ni]);   // hi*hi
                    mma_bf16(acc[mi][ni], ahi[mi], blo[ni]);   // hi*lo
                    mma_bf16(acc[mi][ni], alo[mi], bhi[ni]);   // lo*hi
                }
        }
        __syncthreads();
    }

    #pragma unroll
    for (int mi = 0; mi < 2; mi++) {
        #pragma unroll
        for (int ni = 0; ni < 8; ni++) {
            int gn = bBase + warpN * 64 + ni * 8 + (lane & 3) * 2;
            float2 bs = *reinterpret_cast<const float2*>(&bias[gn]);
            int gm0 = aBase + warpM * 32 + mi * 16 + (lane >> 2);
            int gm1 = gm0 + 8;
            if (gm0 < M) {
                float2 v;
                v.x = fmaxf(acc[mi][ni][0] + bs.x, 0.f);
                v.y = fmaxf(acc[mi][ni][1] + bs.y, 0.f);
                *reinterpret_cast<float2*>(&C[(size_t)gm0 * HID_DIM + gn]) = v;
            }
            if (gm1 < M) {
                float2 v;
                v.x = fmaxf(acc[mi][ni][2] + bs.x, 0.f);
                v.y = fmaxf(acc[mi][ni][3] + bs.y, 0.f);
                *reinterpret_cast<float2*>(&C[(size_t)gm1 * HID_DIM + gn]) = v;
            }
        }
    }
}

// ---------------- init ----------------
__global__ void init_zero_kernel() {
    int i = blockIdx.x * blockDim.x + threadIdx.x;
    if (i < NN) {
        g_deg_out[i] = 0;
        g_deg_in[i]  = 0;
        g_fill[i]    = 0;
    }
}

// ---------------- degrees ----------------
__global__ void degree_kernel(const int* __restrict__ src, const int* __restrict__ dst) {
    int e = blockIdx.x * blockDim.x + threadIdx.x;
    if (e < NE) {
        atomicAdd(&g_deg_out[src[e]], 1);
        atomicAdd(&g_deg_in [dst[e]], 1);
    }
}

__global__ void norm_kernel() {
    int i = blockIdx.x * blockDim.x + threadIdx.x;
    if (i < NN) {
        g_norm_src[i] = rsqrtf((float)max(g_deg_out[i], 1));
        g_norm_dst[i] = rsqrtf((float)max(g_deg_in [i], 1));
    }
}

// ---------------- exclusive scan of deg_in -> g_ptr (3 kernels) ----------------
__global__ void scan_block_kernel() {
    __shared__ int s[512];
    int tid = threadIdx.x;
    int i = blockIdx.x * 512 + tid;
    int v = (i < NN) ? g_deg_in[i] : 0;
    s[tid] = v;
    __syncthreads();
    #pragma unroll
    for (int off = 1; off < 512; off <<= 1) {
        int t = (tid >= off) ? s[tid - off] : 0;
        __syncthreads();
        s[tid] += t;
        __syncthreads();
    }
    if (i < NN) g_ptr[i] = s[tid] - v;
    if (tid == 511) g_bsum[blockIdx.x] = s[511];
}

__global__ void scan_bsum_kernel(int nb) {
    __shared__ int s[128];
    int tid = threadIdx.x;
    int v = (tid < nb) ? g_bsum[tid] : 0;
    s[tid] = v;
    __syncthreads();
    #pragma unroll
    for (int off = 1; off < 128; off <<= 1) {
        int t = (tid >= off) ? s[tid - off] : 0;
        __syncthreads();
        s[tid] += t;
        __syncthreads();
    }
    if (tid < nb) g_bsum[tid] = s[tid] - v;
}

__global__ void scan_add_kernel() {
    int i = blockIdx.x * blockDim.x + threadIdx.x;
    if (i < NN)       g_ptr[i] += g_bsum[i >> 9];
    else if (i == NN) g_ptr[NN] = NE;
}

// ---------------- CSR fill (dst-sorted edge list) ----------------
__global__ void csr_fill_kernel(const int* __restrict__ src, const int* __restrict__ dst) {
    int e = blockIdx.x * blockDim.x + threadIdx.x;
    if (e < NE) {
        int d = dst[e];
        int pos = g_ptr[d] + atomicAdd(&g_fill[d], 1);
        g_csr_src[pos] = src[e];
        g_csr_eid[pos] = e;
    }
}

// ---------------- SGEMM with packed f32x2 accumulation (GEMM2) ----------------
template <int BM, int BN, int BK, int TM, int TN, bool RELU>
__global__ void sgemm_kernel(const float* __restrict__ A, const float* __restrict__ B,
                             const float* __restrict__ bias,
                             float* __restrict__ C,
                             int M, int N, int K) {
    constexpr int THREADS = (BM / TM) * (BN / TN);
    __shared__ __align__(16) float As[BK][BM];
    __shared__ __align__(16) float Bs[BK][BN];

    const int tid  = threadIdx.x;
    const int tcol = tid % (BN / TN);
    const int trow = tid / (BN / TN);
    const int aBase = blockIdx.y * BM;
    const int bBase = blockIdx.x * BN;

    u64 acc2[TM / 2][TN];
    #pragma unroll
    for (int i = 0; i < TM / 2; i++)
        #pragma unroll
        for (int j = 0; j < TN; j++) acc2[i][j] = 0ULL;

    for (int k0 = 0; k0 < K; k0 += BK) {
        #pragma unroll
        for (int i = tid * 4; i < BM * BK; i += THREADS * 4) {
            int m = i / BK, k = i % BK;
            int gm = aBase + m;
            float4 v = make_float4(0.f, 0.f, 0.f, 0.f);
            if (gm < M) v = *reinterpret_cast<const float4*>(&A[(size_t)gm * K + k0 + k]);
            As[k + 0][m] = v.x; As[k + 1][m] = v.y; As[k + 2][m] = v.z; As[k + 3][m] = v.w;
        }
        #pragma unroll
        for (int i = tid * 4; i < BK * BN; i += THREADS * 4) {
            int k = i / BN, n = i % BN;
            *reinterpret_cast<float4*>(&Bs[k][n]) =
                *reinterpret_cast<const float4*>(&B[(size_t)(k0 + k) * N + bBase + n]);
        }
        __syncthreads();

        #pragma unroll
        for (int k = 0; k < BK; ++k) {
            u64 a2[TM / 2];
            #pragma unroll
            for (int i = 0; i < TM / 2; i++)
                a2[i] = *reinterpret_cast<const u64*>(&As[k][trow * TM + 2 * i]);
            u64 b2[TN];
            #pragma unroll
            for (int j = 0; j < TN; j++) {
                float b = Bs[k][tcol * TN + j];
                b2[j] = pk2(b, b);
            }
            #pragma unroll
            for (int i = 0; i < TM / 2; i++)
                #pragma unroll
                for (int j = 0; j < TN; j++) ffma2(acc2[i][j], a2[i], b2[j]);
        }
        __syncthreads();
    }

    #pragma unroll
    for (int i2 = 0; i2 < TM / 2; i2++) {
        float r0[TN], r1[TN];
        #pragma unroll
        for (int j = 0; j < TN; j++) upk2(acc2[i2][j], r0[j], r1[j]);

        #pragma unroll
        for (int half = 0; half < 2; half++) {
            int gm = aBase + trow * TM + 2 * i2 + half;
            if (gm >= M) continue;
            const float* rr = half ? r1 : r0;
            #pragma unroll
            for (int j = 0; j < TN; j += 4) {
                int gn = bBase + tcol * TN + j;
                float4 r;
                r.x = rr[j + 0] + bias[gn + 0];
                r.y = rr[j + 1] + bias[gn + 1];
                r.z = rr[j + 2] + bias[gn + 2];
                r.w = rr[j + 3] + bias[gn + 3];
                if (RELU) {
                    r.x = fmaxf(r.x, 0.f); r.y = fmaxf(r.y, 0.f);
                    r.z = fmaxf(r.z, 0.f); r.w = fmaxf(r.w, 0.f);
                }
                *reinterpret_cast<float4*>(&C[(size_t)gm * N + gn]) = r;
            }
        }
    }
}

// ---------------- propagation hop: warp per dst node, CSR gather ----------------
__global__ void prop_kernel(const float* __restrict__ fin, float* __restrict__ fout) {
    int wid  = (blockIdx.x * blockDim.x + threadIdx.x) >> 5;
    int lane = threadIdx.x & 31;
    if (wid >= NN) return;

    int beg = g_ptr[wid], end = g_ptr[wid + 1];
    float acc0 = 0.f, acc1 = 0.f;

    int j = beg;
    for (; j + 4 <= end; j += 4) {
        int s0 = g_csr_src[j + 0], s1 = g_csr_src[j + 1];
        int s2 = g_csr_src[j + 2], s3 = g_csr_src[j + 3];
        float w0 = g_norm_src[s0], w1 = g_norm_src[s1];
        float w2 = g_norm_src[s2], w3 = g_norm_src[s3];
        const float* p0 = &fin[(size_t)s0 * OUT_DIM];
        const float* p1 = &fin[(size_t)s1 * OUT_DIM];
        const float* p2 = &fin[(size_t)s2 * OUT_DIM];
        const float* p3 = &fin[(size_t)s3 * OUT_DIM];
        acc0 += w0 * p0[lane]      + w1 * p1[lane]      + w2 * p2[lane]      + w3 * p3[lane];
        acc1 += w0 * p0[lane + 32] + w1 * p1[lane + 32] + w2 * p2[lane + 32] + w3 * p3[lane + 32];
    }
    for (; j < end; ++j) {
        int s = g_csr_src[j];
        float w = g_norm_src[s];
        const float* p = &fin[(size_t)s * OUT_DIM];
        acc0 += w * p[lane];
        acc1 += w * p[lane + 32];
    }

    float nd = g_norm_dst[wid];
    size_t o = (size_t)wid * OUT_DIM;
    fout[o + lane]      = (1.0f - ALPHA) * nd * acc0 + ALPHA * g_feat0[o + lane];
    fout[o + 32 + lane] = (1.0f - ALPHA) * nd * acc1 + ALPHA * g_feat0[o + 32 + lane];
}

// ---------------- final hop fused with sd + log_softmax ----------------
// Reads g_featB (hop 3 output); never materializes featA. Computes the final
// feat row in registers, then s/d attention dots and log_softmax in-place.
__global__ void prop_final_kernel(const float* __restrict__ w_src,
                                  const float* __restrict__ w_dst,
                                  float* __restrict__ out) {
    const float* __restrict__ fin = g_featB;

    int wid  = (blockIdx.x * blockDim.x + threadIdx.x) >> 5;
    int lane = threadIdx.x & 31;
    if (wid >= NN) return;

    int beg = g_ptr[wid], end = g_ptr[wid + 1];
    float acc0 = 0.f, acc1 = 0.f;

    int j = beg;
    for (; j + 4 <= end; j += 4) {
        int s0 = g_csr_src[j + 0], s1 = g_csr_src[j + 1];
        int s2 = g_csr_src[j + 2], s3 = g_csr_src[j + 3];
        float w0 = g_norm_src[s0], w1 = g_norm_src[s1];
        float w2 = g_norm_src[s2], w3 = g_norm_src[s3];
        const float* p0 = &fin[(size_t)s0 * OUT_DIM];
        const float* p1 = &fin[(size_t)s1 * OUT_DIM];
        const float* p2 = &fin[(size_t)s2 * OUT_DIM];
        const float* p3 = &fin[(size_t)s3 * OUT_DIM];
        acc0 += w0 * p0[lane]      + w1 * p1[lane]      + w2 * p2[lane]      + w3 * p3[lane];
        acc1 += w0 * p0[lane + 32] + w1 * p1[lane + 32] + w2 * p2[lane + 32] + w3 * p3[lane + 32];
    }
    for (; j < end; ++j) {
        int s = g_csr_src[j];
        float w = g_norm_src[s];
        const float* p = &fin[(size_t)s * OUT_DIM];
        acc0 += w * p[lane];
        acc1 += w * p[lane + 32];
    }

    float nd = g_norm_dst[wid];
    size_t o = (size_t)wid * OUT_DIM;
    float f0 = (1.0f - ALPHA) * nd * acc0 + ALPHA * g_feat0[o + lane];
    float f1 = (1.0f - ALPHA) * nd * acc1 + ALPHA * g_feat0[o + 32 + lane];

    // attention dot products
    float s = f0 * w_src[lane] + f1 * w_src[lane + 32];
    float d = f0 * w_dst[lane] + f1 * w_dst[lane + 32];
    #pragma unroll
    for (int off = 16; off; off >>= 1) {
        s += __shfl_xor_sync(0xFFFFFFFFu, s, off);
        d += __shfl_xor_sync(0xFFFFFFFFu, d, off);
    }
    if (lane == 0) { g_s[wid] = s; g_d[wid] = d; }

    // log_softmax over the 64 features
    float m = fmaxf(f0, f1);
    #pragma unroll
    for (int off = 16; off; off >>= 1)
        m = fmaxf(m, __shfl_xor_sync(0xFFFFFFFFu, m, off));
    float sum = __expf(f0 - m) + __expf(f1 - m);
    #pragma unroll
    for (int off = 16; off; off >>= 1)
        sum += __shfl_xor_sync(0xFFFFFFFFu, sum, off);
    float ls = m + logf(sum);
    out[o + lane]      = f0 - ls;
    out[o + 32 + lane] = f1 - ls;
}

// ---------------- edge-softmax per dst node ----------------
__global__ void attn_kernel(float* __restrict__ attn_out) {
    int wid  = (blockIdx.x * blockDim.x + threadIdx.x) >> 5;
    int lane = threadIdx.x & 31;
    if (wid >= NN) return;
    int beg = g_ptr[wid], end = g_ptr[wid + 1];
    if (beg == end) return;
    float dn = g_d[wid];

    float m = -2.0f;  // tanh >= -1
    for (int j = beg + lane; j < end; j += 32) {
        float e = tanhf(g_s[g_csr_src[j]] + dn);
        g_e[j] = e;
        m = fmaxf(m, e);
    }
    #pragma unroll
    for (int off = 16; off; off >>= 1)
        m = fmaxf(m, __shfl_xor_sync(0xFFFFFFFFu, m, off));

    float sum = 0.f;
    for (int j = beg + lane; j < end; j += 32)
        sum += __expf(g_e[j] - m);
    #pragma unroll
    for (int off = 16; off; off >>= 1)
        sum += __shfl_xor_sync(0xFFFFFFFFu, sum, off);

    float inv = 1.0f / sum;
    for (int j = beg + lane; j < end; j += 32)
        attn_out[g_csr_eid[j]] = __expf(g_e[j] - m) * inv;
}

// ---------------- launch (single stream, capture-safe) ----------------
extern "C" void kernel_launch(void* const* d_in, const int* in_sizes, int n_in,
                              void* d_out, int out_size) {
    const float* h     = (const float*)d_in[0];
    const int*   src   = (const int*)  d_in[1];
    const int*   dst   = (const int*)  d_in[2];
    const float* W1    = (const float*)d_in[3];
    const float* b1    = (const float*)d_in[4];
    const float* W2    = (const float*)d_in[5];
    const float* b2    = (const float*)d_in[6];
    const float* w_src = (const float*)d_in[7];
    const float* w_dst = (const float*)d_in[8];
    float* out = (float*)d_out;

    float *p_hidden, *p_feat0, *p_featA, *p_featB;
    cudaGetSymbolAddress((void**)&p_hidden, g_hidden);
    cudaGetSymbolAddress((void**)&p_feat0,  g_feat0);
    cudaGetSymbolAddress((void**)&p_featA,  g_featA);
    cudaGetSymbolAddress((void**)&p_featB,  g_featB);
    __nv_bfloat16 *p_hhi, *p_hlo, *p_w1hi, *p_w1lo;
    cudaGetSymbolAddress((void**)&p_hhi,  g_h_hi);
    cudaGetSymbolAddress((void**)&p_hlo,  g_h_lo);
    cudaGetSymbolAddress((void**)&p_w1hi, g_W1t_hi);
    cudaGetSymbolAddress((void**)&p_w1lo, g_W1t_lo);

    const int nodeBlocks = (NN + 255) / 256;
    const int edgeBlocks = (NE + 255) / 256;
    const int warpNodeBlocks = (NN + 7) / 8;
    const int nbScan = (NN + 511) / 512;      // 98

    // graph prep
    init_zero_kernel<<<nodeBlocks, 256>>>();
    degree_kernel<<<edgeBlocks, 256>>>(src, dst);
    norm_kernel<<<nodeBlocks, 256>>>();
    scan_block_kernel<<<nbScan, 512>>>();
    scan_bsum_kernel<<<1, 128>>>(nbScan);
    scan_add_kernel<<<(NN + 1 + 255) / 256, 256>>>();
    csr_fill_kernel<<<edgeBlocks, 256>>>(src, dst);

    // conversions + GEMMs
    convert_h_kernel<<<((NN * (size_t)IN_DIM / 4) + 255) / 256, 256>>>(h);
    convert_W1_kernel<<<(IN_DIM * HID_DIM + 255) / 256, 256>>>(W1);
    {
        dim3 grid(HID_DIM / 128, (NN + 127) / 128);
        mma_gemm1_kernel<<<grid, 256>>>(p_hhi, p_hlo, p_w1hi, p_w1lo, b1, p_hidden, NN);
    }
    {
        dim3 grid(OUT_DIM / 64, (NN + 127) / 128);
        sgemm_kernel<128, 64, 16, 8, 4, false><<<grid, 256>>>(
            p_hidden, W2, b2, p_feat0, NN, OUT_DIM, HID_DIM);
    }

    // 4 hops: feat0 -> B -> A -> B -> (fused: sd + log_softmax, writes out)
    prop_kernel<<<warpNodeBlocks, 256>>>(p_feat0, p_featB);
    prop_kernel<<<warpNodeBlocks, 256>>>(p_featB, p_featA);
    prop_kernel<<<warpNodeBlocks, 256>>>(p_featA, p_featB);
    prop_final_kernel<<<warpNodeBlocks, 256>>>(w_src, w_dst, out);

    attn_kernel<<<warpNodeBlocks, 256>>>(out + (size_t)NN * OUT_DIM);
}

// round 9
// speedup vs baseline: 1.4768x; 1.1159x over previous
#include <cuda_runtime.h>
#include <cuda_bf16.h>
#include <math.h>

#define NN      50000
#define NE      1600000
#define IN_DIM  512
#define HID_DIM 256
#define OUT_DIM 64
#define ALPHA   0.1f

// ---------------- static device scratch (no allocations allowed) ----------------
__device__ float g_feat0 [(size_t)NN * OUT_DIM];   // 12.8 MB
__device__ float g_featA [(size_t)NN * OUT_DIM];
__device__ float g_featB [(size_t)NN * OUT_DIM];
__device__ int   g_deg_out[NN];
__device__ int   g_deg_in [NN];
__device__ float g_norm_src[NN];
__device__ float g_norm_dst[NN];
__device__ int   g_ptr [NN + 1];
__device__ int   g_fill[NN];
__device__ int   g_bsum[256];
__device__ int   g_csr_src[NE];
__device__ int   g_csr_eid[NE];
__device__ float g_s[NN];
__device__ float g_d[NN];
__device__ float g_e[NE];

// bf16 split operands
__device__ __nv_bfloat16 g_h_hi  [(size_t)NN * IN_DIM];       // 51.2 MB
__device__ __nv_bfloat16 g_h_lo  [(size_t)NN * IN_DIM];
__device__ __nv_bfloat16 g_W1t_hi[(size_t)HID_DIM * IN_DIM];  // [N][K]
__device__ __nv_bfloat16 g_W1t_lo[(size_t)HID_DIM * IN_DIM];
__device__ __nv_bfloat16 g_hid_hi[(size_t)NN * HID_DIM];      // 25.6 MB
__device__ __nv_bfloat16 g_hid_lo[(size_t)NN * HID_DIM];
__device__ __nv_bfloat16 g_W2t_hi[(size_t)OUT_DIM * HID_DIM]; // [N][K]
__device__ __nv_bfloat16 g_W2t_lo[(size_t)OUT_DIM * HID_DIM];

// ---------------- tensor-core helpers ----------------
__device__ __forceinline__ void ldsm4(unsigned& r0, unsigned& r1, unsigned& r2, unsigned& r3,
                                      unsigned addr) {
    asm volatile("ldmatrix.sync.aligned.m8n8.x4.shared.b16 {%0,%1,%2,%3}, [%4];"
                 : "=r"(r0), "=r"(r1), "=r"(r2), "=r"(r3) : "r"(addr));
}
__device__ __forceinline__ void mma_bf16(float* c, const unsigned* a, const unsigned* b) {
    asm volatile("mma.sync.aligned.m16n8k16.row.col.f32.bf16.bf16.f32 "
                 "{%0,%1,%2,%3}, {%4,%5,%6,%7}, {%8,%9}, {%0,%1,%2,%3};"
                 : "+f"(c[0]), "+f"(c[1]), "+f"(c[2]), "+f"(c[3])
                 : "r"(a[0]), "r"(a[1]), "r"(a[2]), "r"(a[3]), "r"(b[0]), "r"(b[1]));
}
__device__ __forceinline__ void cpa16(unsigned dst, const void* src, bool valid) {
    int sz = valid ? 16 : 0;
    asm volatile("cp.async.cg.shared.global [%0], [%1], 16, %2;"
                 :: "r"(dst), "l"(src), "r"(sz));
}
__device__ __forceinline__ void cpa_commit() { asm volatile("cp.async.commit_group;"); }

// ---------------- bf16 split conversion pre-passes ----------------
__global__ void convert_h_kernel(const float* __restrict__ h) {
    size_t i = ((size_t)blockIdx.x * blockDim.x + threadIdx.x) * 4;
    if (i >= (size_t)NN * IN_DIM) return;
    float4 v = *reinterpret_cast<const float4*>(&h[i]);
    __nv_bfloat16 hx = __float2bfloat16(v.x);
    __nv_bfloat16 hy = __float2bfloat16(v.y);
    __nv_bfloat16 hz = __float2bfloat16(v.z);
    __nv_bfloat16 hw = __float2bfloat16(v.w);
    __nv_bfloat16 lx = __float2bfloat16(v.x - __bfloat162float(hx));
    __nv_bfloat16 ly = __float2bfloat16(v.y - __bfloat162float(hy));
    __nv_bfloat16 lz = __float2bfloat16(v.z - __bfloat162float(hz));
    __nv_bfloat16 lw = __float2bfloat16(v.w - __bfloat162float(hw));
    *reinterpret_cast<__nv_bfloat162*>(&g_h_hi[i])     = __nv_bfloat162(hx, hy);
    *reinterpret_cast<__nv_bfloat162*>(&g_h_hi[i + 2]) = __nv_bfloat162(hz, hw);
    *reinterpret_cast<__nv_bfloat162*>(&g_h_lo[i])     = __nv_bfloat162(lx, ly);
    *reinterpret_cast<__nv_bfloat162*>(&g_h_lo[i + 2]) = __nv_bfloat162(lz, lw);
}

__global__ void convert_W1_kernel(const float* __restrict__ W1) {
    int idx = blockIdx.x * blockDim.x + threadIdx.x;   // over 512*256
    if (idx >= IN_DIM * HID_DIM) return;
    int k = idx >> 8;           // /HID_DIM
    int n = idx & 255;
    float v = W1[idx];
    __nv_bfloat16 hi = __float2bfloat16(v);
    __nv_bfloat16 lo = __float2bfloat16(v - __bfloat162float(hi));
    g_W1t_hi[(size_t)n * IN_DIM + k] = hi;
    g_W1t_lo[(size_t)n * IN_DIM + k] = lo;
}

__global__ void convert_W2_kernel(const float* __restrict__ W2) {
    int idx = blockIdx.x * blockDim.x + threadIdx.x;   // over 256*64
    if (idx >= HID_DIM * OUT_DIM) return;
    int k = idx >> 6;           // /OUT_DIM
    int n = idx & 63;
    float v = W2[idx];
    __nv_bfloat16 hi = __float2bfloat16(v);
    __nv_bfloat16 lo = __float2bfloat16(v - __bfloat162float(hi));
    g_W2t_hi[(size_t)n * HID_DIM + k] = hi;
    g_W2t_lo[(size_t)n * HID_DIM + k] = lo;
}

// ---------------- GEMM1: bf16 split-3 MMA, cp.async double-buffered ----------------
#define SP 40   // smem row stride (bf16 elems), conflict-free for ldmatrix
#define ARR_BYTES (128 * SP * 2)          // one 128-row tile array
#define OFF_AHI 0
#define OFF_ALO (ARR_BYTES)
#define OFF_BHI (2 * ARR_BYTES)
#define OFF_BLO (3 * ARR_BYTES)
#define STAGE_BYTES (4 * ARR_BYTES)       // 40960
#define G1_SMEM (2 * STAGE_BYTES)         // 81920

extern __shared__ __align__(16) char dynsmem[];

__global__ __launch_bounds__(256, 1) void mma_gemm1_kernel(
    const __nv_bfloat16* __restrict__ Ahi, const __nv_bfloat16* __restrict__ Alo,
    const __nv_bfloat16* __restrict__ Bhi, const __nv_bfloat16* __restrict__ Blo,  // [N][K]
    const float* __restrict__ bias,
    __nv_bfloat16* __restrict__ Hhi, __nv_bfloat16* __restrict__ Hlo, int M) {
    const int tid = threadIdx.x;
    const int lane = tid & 31;
    const int warp = tid >> 5;
    const int warpM = warp >> 1;        // 0..3 -> 32 rows each
    const int warpN = warp & 1;         // 0..1 -> 64 cols each
    const int aBase = blockIdx.y * 128;
    const int bBase = blockIdx.x * 128;

    float acc[2][8][4] = {};

    const unsigned uBase = (unsigned)__cvta_generic_to_shared(dynsmem);

    const int aoff0 = ((warpM * 32 + (lane & 15)) * SP + (lane >> 4) * 8) * 2;
    const int aoff1 = aoff0 + 16 * SP * 2;
    const int g = lane >> 3, r = lane & 7;
    const int boff = ((warpN * 64 + r + ((g & 2) ? 8 : 0)) * SP + ((g & 1) ? 8 : 0)) * 2;

    const int row = tid >> 2, seg = tid & 3;
    const int soA = (row * SP + seg * 8) * 2;
    const bool vA0 = (aBase + row) < M;
    const bool vA1 = (aBase + row + 64) < M;
    const size_t gA0 = (size_t)(vA0 ? aBase + row : 0) * IN_DIM + seg * 8;
    const size_t gA1 = (size_t)(vA1 ? aBase + row + 64 : 0) * IN_DIM + seg * 8;
    const size_t gB0 = (size_t)(bBase + row) * IN_DIM + seg * 8;
    const size_t gB1 = (size_t)(bBase + row + 64) * IN_DIM + seg * 8;
    const int soHi = soA + 64 * SP * 2;

    // issue loads for one K-stage into buffer `buf`
    auto issue_stage = [&](int ks, int buf) {
        unsigned sb = uBase + buf * STAGE_BYTES;
        int ko = ks * 32;
        cpa16(sb + OFF_AHI + soA,  Ahi + gA0 + ko, vA0);
        cpa16(sb + OFF_AHI + soHi, Ahi + gA1 + ko, vA1);
        cpa16(sb + OFF_ALO + soA,  Alo + gA0 + ko, vA0);
        cpa16(sb + OFF_ALO + soHi, Alo + gA1 + ko, vA1);
        cpa16(sb + OFF_BHI + soA,  Bhi + gB0 + ko, true);
        cpa16(sb + OFF_BHI + soHi, Bhi + gB1 + ko, true);
        cpa16(sb + OFF_BLO + soA,  Blo + gB0 + ko, true);
        cpa16(sb + OFF_BLO + soHi, Blo + gB1 + ko, true);
    };

    issue_stage(0, 0);
    cpa_commit();

    const int NSTAGE = IN_DIM / 32;   // 16
    for (int ks = 0; ks < NSTAGE; ks++) {
        int buf = ks & 1;
        if (ks + 1 < NSTAGE) {
            issue_stage(ks + 1, buf ^ 1);
            cpa_commit();
            asm volatile("cp.async.wait_group 1;");
        } else {
            asm volatile("cp.async.wait_group 0;");
        }
        __syncthreads();

        unsigned sb = uBase + buf * STAGE_BYTES;
        #pragma unroll
        for (int kk = 0; kk < 32; kk += 16) {
            unsigned ahi[2][4], alo[2][4], bhi[8][2], blo[8][2];
            ldsm4(ahi[0][0], ahi[0][1], ahi[0][2], ahi[0][3], sb + OFF_AHI + aoff0 + kk * 2);
            ldsm4(ahi[1][0], ahi[1][1], ahi[1][2], ahi[1][3], sb + OFF_AHI + aoff1 + kk * 2);
            ldsm4(alo[0][0], alo[0][1], alo[0][2], alo[0][3], sb + OFF_ALO + aoff0 + kk * 2);
            ldsm4(alo[1][0], alo[1][1], alo[1][2], alo[1][3], sb + OFF_ALO + aoff1 + kk * 2);
            #pragma unroll
            for (int n2 = 0; n2 < 4; n2++) {
                int off = boff + n2 * 16 * SP * 2 + kk * 2;
                ldsm4(bhi[2 * n2][0], bhi[2 * n2][1], bhi[2 * n2 + 1][0], bhi[2 * n2 + 1][1],
                      sb + OFF_BHI + off);
                ldsm4(blo[2 * n2][0], blo[2 * n2][1], blo[2 * n2 + 1][0], blo[2 * n2 + 1][1],
                      sb + OFF_BLO + off);
            }
            #pragma unroll
            for (int mi = 0; mi < 2; mi++)
                #pragma unroll
                for (int ni = 0; ni < 8; ni++) {
                    mma_bf16(acc[mi][ni], ahi[mi], bhi[ni]);   // hi*hi
                    mma_bf16(acc[mi][ni], ahi[mi], blo[ni]);   // hi*lo
                    mma_bf16(acc[mi][ni], alo[mi], bhi[ni]);   // lo*hi
                }
        }
        __syncthreads();
    }

    // epilogue: bias + relu, split to bf16 hi/lo for GEMM2
    #pragma unroll
    for (int mi = 0; mi < 2; mi++) {
        #pragma unroll
        for (int ni = 0; ni < 8; ni++) {
            int gn = bBase + warpN * 64 + ni * 8 + (lane & 3) * 2;
            float2 bs = *reinterpret_cast<const float2*>(&bias[gn]);
            int gm0 = aBase + warpM * 32 + mi * 16 + (lane >> 2);
            int gm1 = gm0 + 8;
            #pragma unroll
            for (int half = 0; half < 2; half++) {
                int gm = half ? gm1 : gm0;
                if (gm >= M) continue;
                float vx = fmaxf(acc[mi][ni][half * 2 + 0] + bs.x, 0.f);
                float vy = fmaxf(acc[mi][ni][half * 2 + 1] + bs.y, 0.f);
                __nv_bfloat16 hx = __float2bfloat16(vx);
                __nv_bfloat16 hy = __float2bfloat16(vy);
                __nv_bfloat16 lx = __float2bfloat16(vx - __bfloat162float(hx));
                __nv_bfloat16 ly = __float2bfloat16(vy - __bfloat162float(hy));
                size_t o = (size_t)gm * HID_DIM + gn;
                *reinterpret_cast<__nv_bfloat162*>(&Hhi[o]) = __nv_bfloat162(hx, hy);
                *reinterpret_cast<__nv_bfloat162*>(&Hlo[o]) = __nv_bfloat162(lx, ly);
            }
        }
    }
}

// ---------------- GEMM2: bf16 split-3 MMA, 128x64 block, K=256 ----------------
__global__ __launch_bounds__(256, 1) void mma_gemm2_kernel(
    const __nv_bfloat16* __restrict__ Ahi, const __nv_bfloat16* __restrict__ Alo,  // [M][256]
    const __nv_bfloat16* __restrict__ Bhi, const __nv_bfloat16* __restrict__ Blo,  // [64][256]
    const float* __restrict__ bias, float* __restrict__ C, int M) {
    __shared__ __align__(16) __nv_bfloat16 sAhi[128 * SP];
    __shared__ __align__(16) __nv_bfloat16 sAlo[128 * SP];
    __shared__ __align__(16) __nv_bfloat16 sBhi[64 * SP];
    __shared__ __align__(16) __nv_bfloat16 sBlo[64 * SP];

    const int tid = threadIdx.x;
    const int lane = tid & 31;
    const int warp = tid >> 5;          // 0..7, each 16 rows x 64 cols
    const int aBase = blockIdx.y * 128;

    float acc[8][4] = {};

    const unsigned uAhi = (unsigned)__cvta_generic_to_shared(sAhi);
    const unsigned uAlo = (unsigned)__cvta_generic_to_shared(sAlo);
    const unsigned uBhi = (unsigned)__cvta_generic_to_shared(sBhi);
    const unsigned uBlo = (unsigned)__cvta_generic_to_shared(sBlo);

    const int aoff = ((warp * 16 + (lane & 15)) * SP + (lane >> 4) * 8) * 2;
    const int g = lane >> 3, r = lane & 7;
    const int boff = ((r + ((g & 2) ? 8 : 0)) * SP + ((g & 1) ? 8 : 0)) * 2;

    for (int k0 = 0; k0 < HID_DIM; k0 += 32) {
        // A: 128x32 bf16 = 512 uint4 per array; 2 per thread
        #pragma unroll
        for (int i = 0; i < 2; i++) {
            int f = tid + i * 256;
            int row = f >> 2, seg = f & 3;
            int gm = aBase + row;
            uint4 vh = make_uint4(0, 0, 0, 0), vl = make_uint4(0, 0, 0, 0);
            if (gm < M) {
                size_t go = (size_t)gm * HID_DIM + k0 + seg * 8;
                vh = *reinterpret_cast<const uint4*>(&Ahi[go]);
                vl = *reinterpret_cast<const uint4*>(&Alo[go]);
            }
            int so = row * SP + seg * 8;
            *reinterpret_cast<uint4*>(&sAhi[so]) = vh;
            *reinterpret_cast<uint4*>(&sAlo[so]) = vl;
        }
        // B: 64x32 bf16 = 256 uint4 per array; 1 per thread
        {
            int row = tid >> 2, seg = tid & 3;
            size_t go = (size_t)row * HID_DIM + k0 + seg * 8;
            int so = row * SP + seg * 8;
            *reinterpret_cast<uint4*>(&sBhi[so]) = *reinterpret_cast<const uint4*>(&Bhi[go]);
            *reinterpret_cast<uint4*>(&sBlo[so]) = *reinterpret_cast<const uint4*>(&Blo[go]);
        }
        __syncthreads();

        #pragma unroll
        for (int kk = 0; kk < 32; kk += 16) {
            unsigned ahi[4], alo[4], bhi[8][2], blo[8][2];
            ldsm4(ahi[0], ahi[1], ahi[2], ahi[3], uAhi + aoff + kk * 2);
            ldsm4(alo[0], alo[1], alo[2], alo[3], uAlo + aoff + kk * 2);
            #pragma unroll
            for (int n2 = 0; n2 < 4; n2++) {
                int off = boff + n2 * 16 * SP * 2 + kk * 2;
                ldsm4(bhi[2 * n2][0], bhi[2 * n2][1], bhi[2 * n2 + 1][0], bhi[2 * n2 + 1][1],
                      uBhi + off);
                ldsm4(blo[2 * n2][0], blo[2 * n2][1], blo[2 * n2 + 1][0], blo[2 * n2 + 1][1],
                      uBlo + off);
            }
            #pragma unroll
            for (int ni = 0; ni < 8; ni++) {
                mma_bf16(acc[ni], ahi, bhi[ni]);
                mma_bf16(acc[ni], ahi, blo[ni]);
                mma_bf16(acc[ni], alo, bhi[ni]);
            }
        }
        __syncthreads();
    }

    #pragma unroll
    for (int ni = 0; ni < 8; ni++) {
        int gn = ni * 8 + (lane & 3) * 2;
        float2 bs = *reinterpret_cast<const float2*>(&bias[gn]);
        int gm0 = aBase + warp * 16 + (lane >> 2);
        int gm1 = gm0 + 8;
        if (gm0 < M) {
            float2 v = make_float2(acc[ni][0] + bs.x, acc[ni][1] + bs.y);
            *reinterpret_cast<float2*>(&C[(size_t)gm0 * OUT_DIM + gn]) = v;
        }
        if (gm1 < M) {
            float2 v = make_float2(acc[ni][2] + bs.x, acc[ni][3] + bs.y);
            *reinterpret_cast<float2*>(&C[(size_t)gm1 * OUT_DIM + gn]) = v;
        }
    }
}

// ---------------- init ----------------
__global__ void init_zero_kernel() {
    int i = blockIdx.x * blockDim.x + threadIdx.x;
    if (i < NN) {
        g_deg_out[i] = 0;
        g_deg_in[i]  = 0;
        g_fill[i]    = 0;
    }
}

// ---------------- degrees ----------------
__global__ void degree_kernel(const int* __restrict__ src, const int* __restrict__ dst) {
    int e = blockIdx.x * blockDim.x + threadIdx.x;
    if (e < NE) {
        atomicAdd(&g_deg_out[src[e]], 1);
        atomicAdd(&g_deg_in [dst[e]], 1);
    }
}

__global__ void norm_kernel() {
    int i = blockIdx.x * blockDim.x + threadIdx.x;
    if (i < NN) {
        g_norm_src[i] = rsqrtf((float)max(g_deg_out[i], 1));
        g_norm_dst[i] = rsqrtf((float)max(g_deg_in [i], 1));
    }
}

// ---------------- exclusive scan of deg_in -> g_ptr (3 kernels) ----------------
__global__ void scan_block_kernel() {
    __shared__ int s[512];
    int tid = threadIdx.x;
    int i = blockIdx.x * 512 + tid;
    int v = (i < NN) ? g_deg_in[i] : 0;
    s[tid] = v;
    __syncthreads();
    #pragma unroll
    for (int off = 1; off < 512; off <<= 1) {
        int t = (tid >= off) ? s[tid - off] : 0;
        __syncthreads();
        s[tid] += t;
        __syncthreads();
    }
    if (i < NN) g_ptr[i] = s[tid] - v;
    if (tid == 511) g_bsum[blockIdx.x] = s[511];
}

__global__ void scan_bsum_kernel(int nb) {
    __shared__ int s[128];
    int tid = threadIdx.x;
    int v = (tid < nb) ? g_bsum[tid] : 0;
    s[tid] = v;
    __syncthreads();
    #pragma unroll
    for (int off = 1; off < 128; off <<= 1) {
        int t = (tid >= off) ? s[tid - off] : 0;
        __syncthreads();
        s[tid] += t;
        __syncthreads();
    }
    if (tid < nb) g_bsum[tid] = s[tid] - v;
}

__global__ void scan_add_kernel() {
    int i = blockIdx.x * blockDim.x + threadIdx.x;
    if (i < NN)       g_ptr[i] += g_bsum[i >> 9];
    else if (i == NN) g_ptr[NN] = NE;
}

// ---------------- CSR fill (dst-sorted edge list) ----------------
__global__ void csr_fill_kernel(const int* __restrict__ src, const int* __restrict__ dst) {
    int e = blockIdx.x * blockDim.x + threadIdx.x;
    if (e < NE) {
        int d = dst[e];
        int pos = g_ptr[d] + atomicAdd(&g_fill[d], 1);
        g_csr_src[pos] = src[e];
        g_csr_eid[pos] = e;
    }
}

// ---------------- propagation hop: warp per dst node, CSR gather ----------------
__global__ void prop_kernel(const float* __restrict__ fin, float* __restrict__ fout) {
    int wid  = (blockIdx.x * blockDim.x + threadIdx.x) >> 5;
    int lane = threadIdx.x & 31;
    if (wid >= NN) return;

    int beg = g_ptr[wid], end = g_ptr[wid + 1];
    float acc0 = 0.f, acc1 = 0.f;

    int j = beg;
    for (; j + 4 <= end; j += 4) {
        int s0 = g_csr_src[j + 0], s1 = g_csr_src[j + 1];
        int s2 = g_csr_src[j + 2], s3 = g_csr_src[j + 3];
        float w0 = g_norm_src[s0], w1 = g_norm_src[s1];
        float w2 = g_norm_src[s2], w3 = g_norm_src[s3];
        const float* p0 = &fin[(size_t)s0 * OUT_DIM];
        const float* p1 = &fin[(size_t)s1 * OUT_DIM];
        const float* p2 = &fin[(size_t)s2 * OUT_DIM];
        const float* p3 = &fin[(size_t)s3 * OUT_DIM];
        acc0 += w0 * p0[lane]      + w1 * p1[lane]      + w2 * p2[lane]      + w3 * p3[lane];
        acc1 += w0 * p0[lane + 32] + w1 * p1[lane + 32] + w2 * p2[lane + 32] + w3 * p3[lane + 32];
    }
    for (; j < end; ++j) {
        int s = g_csr_src[j];
        float w = g_norm_src[s];
        const float* p = &fin[(size_t)s * OUT_DIM];
        acc0 += w * p[lane];
        acc1 += w * p[lane + 32];
    }

    float nd = g_norm_dst[wid];
    size_t o = (size_t)wid * OUT_DIM;
    fout[o + lane]      = (1.0f - ALPHA) * nd * acc0 + ALPHA * g_feat0[o + lane];
    fout[o + 32 + lane] = (1.0f - ALPHA) * nd * acc1 + ALPHA * g_feat0[o + 32 + lane];
}

// ---------------- final hop fused with sd + log_softmax ----------------
__global__ void prop_final_kernel(const float* __restrict__ w_src,
                                  const float* __restrict__ w_dst,
                                  float* __restrict__ out) {
    const float* __restrict__ fin = g_featB;

    int wid  = (blockIdx.x * blockDim.x + threadIdx.x) >> 5;
    int lane = threadIdx.x & 31;
    if (wid >= NN) return;

    int beg = g_ptr[wid], end = g_ptr[wid + 1];
    float acc0 = 0.f, acc1 = 0.f;

    int j = beg;
    for (; j + 4 <= end; j += 4) {
        int s0 = g_csr_src[j + 0], s1 = g_csr_src[j + 1];
        int s2 = g_csr_src[j + 2], s3 = g_csr_src[j + 3];
        float w0 = g_norm_src[s0], w1 = g_norm_src[s1];
        float w2 = g_norm_src[s2], w3 = g_norm_src[s3];
        const float* p0 = &fin[(size_t)s0 * OUT_DIM];
        const float* p1 = &fin[(size_t)s1 * OUT_DIM];
        const float* p2 = &fin[(size_t)s2 * OUT_DIM];
        const float* p3 = &fin[(size_t)s3 * OUT_DIM];
        acc0 += w0 * p0[lane]      + w1 * p1[lane]      + w2 * p2[lane]      + w3 * p3[lane];
        acc1 += w0 * p0[lane + 32] + w1 * p1[lane + 32] + w2 * p2[lane + 32] + w3 * p3[lane + 32];
    }
    for (; j < end; ++j) {
        int s = g_csr_src[j];
        float w = g_norm_src[s];
        const float* p = &fin[(size_t)s * OUT_DIM];
        acc0 += w * p[lane];
        acc1 += w * p[lane + 32];
    }

    float nd = g_norm_dst[wid];
    size_t o = (size_t)wid * OUT_DIM;
    float f0 = (1.0f - ALPHA) * nd * acc0 + ALPHA * g_feat0[o + lane];
    float f1 = (1.0f - ALPHA) * nd * acc1 + ALPHA * g_feat0[o + 32 + lane];

    // attention dot products
    float s = f0 * w_src[lane] + f1 * w_src[lane + 32];
    float d = f0 * w_dst[lane] + f1 * w_dst[lane + 32];
    #pragma unroll
    for (int off = 16; off; off >>= 1) {
        s += __shfl_xor_sync(0xFFFFFFFFu, s, off);
        d += __shfl_xor_sync(0xFFFFFFFFu, d, off);
    }
    if (lane == 0) { g_s[wid] = s; g_d[wid] = d; }

    // log_softmax over the 64 features
    float m = fmaxf(f0, f1);
    #pragma unroll
    for (int off = 16; off; off >>= 1)
        m = fmaxf(m, __shfl_xor_sync(0xFFFFFFFFu, m, off));
    float sum = __expf(f0 - m) + __expf(f1 - m);
    #pragma unroll
    for (int off = 16; off; off >>= 1)
        sum += __shfl_xor_sync(0xFFFFFFFFu, sum, off);
    float ls = m + logf(sum);
    out[o + lane]      = f0 - ls;
    out[o + 32 + lane] = f1 - ls;
}

// ---------------- edge-softmax per dst node ----------------
__global__ void attn_kernel(float* __restrict__ attn_out) {
    int wid  = (blockIdx.x * blockDim.x + threadIdx.x) >> 5;
    int lane = threadIdx.x & 31;
    if (wid >= NN) return;
    int beg = g_ptr[wid], end = g_ptr[wid + 1];
    if (beg == end) return;
    float dn = g_d[wid];

    float m = -2.0f;  // tanh >= -1
    for (int j = beg + lane; j < end; j += 32) {
        float e = tanhf(g_s[g_csr_src[j]] + dn);
        g_e[j] = e;
        m = fmaxf(m, e);
    }
    #pragma unroll
    for (int off = 16; off; off >>= 1)
        m = fmaxf(m, __shfl_xor_sync(0xFFFFFFFFu, m, off));

    float sum = 0.f;
    for (int j = beg + lane; j < end; j += 32)
        sum += __expf(g_e[j] - m);
    #pragma unroll
    for (int off = 16; off; off >>= 1)
        sum += __shfl_xor_sync(0xFFFFFFFFu, sum, off);

    float inv = 1.0f / sum;
    for (int j = beg + lane; j < end; j += 32)
        attn_out[g_csr_eid[j]] = __expf(g_e[j] - m) * inv;
}

// ---------------- launch (single stream, capture-safe) ----------------
extern "C" void kernel_launch(void* const* d_in, const int* in_sizes, int n_in,
                              void* d_out, int out_size) {
    const float* h     = (const float*)d_in[0];
    const int*   src   = (const int*)  d_in[1];
    const int*   dst   = (const int*)  d_in[2];
    const float* W1    = (const float*)d_in[3];
    const float* b1    = (const float*)d_in[4];
    const float* W2    = (const float*)d_in[5];
    const float* b2    = (const float*)d_in[6];
    const float* w_src = (const float*)d_in[7];
    const float* w_dst = (const float*)d_in[8];
    float* out = (float*)d_out;

    float *p_feat0, *p_featA, *p_featB;
    cudaGetSymbolAddress((void**)&p_feat0, g_feat0);
    cudaGetSymbolAddress((void**)&p_featA, g_featA);
    cudaGetSymbolAddress((void**)&p_featB, g_featB);
    __nv_bfloat16 *p_hhi, *p_hlo, *p_w1hi, *p_w1lo, *p_hidhi, *p_hidlo, *p_w2hi, *p_w2lo;
    cudaGetSymbolAddress((void**)&p_hhi,   g_h_hi);
    cudaGetSymbolAddress((void**)&p_hlo,   g_h_lo);
    cudaGetSymbolAddress((void**)&p_w1hi,  g_W1t_hi);
    cudaGetSymbolAddress((void**)&p_w1lo,  g_W1t_lo);
    cudaGetSymbolAddress((void**)&p_hidhi, g_hid_hi);
    cudaGetSymbolAddress((void**)&p_hidlo, g_hid_lo);
    cudaGetSymbolAddress((void**)&p_w2hi,  g_W2t_hi);
    cudaGetSymbolAddress((void**)&p_w2lo,  g_W2t_lo);

    static bool attrSet = false;
    if (!attrSet) {
        cudaFuncSetAttribute(mma_gemm1_kernel,
                             cudaFuncAttributeMaxDynamicSharedMemorySize, G1_SMEM);
        attrSet = true;
    }

    const int nodeBlocks = (NN + 255) / 256;
    const int edgeBlocks = (NE + 255) / 256;
    const int warpNodeBlocks = (NN + 7) / 8;
    const int nbScan = (NN + 511) / 512;      // 98

    // graph prep
    init_zero_kernel<<<nodeBlocks, 256>>>();
    degree_kernel<<<edgeBlocks, 256>>>(src, dst);
    norm_kernel<<<nodeBlocks, 256>>>();
    scan_block_kernel<<<nbScan, 512>>>();
    scan_bsum_kernel<<<1, 128>>>(nbScan);
    scan_add_kernel<<<(NN + 1 + 255) / 256, 256>>>();
    csr_fill_kernel<<<edgeBlocks, 256>>>(src, dst);

    // conversions + GEMMs
    convert_h_kernel<<<((NN * (size_t)IN_DIM / 4) + 255) / 256, 256>>>(h);
    convert_W1_kernel<<<(IN_DIM * HID_DIM + 255) / 256, 256>>>(W1);
    convert_W2_kernel<<<(HID_DIM * OUT_DIM + 255) / 256, 256>>>(W2);
    {
        dim3 grid(HID_DIM / 128, (NN + 127) / 128);
        mma_gemm1_kernel<<<grid, 256, G1_SMEM>>>(
            p_hhi, p_hlo, p_w1hi, p_w1lo, b1, p_hidhi, p_hidlo, NN);
    }
    {
        dim3 grid(1, (NN + 127) / 128);
        mma_gemm2_kernel<<<grid, 256>>>(
            p_hidhi, p_hidlo, p_w2hi, p_w2lo, b2, p_feat0, NN);
    }

    // 4 hops: feat0 -> B -> A -> B -> (fused: sd + log_softmax, writes out)
    prop_kernel<<<warpNodeBlocks, 256>>>(p_feat0, p_featB);
    prop_kernel<<<warpNodeBlocks, 256>>>(p_featB, p_featA);
    prop_kernel<<<warpNodeBlocks, 256>>>(p_featA, p_featB);
    prop_final_kernel<<<warpNodeBlocks, 256>>>(w_src, w_dst, out);

    attn_kernel<<<warpNodeBlocks, 256>>>(out + (size_t)NN * OUT_DIM);
}

// round 12
// speedup vs baseline: 1.5495x; 1.0493x over previous
#include <cuda_runtime.h>
#include <cuda_bf16.h>
#include <math.h>

#define NN      50000
#define NE      1600000
#define IN_DIM  512
#define HID_DIM 256
#define OUT_DIM 64
#define ALPHA   0.1f

// ---------------- static device scratch (no allocations allowed) ----------------
__device__ float g_feat0 [(size_t)NN * OUT_DIM];
__device__ float g_featA [(size_t)NN * OUT_DIM];
__device__ float g_featB [(size_t)NN * OUT_DIM];
__device__ int   g_deg_out[NN];
__device__ int   g_deg_in [NN];
__device__ float g_norm_src[NN];
__device__ float g_norm_dst[NN];
__device__ int   g_ptr [NN + 1];
__device__ int   g_fill[NN];
__device__ int   g_bsum[256];
__device__ int   g_csr_src[NE];
__device__ int   g_csr_eid[NE];
__device__ float g_s[NN];
__device__ float g_d[NN];
__device__ float g_e[NE];

// bf16 split operands (W1 transposed, hidden, W2 transposed)
__device__ __nv_bfloat16 g_W1t_hi[(size_t)HID_DIM * IN_DIM];  // [N][K]
__device__ __nv_bfloat16 g_W1t_lo[(size_t)HID_DIM * IN_DIM];
__device__ __nv_bfloat16 g_hid_hi[(size_t)NN * HID_DIM];
__device__ __nv_bfloat16 g_hid_lo[(size_t)NN * HID_DIM];
__device__ __nv_bfloat16 g_W2t_hi[(size_t)OUT_DIM * HID_DIM]; // [N][K]
__device__ __nv_bfloat16 g_W2t_lo[(size_t)OUT_DIM * HID_DIM];

// ---------------- mma.sync helpers ----------------
__device__ __forceinline__ void ldsm4(unsigned& r0, unsigned& r1, unsigned& r2, unsigned& r3,
                                      unsigned addr) {
    asm volatile("ldmatrix.sync.aligned.m8n8.x4.shared.b16 {%0,%1,%2,%3}, [%4];"
                 : "=r"(r0), "=r"(r1), "=r"(r2), "=r"(r3) : "r"(addr));
}
__device__ __forceinline__ void mma_bf16(float* c, const unsigned* a, const unsigned* b) {
    asm volatile("mma.sync.aligned.m16n8k16.row.col.f32.bf16.bf16.f32 "
                 "{%0,%1,%2,%3}, {%4,%5,%6,%7}, {%8,%9}, {%0,%1,%2,%3};"
                 : "+f"(c[0]), "+f"(c[1]), "+f"(c[2]), "+f"(c[3])
                 : "r"(a[0]), "r"(a[1]), "r"(a[2]), "r"(a[3]), "r"(b[0]), "r"(b[1]));
}

// split one float into bf16 hi + lo
__device__ __forceinline__ void bsplit(float v, __nv_bfloat16& hi, __nv_bfloat16& lo) {
    hi = __float2bfloat16(v);
    lo = __float2bfloat16(v - __bfloat162float(hi));
}

// ---------------- weight conversion pre-passes ----------------
__global__ void convert_W1_kernel(const float* __restrict__ W1) {
    int idx = blockIdx.x * blockDim.x + threadIdx.x;   // over 512*256
    if (idx >= IN_DIM * HID_DIM) return;
    int k = idx >> 8;
    int n = idx & 255;
    __nv_bfloat16 hi, lo;
    bsplit(W1[idx], hi, lo);
    g_W1t_hi[(size_t)n * IN_DIM + k] = hi;
    g_W1t_lo[(size_t)n * IN_DIM + k] = lo;
}

__global__ void convert_W2_kernel(const float* __restrict__ W2) {
    int idx = blockIdx.x * blockDim.x + threadIdx.x;   // over 256*64
    if (idx >= HID_DIM * OUT_DIM) return;
    int k = idx >> 6;
    int n = idx & 63;
    __nv_bfloat16 hi, lo;
    bsplit(W2[idx], hi, lo);
    g_W2t_hi[(size_t)n * HID_DIM + k] = hi;
    g_W2t_lo[(size_t)n * HID_DIM + k] = lo;
}

// ---------------- GEMM1: bf16 split-3 MMA with fused fp32->bf16 A conversion --
// A loaded as fp32 from h and split in-register (convert_h pass eliminated);
// reg-staged LDG double buffering hides DRAM latency under the HMMA pipe.
#define SP 40                              // smem row stride (bf16), ldmatrix conflict-free
#define ARR_BYTES (128 * SP * 2)           // 10240 per tile array
#define OFF_AHI 0
#define OFF_ALO (ARR_BYTES)
#define OFF_BHI (2 * ARR_BYTES)
#define OFF_BLO (3 * ARR_BYTES)
#define STAGE_BYTES (4 * ARR_BYTES)        // 40960
#define G1_SMEM (2 * STAGE_BYTES)          // 81920

extern __shared__ __align__(16) char dynsmem[];

__global__ __launch_bounds__(256, 1) void mma_gemm1_kernel(
    const float* __restrict__ A,                                               // h [M][512] fp32
    const __nv_bfloat16* __restrict__ Bhi, const __nv_bfloat16* __restrict__ Blo,  // [N][K]
    const float* __restrict__ bias,
    __nv_bfloat16* __restrict__ Hhi, __nv_bfloat16* __restrict__ Hlo, int M) {
    const int tid = threadIdx.x;
    const int lane = tid & 31;
    const int warp = tid >> 5;
    const int warpM = warp >> 1;        // 0..3 -> 32 rows each
    const int warpN = warp & 1;         // 0..1 -> 64 cols each
    const int aBase = blockIdx.y * 128;
    const int bBase = blockIdx.x * 128;

    float acc[2][8][4] = {};

    const unsigned uBase = (unsigned)__cvta_generic_to_shared(dynsmem);

    // ldmatrix per-lane offsets (proven layout from prior rounds)
    const int aoff0 = ((warpM * 32 + (lane & 15)) * SP + (lane >> 4) * 8) * 2;
    const int aoff1 = aoff0 + 16 * SP * 2;
    const int g = lane >> 3, r = lane & 7;
    const int boff = ((warpN * 64 + r + ((g & 2) ? 8 : 0)) * SP + ((g & 1) ? 8 : 0)) * 2;

    // loader mapping: thread -> (row, 16-col half)
    const int lrow  = tid >> 1;          // 0..127
    const int lhalf = (tid & 1) * 16;    // col offset 0 or 16
    const bool vA = (aBase + lrow) < M;
    const float* aRow = A + (size_t)(vA ? aBase + lrow : 0) * IN_DIM + lhalf;
    const __nv_bfloat16* bRowHi = Bhi + (size_t)(bBase + lrow) * IN_DIM + lhalf;
    const __nv_bfloat16* bRowLo = Blo + (size_t)(bBase + lrow) * IN_DIM + lhalf;
    const int soff = (lrow * SP + lhalf) * 2;   // byte offset in each tile array

    float4 a4[4];
    uint4  b4h[2], b4l[2];

    auto ldg_stage = [&](int ks) {
        int k0 = ks * 32;
        if (vA) {
            #pragma unroll
            for (int i = 0; i < 4; i++)
                a4[i] = *reinterpret_cast<const float4*>(aRow + k0 + i * 4);
        } else {
            #pragma unroll
            for (int i = 0; i < 4; i++) a4[i] = make_float4(0.f, 0.f, 0.f, 0.f);
        }
        b4h[0] = *reinterpret_cast<const uint4*>(bRowHi + k0);
        b4h[1] = *reinterpret_cast<const uint4*>(bRowHi + k0 + 8);
        b4l[0] = *reinterpret_cast<const uint4*>(bRowLo + k0);
        b4l[1] = *reinterpret_cast<const uint4*>(bRowLo + k0 + 8);
    };

    auto sts_stage = [&](int buf) {
        char* sb = dynsmem + buf * STAGE_BYTES;
        // convert A fp32 -> bf16 hi/lo, pack 16 values into 2 uint4 each
        unsigned hp[8], lp[8];
        #pragma unroll
        for (int i = 0; i < 4; i++) {
            __nv_bfloat16 hx, hy, hz, hw, lx, ly, lz, lw;
            bsplit(a4[i].x, hx, lx); bsplit(a4[i].y, hy, ly);
            bsplit(a4[i].z, hz, lz); bsplit(a4[i].w, hw, lw);
            __nv_bfloat162 h0(hx, hy), h1(hz, hw), l0(lx, ly), l1(lz, lw);
            hp[i * 2]     = *reinterpret_cast<unsigned*>(&h0);
            hp[i * 2 + 1] = *reinterpret_cast<unsigned*>(&h1);
            lp[i * 2]     = *reinterpret_cast<unsigned*>(&l0);
            lp[i * 2 + 1] = *reinterpret_cast<unsigned*>(&l1);
        }
        *reinterpret_cast<uint4*>(sb + OFF_AHI + soff)      = make_uint4(hp[0], hp[1], hp[2], hp[3]);
        *reinterpret_cast<uint4*>(sb + OFF_AHI + soff + 16) = make_uint4(hp[4], hp[5], hp[6], hp[7]);
        *reinterpret_cast<uint4*>(sb + OFF_ALO + soff)      = make_uint4(lp[0], lp[1], lp[2], lp[3]);
        *reinterpret_cast<uint4*>(sb + OFF_ALO + soff + 16) = make_uint4(lp[4], lp[5], lp[6], lp[7]);
        *reinterpret_cast<uint4*>(sb + OFF_BHI + soff)      = b4h[0];
        *reinterpret_cast<uint4*>(sb + OFF_BHI + soff + 16) = b4h[1];
        *reinterpret_cast<uint4*>(sb + OFF_BLO + soff)      = b4l[0];
        *reinterpret_cast<uint4*>(sb + OFF_BLO + soff + 16) = b4l[1];
    };

    // prologue: stage 0
    ldg_stage(0);
    sts_stage(0);
    __syncthreads();

    const int NSTAGE = IN_DIM / 32;   // 16
    for (int ks = 0; ks < NSTAGE; ks++) {
        int buf = ks & 1;
        if (ks + 1 < NSTAGE) ldg_stage(ks + 1);   // LDGs fly during compute

        unsigned sb = uBase + buf * STAGE_BYTES;
        #pragma unroll
        for (int kk = 0; kk < 32; kk += 16) {
            unsigned ahi[2][4], alo[2][4], bhi[8][2], blo[8][2];
            ldsm4(ahi[0][0], ahi[0][1], ahi[0][2], ahi[0][3], sb + OFF_AHI + aoff0 + kk * 2);
            ldsm4(ahi[1][0], ahi[1][1], ahi[1][2], ahi[1][3], sb + OFF_AHI + aoff1 + kk * 2);
            ldsm4(alo[0][0], alo[0][1], alo[0][2], alo[0][3], sb + OFF_ALO + aoff0 + kk * 2);
            ldsm4(alo[1][0], alo[1][1], alo[1][2], alo[1][3], sb + OFF_ALO + aoff1 + kk * 2);
            #pragma unroll
            for (int n2 = 0; n2 < 4; n2++) {
                int off = boff + n2 * 16 * SP * 2 + kk * 2;
                ldsm4(bhi[2 * n2][0], bhi[2 * n2][1], bhi[2 * n2 + 1][0], bhi[2 * n2 + 1][1],
                      sb + OFF_BHI + off);
                ldsm4(blo[2 * n2][0], blo[2 * n2][1], blo[2 * n2 + 1][0], blo[2 * n2 + 1][1],
                      sb + OFF_BLO + off);
            }
            #pragma unroll
            for (int mi = 0; mi < 2; mi++)
                #pragma unroll
                for (int ni = 0; ni < 8; ni++) {
                    mma_bf16(acc[mi][ni], ahi[mi], bhi[ni]);   // hi*hi
                    mma_bf16(acc[mi][ni], ahi[mi], blo[ni]);   // hi*lo
                    mma_bf16(acc[mi][ni], alo[mi], bhi[ni]);   // lo*hi
                }
        }

        if (ks + 1 < NSTAGE) {
            // safe: all reads of buf^1 completed before the sync at end of ks-1
            sts_stage(buf ^ 1);
            __syncthreads();
        }
    }

    // epilogue: bias + relu, split to bf16 hi/lo for GEMM2
    #pragma unroll
    for (int mi = 0; mi < 2; mi++) {
        #pragma unroll
        for (int ni = 0; ni < 8; ni++) {
            int gn = bBase + warpN * 64 + ni * 8 + (lane & 3) * 2;
            float2 bs = *reinterpret_cast<const float2*>(&bias[gn]);
            int gm0 = aBase + warpM * 32 + mi * 16 + (lane >> 2);
            int gm1 = gm0 + 8;
            #pragma unroll
            for (int half = 0; half < 2; half++) {
                int gm = half ? gm1 : gm0;
                if (gm >= M) continue;
                float vx = fmaxf(acc[mi][ni][half * 2 + 0] + bs.x, 0.f);
                float vy = fmaxf(acc[mi][ni][half * 2 + 1] + bs.y, 0.f);
                __nv_bfloat16 hx, hy, lx, ly;
                bsplit(vx, hx, lx);
                bsplit(vy, hy, ly);
                size_t o = (size_t)gm * HID_DIM + gn;
                *reinterpret_cast<__nv_bfloat162*>(&Hhi[o]) = __nv_bfloat162(hx, hy);
                *reinterpret_cast<__nv_bfloat162*>(&Hlo[o]) = __nv_bfloat162(lx, ly);
            }
        }
    }
}

// ---------------- GEMM2: bf16 split-3 mma.sync, 128x64 block, K=256 ----------------
__global__ __launch_bounds__(256, 1) void mma_gemm2_kernel(
    const __nv_bfloat16* __restrict__ Ahi, const __nv_bfloat16* __restrict__ Alo,
    const __nv_bfloat16* __restrict__ Bhi, const __nv_bfloat16* __restrict__ Blo,
    const float* __restrict__ bias, float* __restrict__ C, int M) {
    __shared__ __align__(16) __nv_bfloat16 sAhi[128 * SP];
    __shared__ __align__(16) __nv_bfloat16 sAlo[128 * SP];
    __shared__ __align__(16) __nv_bfloat16 sBhi[64 * SP];
    __shared__ __align__(16) __nv_bfloat16 sBlo[64 * SP];

    const int tid = threadIdx.x;
    const int lane = tid & 31;
    const int warp = tid >> 5;          // 0..7, each 16 rows x 64 cols
    const int aBase = blockIdx.y * 128;

    float acc[8][4] = {};

    const unsigned uAhi = (unsigned)__cvta_generic_to_shared(sAhi);
    const unsigned uAlo = (unsigned)__cvta_generic_to_shared(sAlo);
    const unsigned uBhi = (unsigned)__cvta_generic_to_shared(sBhi);
    const unsigned uBlo = (unsigned)__cvta_generic_to_shared(sBlo);

    const int aoff = ((warp * 16 + (lane & 15)) * SP + (lane >> 4) * 8) * 2;
    const int g = lane >> 3, r = lane & 7;
    const int boff = ((r + ((g & 2) ? 8 : 0)) * SP + ((g & 1) ? 8 : 0)) * 2;

    for (int k0 = 0; k0 < HID_DIM; k0 += 32) {
        #pragma unroll
        for (int i = 0; i < 2; i++) {
            int f = tid + i * 256;
            int row = f >> 2, seg = f & 3;
            int gm = aBase + row;
            uint4 vh = make_uint4(0, 0, 0, 0), vl = make_uint4(0, 0, 0, 0);
            if (gm < M) {
                size_t go = (size_t)gm * HID_DIM + k0 + seg * 8;
                vh = *reinterpret_cast<const uint4*>(&Ahi[go]);
                vl = *reinterpret_cast<const uint4*>(&Alo[go]);
            }
            int so = row * SP + seg * 8;
            *reinterpret_cast<uint4*>(&sAhi[so]) = vh;
            *reinterpret_cast<uint4*>(&sAlo[so]) = vl;
        }
        {
            int row = tid >> 2, seg = tid & 3;
            size_t go = (size_t)row * HID_DIM + k0 + seg * 8;
            int so = row * SP + seg * 8;
            *reinterpret_cast<uint4*>(&sBhi[so]) = *reinterpret_cast<const uint4*>(&Bhi[go]);
            *reinterpret_cast<uint4*>(&sBlo[so]) = *reinterpret_cast<const uint4*>(&Blo[go]);
        }
        __syncthreads();

        #pragma unroll
        for (int kk = 0; kk < 32; kk += 16) {
            unsigned ahi[4], alo[4], bhi[8][2], blo[8][2];
            ldsm4(ahi[0], ahi[1], ahi[2], ahi[3], uAhi + aoff + kk * 2);
            ldsm4(alo[0], alo[1], alo[2], alo[3], uAlo + aoff + kk * 2);
            #pragma unroll
            for (int n2 = 0; n2 < 4; n2++) {
                int off = boff + n2 * 16 * SP * 2 + kk * 2;
                ldsm4(bhi[2 * n2][0], bhi[2 * n2][1], bhi[2 * n2 + 1][0], bhi[2 * n2 + 1][1],
                      uBhi + off);
                ldsm4(blo[2 * n2][0], blo[2 * n2][1], blo[2 * n2 + 1][0], blo[2 * n2 + 1][1],
                      uBlo + off);
            }
            #pragma unroll
            for (int ni = 0; ni < 8; ni++) {
                mma_bf16(acc[ni], ahi, bhi[ni]);
                mma_bf16(acc[ni], ahi, blo[ni]);
                mma_bf16(acc[ni], alo, bhi[ni]);
            }
        }
        __syncthreads();
    }

    #pragma unroll
    for (int ni = 0; ni < 8; ni++) {
        int gn = ni * 8 + (lane & 3) * 2;
        float2 bs = *reinterpret_cast<const float2*>(&bias[gn]);
        int gm0 = aBase + warp * 16 + (lane >> 2);
        int gm1 = gm0 + 8;
        if (gm0 < M) {
            float2 v = make_float2(acc[ni][0] + bs.x, acc[ni][1] + bs.y);
            *reinterpret_cast<float2*>(&C[(size_t)gm0 * OUT_DIM + gn]) = v;
        }
        if (gm1 < M) {
            float2 v = make_float2(acc[ni][2] + bs.x, acc[ni][3] + bs.y);
            *reinterpret_cast<float2*>(&C[(size_t)gm1 * OUT_DIM + gn]) = v;
        }
    }
}

// ---------------- graph prep ----------------
__global__ void init_zero_kernel() {
    int i = blockIdx.x * blockDim.x + threadIdx.x;
    if (i < NN) {
        g_deg_out[i] = 0;
        g_deg_in[i]  = 0;
        g_fill[i]    = 0;
    }
}

__global__ void degree_kernel(const int* __restrict__ src, const int* __restrict__ dst) {
    int e = blockIdx.x * blockDim.x + threadIdx.x;
    if (e < NE) {
        atomicAdd(&g_deg_out[src[e]], 1);
        atomicAdd(&g_deg_in [dst[e]], 1);
    }
}

__global__ void scan_block_kernel() {
    __shared__ int s[512];
    int tid = threadIdx.x;
    int i = blockIdx.x * 512 + tid;
    int v = (i < NN) ? g_deg_in[i] : 0;
    s[tid] = v;
    __syncthreads();
    #pragma unroll
    for (int off = 1; off < 512; off <<= 1) {
        int t = (tid >= off) ? s[tid - off] : 0;
        __syncthreads();
        s[tid] += t;
        __syncthreads();
    }
    if (i < NN) g_ptr[i] = s[tid] - v;
    if (tid == 511) g_bsum[blockIdx.x] = s[511];
}

__global__ void scan_bsum_kernel(int nb) {
    __shared__ int s[128];
    int tid = threadIdx.x;
    int v = (tid < nb) ? g_bsum[tid] : 0;
    s[tid] = v;
    __syncthreads();
    #pragma unroll
    for (int off = 1; off < 128; off <<= 1) {
        int t = (tid >= off) ? s[tid - off] : 0;
        __syncthreads();
        s[tid] += t;
        __syncthreads();
    }
    if (tid < nb) g_bsum[tid] = s[tid] - v;
}

// scan finalize + degree norms (fused)
__global__ void scan_add_kernel() {
    int i = blockIdx.x * blockDim.x + threadIdx.x;
    if (i < NN) {
        g_ptr[i] += g_bsum[i >> 9];
        g_norm_src[i] = rsqrtf((float)max(g_deg_out[i], 1));
        g_norm_dst[i] = rsqrtf((float)max(g_deg_in [i], 1));
    } else if (i == NN) {
        g_ptr[NN] = NE;
    }
}

__global__ void csr_fill_kernel(const int* __restrict__ src, const int* __restrict__ dst) {
    int e = blockIdx.x * blockDim.x + threadIdx.x;
    if (e < NE) {
        int d = dst[e];
        int pos = g_ptr[d] + atomicAdd(&g_fill[d], 1);
        g_csr_src[pos] = src[e];
        g_csr_eid[pos] = e;
    }
}

// ---------------- propagation hop: warp per dst node, CSR gather ----------------
__global__ void prop_kernel(const float* __restrict__ fin, float* __restrict__ fout) {
    int wid  = (blockIdx.x * blockDim.x + threadIdx.x) >> 5;
    int lane = threadIdx.x & 31;
    if (wid >= NN) return;

    int beg = g_ptr[wid], end = g_ptr[wid + 1];
    float acc0 = 0.f, acc1 = 0.f;

    int j = beg;
    for (; j + 4 <= end; j += 4) {
        int s0 = g_csr_src[j + 0], s1 = g_csr_src[j + 1];
        int s2 = g_csr_src[j + 2], s3 = g_csr_src[j + 3];
        float w0 = g_norm_src[s0], w1 = g_norm_src[s1];
        float w2 = g_norm_src[s2], w3 = g_norm_src[s3];
        const float* p0 = &fin[(size_t)s0 * OUT_DIM];
        const float* p1 = &fin[(size_t)s1 * OUT_DIM];
        const float* p2 = &fin[(size_t)s2 * OUT_DIM];
        const float* p3 = &fin[(size_t)s3 * OUT_DIM];
        acc0 += w0 * p0[lane]      + w1 * p1[lane]      + w2 * p2[lane]      + w3 * p3[lane];
        acc1 += w0 * p0[lane + 32] + w1 * p1[lane + 32] + w2 * p2[lane + 32] + w3 * p3[lane + 32];
    }
    for (; j < end; ++j) {
        int s = g_csr_src[j];
        float w = g_norm_src[s];
        const float* p = &fin[(size_t)s * OUT_DIM];
        acc0 += w * p[lane];
        acc1 += w * p[lane + 32];
    }

    float nd = g_norm_dst[wid];
    size_t o = (size_t)wid * OUT_DIM;
    fout[o + lane]      = (1.0f - ALPHA) * nd * acc0 + ALPHA * g_feat0[o + lane];
    fout[o + 32 + lane] = (1.0f - ALPHA) * nd * acc1 + ALPHA * g_feat0[o + 32 + lane];
}

// ---------------- final hop fused with sd + log_softmax ----------------
__global__ void prop_final_kernel(const float* __restrict__ w_src,
                                  const float* __restrict__ w_dst,
                                  float* __restrict__ out) {
    const float* __restrict__ fin = g_featB;

    int wid  = (blockIdx.x * blockDim.x + threadIdx.x) >> 5;
    int lane = threadIdx.x & 31;
    if (wid >= NN) return;

    int beg = g_ptr[wid], end = g_ptr[wid + 1];
    float acc0 = 0.f, acc1 = 0.f;

    int j = beg;
    for (; j + 4 <= end; j += 4) {
        int s0 = g_csr_src[j + 0], s1 = g_csr_src[j + 1];
        int s2 = g_csr_src[j + 2], s3 = g_csr_src[j + 3];
        float w0 = g_norm_src[s0], w1 = g_norm_src[s1];
        float w2 = g_norm_src[s2], w3 = g_norm_src[s3];
        const float* p0 = &fin[(size_t)s0 * OUT_DIM];
        const float* p1 = &fin[(size_t)s1 * OUT_DIM];
        const float* p2 = &fin[(size_t)s2 * OUT_DIM];
        const float* p3 = &fin[(size_t)s3 * OUT_DIM];
        acc0 += w0 * p0[lane]      + w1 * p1[lane]      + w2 * p2[lane]      + w3 * p3[lane];
        acc1 += w0 * p0[lane + 32] + w1 * p1[lane + 32] + w2 * p2[lane + 32] + w3 * p3[lane + 32];
    }
    for (; j < end; ++j) {
        int s = g_csr_src[j];
        float w = g_norm_src[s];
        const float* p = &fin[(size_t)s * OUT_DIM];
        acc0 += w * p[lane];
        acc1 += w * p[lane + 32];
    }

    float nd = g_norm_dst[wid];
    size_t o = (size_t)wid * OUT_DIM;
    float f0 = (1.0f - ALPHA) * nd * acc0 + ALPHA * g_feat0[o + lane];
    float f1 = (1.0f - ALPHA) * nd * acc1 + ALPHA * g_feat0[o + 32 + lane];

    // attention dot products
    float s = f0 * w_src[lane] + f1 * w_src[lane + 32];
    float d = f0 * w_dst[lane] + f1 * w_dst[lane + 32];
    #pragma unroll
    for (int off = 16; off; off >>= 1) {
        s += __shfl_xor_sync(0xFFFFFFFFu, s, off);
        d += __shfl_xor_sync(0xFFFFFFFFu, d, off);
    }
    if (lane == 0) { g_s[wid] = s; g_d[wid] = d; }

    // log_softmax over the 64 features
    float m = fmaxf(f0, f1);
    #pragma unroll
    for (int off = 16; off; off >>= 1)
        m = fmaxf(m, __shfl_xor_sync(0xFFFFFFFFu, m, off));
    float sum = __expf(f0 - m) + __expf(f1 - m);
    #pragma unroll
    for (int off = 16; off; off >>= 1)
        sum += __shfl_xor_sync(0xFFFFFFFFu, sum, off);
    float ls = m + logf(sum);
    out[o + lane]      = f0 - ls;
    out[o + 32 + lane] = f1 - ls;
}

// ---------------- edge-softmax per dst node (exp cached in g_e) ----------------
__global__ void attn_kernel(float* __restrict__ attn_out) {
    int wid  = (blockIdx.x * blockDim.x + threadIdx.x) >> 5;
    int lane = threadIdx.x & 31;
    if (wid >= NN) return;
    int beg = g_ptr[wid], end = g_ptr[wid + 1];
    if (beg == end) return;
    float dn = g_d[wid];

    float m = -2.0f;  // tanh >= -1
    for (int j = beg + lane; j < end; j += 32) {
        float e = tanhf(g_s[g_csr_src[j]] + dn);
        g_e[j] = e;
        m = fmaxf(m, e);
    }
    #pragma unroll
    for (int off = 16; off; off >>= 1)
        m = fmaxf(m, __shfl_xor_sync(0xFFFFFFFFu, m, off));

    float sum = 0.f;
    for (int j = beg + lane; j < end; j += 32) {
        float ex = __expf(g_e[j] - m);
        g_e[j] = ex;                    // cache exp for pass 3
        sum += ex;
    }
    #pragma unroll
    for (int off = 16; off; off >>= 1)
        sum += __shfl_xor_sync(0xFFFFFFFFu, sum, off);

    float inv = 1.0f / sum;
    for (int j = beg + lane; j < end; j += 32)
        attn_out[g_csr_eid[j]] = g_e[j] * inv;
}

// ---------------- launch (single stream, capture-safe) ----------------
extern "C" void kernel_launch(void* const* d_in, const int* in_sizes, int n_in,
                              void* d_out, int out_size) {
    const float* h     = (const float*)d_in[0];
    const int*   src   = (const int*)  d_in[1];
    const int*   dst   = (const int*)  d_in[2];
    const float* W1    = (const float*)d_in[3];
    const float* b1    = (const float*)d_in[4];
    const float* W2    = (const float*)d_in[5];
    const float* b2    = (const float*)d_in[6];
    const float* w_src = (const float*)d_in[7];
    const float* w_dst = (const float*)d_in[8];
    float* out = (float*)d_out;

    float *p_feat0, *p_featA, *p_featB;
    cudaGetSymbolAddress((void**)&p_feat0, g_feat0);
    cudaGetSymbolAddress((void**)&p_featA, g_featA);
    cudaGetSymbolAddress((void**)&p_featB, g_featB);
    __nv_bfloat16 *p_w1hi, *p_w1lo, *p_hidhi, *p_hidlo, *p_w2hi, *p_w2lo;
    cudaGetSymbolAddress((void**)&p_w1hi,  g_W1t_hi);
    cudaGetSymbolAddress((void**)&p_w1lo,  g_W1t_lo);
    cudaGetSymbolAddress((void**)&p_hidhi, g_hid_hi);
    cudaGetSymbolAddress((void**)&p_hidlo, g_hid_lo);
    cudaGetSymbolAddress((void**)&p_w2hi,  g_W2t_hi);
    cudaGetSymbolAddress((void**)&p_w2lo,  g_W2t_lo);

    static bool attrSet = false;
    if (!attrSet) {
        cudaFuncSetAttribute(mma_gemm1_kernel,
                             cudaFuncAttributeMaxDynamicSharedMemorySize, G1_SMEM);
        attrSet = true;
    }

    const int nodeBlocks = (NN + 255) / 256;
    const int edgeBlocks = (NE + 255) / 256;
    const int warpNodeBlocks = (NN + 7) / 8;
    const int nbScan = (NN + 511) / 512;      // 98

    // graph prep
    init_zero_kernel<<<nodeBlocks, 256>>>();
    degree_kernel<<<edgeBlocks, 256>>>(src, dst);
    scan_block_kernel<<<nbScan, 512>>>();
    scan_bsum_kernel<<<1, 128>>>(nbScan);
    scan_add_kernel<<<(NN + 1 + 255) / 256, 256>>>();
    csr_fill_kernel<<<edgeBlocks, 256>>>(src, dst);

    // weight conversions + GEMMs (h conversion fused into GEMM1)
    convert_W1_kernel<<<(IN_DIM * HID_DIM + 255) / 256, 256>>>(W1);
    convert_W2_kernel<<<(HID_DIM * OUT_DIM + 255) / 256, 256>>>(W2);
    {
        dim3 grid(HID_DIM / 128, (NN + 127) / 128);
        mma_gemm1_kernel<<<grid, 256, G1_SMEM>>>(
            h, p_w1hi, p_w1lo, b1, p_hidhi, p_hidlo, NN);
    }
    {
        dim3 grid(1, (NN + 127) / 128);
        mma_gemm2_kernel<<<grid, 256>>>(
            p_hidhi, p_hidlo, p_w2hi, p_w2lo, b2, p_feat0, NN);
    }

    // 4 hops: feat0 -> B -> A -> B -> (fused: sd + log_softmax, writes out)
    prop_kernel<<<warpNodeBlocks, 256>>>(p_feat0, p_featB);
    prop_kernel<<<warpNodeBlocks, 256>>>(p_featB, p_featA);
    prop_kernel<<<warpNodeBlocks, 256>>>(p_featA, p_featB);
    prop_final_kernel<<<warpNodeBlocks, 256>>>(w_src, w_dst, out);

    attn_kernel<<<warpNodeBlocks, 256>>>(out + (size_t)NN * OUT_DIM);
}

// round 14
// speedup vs baseline: 1.6444x; 1.0612x over previous
#include <cuda_runtime.h>
#include <cuda_bf16.h>
#include <math.h>

#define NN      50000
#define NE      1600000
#define IN_DIM  512
#define HID_DIM 256
#define OUT_DIM 64
#define ALPHA   0.1f

// ---------------- static device scratch (no allocations allowed) ----------------
__device__ float g_feat0 [(size_t)NN * OUT_DIM];
__device__ float g_featA [(size_t)NN * OUT_DIM];
__device__ float g_featB [(size_t)NN * OUT_DIM];
__device__ int   g_deg_out[NN];
__device__ int   g_deg_in [NN];
__device__ float g_norm_src[NN];
__device__ float g_norm_dst[NN];
__device__ int   g_ptr [NN + 1];
__device__ int   g_fill[NN];
__device__ int   g_bsum[256];
__device__ int   g_csr_src[NE];
__device__ int   g_csr_eid[NE];
__device__ float g_s[NN];
__device__ float g_d[NN];
__device__ float g_e[NE];

// bf16 split operands (W1 transposed, hidden, W2 transposed)
__device__ __nv_bfloat16 g_W1t_hi[(size_t)HID_DIM * IN_DIM];  // [N][K]
__device__ __nv_bfloat16 g_W1t_lo[(size_t)HID_DIM * IN_DIM];
__device__ __nv_bfloat16 g_hid_hi[(size_t)NN * HID_DIM];
__device__ __nv_bfloat16 g_hid_lo[(size_t)NN * HID_DIM];
__device__ __nv_bfloat16 g_W2t_hi[(size_t)OUT_DIM * HID_DIM]; // [N][K]
__device__ __nv_bfloat16 g_W2t_lo[(size_t)OUT_DIM * HID_DIM];

// ---------------- mma.sync helpers ----------------
__device__ __forceinline__ void ldsm4(unsigned& r0, unsigned& r1, unsigned& r2, unsigned& r3,
                                      unsigned addr) {
    asm volatile("ldmatrix.sync.aligned.m8n8.x4.shared.b16 {%0,%1,%2,%3}, [%4];"
                 : "=r"(r0), "=r"(r1), "=r"(r2), "=r"(r3) : "r"(addr));
}
__device__ __forceinline__ void mma_bf16(float* c, const unsigned* a, const unsigned* b) {
    asm volatile("mma.sync.aligned.m16n8k16.row.col.f32.bf16.bf16.f32 "
                 "{%0,%1,%2,%3}, {%4,%5,%6,%7}, {%8,%9}, {%0,%1,%2,%3};"
                 : "+f"(c[0]), "+f"(c[1]), "+f"(c[2]), "+f"(c[3])
                 : "r"(a[0]), "r"(a[1]), "r"(a[2]), "r"(a[3]), "r"(b[0]), "r"(b[1]));
}
__device__ __forceinline__ void cpa16(unsigned dst, const void* src) {
    asm volatile("cp.async.cg.shared.global [%0], [%1], 16;" :: "r"(dst), "l"(src));
}

// split one float into bf16 hi + lo
__device__ __forceinline__ void bsplit(float v, __nv_bfloat16& hi, __nv_bfloat16& lo) {
    hi = __float2bfloat16(v);
    lo = __float2bfloat16(v - __bfloat162float(hi));
}

// ---------------- weight conversion pre-passes ----------------
__global__ void convert_W1_kernel(const float* __restrict__ W1) {
    int idx = blockIdx.x * blockDim.x + threadIdx.x;   // over 512*256
    if (idx >= IN_DIM * HID_DIM) return;
    int k = idx >> 8;
    int n = idx & 255;
    __nv_bfloat16 hi, lo;
    bsplit(W1[idx], hi, lo);
    g_W1t_hi[(size_t)n * IN_DIM + k] = hi;
    g_W1t_lo[(size_t)n * IN_DIM + k] = lo;
}

__global__ void convert_W2_kernel(const float* __restrict__ W2) {
    int idx = blockIdx.x * blockDim.x + threadIdx.x;   // over 256*64
    if (idx >= HID_DIM * OUT_DIM) return;
    int k = idx >> 6;
    int n = idx & 63;
    __nv_bfloat16 hi, lo;
    bsplit(W2[idx], hi, lo);
    g_W2t_hi[(size_t)n * HID_DIM + k] = hi;
    g_W2t_lo[(size_t)n * HID_DIM + k] = lo;
}

// ---------------- GEMM1: bf16 split-3 MMA, fused A conversion, cp.async B ----
// A loaded as fp32 (LDG, reg double-buffered) and split to bf16 in-register;
// B tiles stream via cp.async (no register staging). 2 CTAs/SM enforced.
#define SP 40                              // smem row stride (bf16), ldmatrix conflict-free
#define ARR_BYTES (128 * SP * 2)           // 10240 per tile array
#define OFF_AHI 0
#define OFF_ALO (ARR_BYTES)
#define OFF_BHI (2 * ARR_BYTES)
#define OFF_BLO (3 * ARR_BYTES)
#define STAGE_BYTES (4 * ARR_BYTES)        // 40960
#define G1_SMEM (2 * STAGE_BYTES)          // 81920

extern __shared__ __align__(16) char dynsmem[];

__global__ __launch_bounds__(256, 2) void mma_gemm1_kernel(
    const float* __restrict__ A,                                               // h [M][512] fp32
    const __nv_bfloat16* __restrict__ Bhi, const __nv_bfloat16* __restrict__ Blo,  // [N][K]
    const float* __restrict__ bias,
    __nv_bfloat16* __restrict__ Hhi, __nv_bfloat16* __restrict__ Hlo, int M) {
    const int tid = threadIdx.x;
    const int lane = tid & 31;
    const int warp = tid >> 5;
    const int warpM = warp >> 1;        // 0..3 -> 32 rows each
    const int warpN = warp & 1;         // 0..1 -> 64 cols each
    const int aBase = blockIdx.y * 128;
    const int bBase = blockIdx.x * 128;

    float acc[2][8][4] = {};

    const unsigned uBase = (unsigned)__cvta_generic_to_shared(dynsmem);

    // ldmatrix per-lane offsets (proven layout from prior rounds)
    const int aoff0 = ((warpM * 32 + (lane & 15)) * SP + (lane >> 4) * 8) * 2;
    const int aoff1 = aoff0 + 16 * SP * 2;
    const int g = lane >> 3, r = lane & 7;
    const int boff = ((warpN * 64 + r + ((g & 2) ? 8 : 0)) * SP + ((g & 1) ? 8 : 0)) * 2;

    // loader mapping: thread -> (row, 16-col half)
    const int lrow  = tid >> 1;          // 0..127
    const int lhalf = (tid & 1) * 16;    // col offset 0 or 16
    const bool vA = (aBase + lrow) < M;
    const float* aRow = A + (size_t)(vA ? aBase + lrow : 0) * IN_DIM + lhalf;
    const __nv_bfloat16* bRowHi = Bhi + (size_t)(bBase + lrow) * IN_DIM + lhalf;
    const __nv_bfloat16* bRowLo = Blo + (size_t)(bBase + lrow) * IN_DIM + lhalf;
    const int soff = (lrow * SP + lhalf) * 2;   // byte offset in each tile array

    float4 a4[4];

    // A global load for one K-stage (registers; converted at sts_stage)
    auto ldg_stage = [&](int ks) {
        int k0 = ks * 32;
        if (vA) {
            #pragma unroll
            for (int i = 0; i < 4; i++)
                a4[i] = *reinterpret_cast<const float4*>(aRow + k0 + i * 4);
        } else {
            #pragma unroll
            for (int i = 0; i < 4; i++) a4[i] = make_float4(0.f, 0.f, 0.f, 0.f);
        }
    };

    // B loads stream straight into smem (no registers)
    auto cpa_stage = [&](int ks, int buf) {
        int k0 = ks * 32;
        unsigned sb = uBase + buf * STAGE_BYTES;
        cpa16(sb + OFF_BHI + soff,      bRowHi + k0);
        cpa16(sb + OFF_BHI + soff + 16, bRowHi + k0 + 8);
        cpa16(sb + OFF_BLO + soff,      bRowLo + k0);
        cpa16(sb + OFF_BLO + soff + 16, bRowLo + k0 + 8);
        asm volatile("cp.async.commit_group;");
    };

    // convert A fp32 -> bf16 hi/lo and store to smem
    auto sts_stage = [&](int buf) {
        char* sb = dynsmem + buf * STAGE_BYTES;
        unsigned hp[8], lp[8];
        #pragma unroll
        for (int i = 0; i < 4; i++) {
            __nv_bfloat16 hx, hy, hz, hw, lx, ly, lz, lw;
            bsplit(a4[i].x, hx, lx); bsplit(a4[i].y, hy, ly);
            bsplit(a4[i].z, hz, lz); bsplit(a4[i].w, hw, lw);
            __nv_bfloat162 h0(hx, hy), h1(hz, hw), l0(lx, ly), l1(lz, lw);
            hp[i * 2]     = *reinterpret_cast<unsigned*>(&h0);
            hp[i * 2 + 1] = *reinterpret_cast<unsigned*>(&h1);
            lp[i * 2]     = *reinterpret_cast<unsigned*>(&l0);
            lp[i * 2 + 1] = *reinterpret_cast<unsigned*>(&l1);
        }
        *reinterpret_cast<uint4*>(sb + OFF_AHI + soff)      = make_uint4(hp[0], hp[1], hp[2], hp[3]);
        *reinterpret_cast<uint4*>(sb + OFF_AHI + soff + 16) = make_uint4(hp[4], hp[5], hp[6], hp[7]);
        *reinterpret_cast<uint4*>(sb + OFF_ALO + soff)      = make_uint4(lp[0], lp[1], lp[2], lp[3]);
        *reinterpret_cast<uint4*>(sb + OFF_ALO + soff + 16) = make_uint4(lp[4], lp[5], lp[6], lp[7]);
    };

    // prologue: stage 0
    ldg_stage(0);
    cpa_stage(0, 0);
    sts_stage(0);
    asm volatile("cp.async.wait_group 0;");
    __syncthreads();

    const int NSTAGE = IN_DIM / 32;   // 16
    for (int ks = 0; ks < NSTAGE; ks++) {
        int buf = ks & 1;
        if (ks + 1 < NSTAGE) {
            ldg_stage(ks + 1);            // A LDGs fly during compute
            cpa_stage(ks + 1, buf ^ 1);   // B streams into the other buffer
        }

        unsigned sb = uBase + buf * STAGE_BYTES;
        #pragma unroll
        for (int kk = 0; kk < 32; kk += 16) {
            unsigned ahi[2][4], alo[2][4], bhi[8][2], blo[8][2];
            ldsm4(ahi[0][0], ahi[0][1], ahi[0][2], ahi[0][3], sb + OFF_AHI + aoff0 + kk * 2);
            ldsm4(ahi[1][0], ahi[1][1], ahi[1][2], ahi[1][3], sb + OFF_AHI + aoff1 + kk * 2);
            ldsm4(alo[0][0], alo[0][1], alo[0][2], alo[0][3], sb + OFF_ALO + aoff0 + kk * 2);
            ldsm4(alo[1][0], alo[1][1], alo[1][2], alo[1][3], sb + OFF_ALO + aoff1 + kk * 2);
            #pragma unroll
            for (int n2 = 0; n2 < 4; n2++) {
                int off = boff + n2 * 16 * SP * 2 + kk * 2;
                ldsm4(bhi[2 * n2][0], bhi[2 * n2][1], bhi[2 * n2 + 1][0], bhi[2 * n2 + 1][1],
                      sb + OFF_BHI + off);
                ldsm4(blo[2 * n2][0], blo[2 * n2][1], blo[2 * n2 + 1][0], blo[2 * n2 + 1][1],
                      sb + OFF_BLO + off);
            }
            #pragma unroll
            for (int mi = 0; mi < 2; mi++)
                #pragma unroll
                for (int ni = 0; ni < 8; ni++) {
                    mma_bf16(acc[mi][ni], ahi[mi], bhi[ni]);   // hi*hi
                    mma_bf16(acc[mi][ni], ahi[mi], blo[ni]);   // hi*lo
                    mma_bf16(acc[mi][ni], alo[mi], bhi[ni]);   // lo*hi
                }
        }

        if (ks + 1 < NSTAGE) {
            // safe: all reads of buf^1 completed before the sync at end of ks-1
            sts_stage(buf ^ 1);
            asm volatile("cp.async.wait_group 0;");
            __syncthreads();
        }
    }

    // epilogue: bias + relu, split to bf16 hi/lo for GEMM2
    #pragma unroll
    for (int mi = 0; mi < 2; mi++) {
        #pragma unroll
        for (int ni = 0; ni < 8; ni++) {
            int gn = bBase + warpN * 64 + ni * 8 + (lane & 3) * 2;
            float2 bs = *reinterpret_cast<const float2*>(&bias[gn]);
            int gm0 = aBase + warpM * 32 + mi * 16 + (lane >> 2);
            int gm1 = gm0 + 8;
            #pragma unroll
            for (int half = 0; half < 2; half++) {
                int gm = half ? gm1 : gm0;
                if (gm >= M) continue;
                float vx = fmaxf(acc[mi][ni][half * 2 + 0] + bs.x, 0.f);
                float vy = fmaxf(acc[mi][ni][half * 2 + 1] + bs.y, 0.f);
                __nv_bfloat16 hx, hy, lx, ly;
                bsplit(vx, hx, lx);
                bsplit(vy, hy, ly);
                size_t o = (size_t)gm * HID_DIM + gn;
                *reinterpret_cast<__nv_bfloat162*>(&Hhi[o]) = __nv_bfloat162(hx, hy);
                *reinterpret_cast<__nv_bfloat162*>(&Hlo[o]) = __nv_bfloat162(lx, ly);
            }
        }
    }
}

// ---------------- GEMM2: bf16 split-3 mma.sync, 128x64 block, K=256 ----------------
__global__ __launch_bounds__(256, 2) void mma_gemm2_kernel(
    const __nv_bfloat16* __restrict__ Ahi, const __nv_bfloat16* __restrict__ Alo,
    const __nv_bfloat16* __restrict__ Bhi, const __nv_bfloat16* __restrict__ Blo,
    const float* __restrict__ bias, float* __restrict__ C, int M) {
    __shared__ __align__(16) __nv_bfloat16 sAhi[128 * SP];
    __shared__ __align__(16) __nv_bfloat16 sAlo[128 * SP];
    __shared__ __align__(16) __nv_bfloat16 sBhi[64 * SP];
    __shared__ __align__(16) __nv_bfloat16 sBlo[64 * SP];

    const int tid = threadIdx.x;
    const int lane = tid & 31;
    const int warp = tid >> 5;          // 0..7, each 16 rows x 64 cols
    const int aBase = blockIdx.y * 128;

    float acc[8][4] = {};

    const unsigned uAhi = (unsigned)__cvta_generic_to_shared(sAhi);
    const unsigned uAlo = (unsigned)__cvta_generic_to_shared(sAlo);
    const unsigned uBhi = (unsigned)__cvta_generic_to_shared(sBhi);
    const unsigned uBlo = (unsigned)__cvta_generic_to_shared(sBlo);

    const int aoff = ((warp * 16 + (lane & 15)) * SP + (lane >> 4) * 8) * 2;
    const int g = lane >> 3, r = lane & 7;
    const int boff = ((r + ((g & 2) ? 8 : 0)) * SP + ((g & 1) ? 8 : 0)) * 2;

    for (int k0 = 0; k0 < HID_DIM; k0 += 32) {
        #pragma unroll
        for (int i = 0; i < 2; i++) {
            int f = tid + i * 256;
            int row = f >> 2, seg = f & 3;
            int gm = aBase + row;
            uint4 vh = make_uint4(0, 0, 0, 0), vl = make_uint4(0, 0, 0, 0);
            if (gm < M) {
                size_t go = (size_t)gm * HID_DIM + k0 + seg * 8;
                vh = *reinterpret_cast<const uint4*>(&Ahi[go]);
                vl = *reinterpret_cast<const uint4*>(&Alo[go]);
            }
            int so = row * SP + seg * 8;
            *reinterpret_cast<uint4*>(&sAhi[so]) = vh;
            *reinterpret_cast<uint4*>(&sAlo[so]) = vl;
        }
        {
            int row = tid >> 2, seg = tid & 3;
            size_t go = (size_t)row * HID_DIM + k0 + seg * 8;
            int so = row * SP + seg * 8;
            *reinterpret_cast<uint4*>(&sBhi[so]) = *reinterpret_cast<const uint4*>(&Bhi[go]);
            *reinterpret_cast<uint4*>(&sBlo[so]) = *reinterpret_cast<const uint4*>(&Blo[go]);
        }
        __syncthreads();

        #pragma unroll
        for (int kk = 0; kk < 32; kk += 16) {
            unsigned ahi[4], alo[4], bhi[8][2], blo[8][2];
            ldsm4(ahi[0], ahi[1], ahi[2], ahi[3], uAhi + aoff + kk * 2);
            ldsm4(alo[0], alo[1], alo[2], alo[3], uAlo + aoff + kk * 2);
            #pragma unroll
            for (int n2 = 0; n2 < 4; n2++) {
                int off = boff + n2 * 16 * SP * 2 + kk * 2;
                ldsm4(bhi[2 * n2][0], bhi[2 * n2][1], bhi[2 * n2 + 1][0], bhi[2 * n2 + 1][1],
                      uBhi + off);
                ldsm4(blo[2 * n2][0], blo[2 * n2][1], blo[2 * n2 + 1][0], blo[2 * n2 + 1][1],
                      uBlo + off);
            }
            #pragma unroll
            for (int ni = 0; ni < 8; ni++) {
                mma_bf16(acc[ni], ahi, bhi[ni]);
                mma_bf16(acc[ni], ahi, blo[ni]);
                mma_bf16(acc[ni], alo, bhi[ni]);
            }
        }
        __syncthreads();
    }

    #pragma unroll
    for (int ni = 0; ni < 8; ni++) {
        int gn = ni * 8 + (lane & 3) * 2;
        float2 bs = *reinterpret_cast<const float2*>(&bias[gn]);
        int gm0 = aBase + warp * 16 + (lane >> 2);
        int gm1 = gm0 + 8;
        if (gm0 < M) {
            float2 v = make_float2(acc[ni][0] + bs.x, acc[ni][1] + bs.y);
            *reinterpret_cast<float2*>(&C[(size_t)gm0 * OUT_DIM + gn]) = v;
        }
        if (gm1 < M) {
            float2 v = make_float2(acc[ni][2] + bs.x, acc[ni][3] + bs.y);
            *reinterpret_cast<float2*>(&C[(size_t)gm1 * OUT_DIM + gn]) = v;
        }
    }
}

// ---------------- graph prep ----------------
__global__ void init_zero_kernel() {
    int i = blockIdx.x * blockDim.x + threadIdx.x;
    if (i < NN) {
        g_deg_out[i] = 0;
        g_deg_in[i]  = 0;
        g_fill[i]    = 0;
    }
}

__global__ void degree_kernel(const int* __restrict__ src, const int* __restrict__ dst) {
    int e = blockIdx.x * blockDim.x + threadIdx.x;
    if (e < NE) {
        atomicAdd(&g_deg_out[src[e]], 1);
        atomicAdd(&g_deg_in [dst[e]], 1);
    }
}

__global__ void scan_block_kernel() {
    __shared__ int s[512];
    int tid = threadIdx.x;
    int i = blockIdx.x * 512 + tid;
    int v = (i < NN) ? g_deg_in[i] : 0;
    s[tid] = v;
    __syncthreads();
    #pragma unroll
    for (int off = 1; off < 512; off <<= 1) {
        int t = (tid >= off) ? s[tid - off] : 0;
        __syncthreads();
        s[tid] += t;
        __syncthreads();
    }
    if (i < NN) g_ptr[i] = s[tid] - v;
    if (tid == 511) g_bsum[blockIdx.x] = s[511];
}

__global__ void scan_bsum_kernel(int nb) {
    __shared__ int s[128];
    int tid = threadIdx.x;
    int v = (tid < nb) ? g_bsum[tid] : 0;
    s[tid] = v;
    __syncthreads();
    #pragma unroll
    for (int off = 1; off < 128; off <<= 1) {
        int t = (tid >= off) ? s[tid - off] : 0;
        __syncthreads();
        s[tid] += t;
        __syncthreads();
    }
    if (tid < nb) g_bsum[tid] = s[tid] - v;
}

// scan finalize + degree norms (fused)
__global__ void scan_add_kernel() {
    int i = blockIdx.x * blockDim.x + threadIdx.x;
    if (i < NN) {
        g_ptr[i] += g_bsum[i >> 9];
        g_norm_src[i] = rsqrtf((float)max(g_deg_out[i], 1));
        g_norm_dst[i] = rsqrtf((float)max(g_deg_in [i], 1));
    } else if (i == NN) {
        g_ptr[NN] = NE;
    }
}

__global__ void csr_fill_kernel(const int* __restrict__ src, const int* __restrict__ dst) {
    int e = blockIdx.x * blockDim.x + threadIdx.x;
    if (e < NE) {
        int d = dst[e];
        int pos = g_ptr[d] + atomicAdd(&g_fill[d], 1);
        g_csr_src[pos] = src[e];
        g_csr_eid[pos] = e;
    }
}

// ---------------- propagation hop: warp per dst node, CSR gather ----------------
__global__ void prop_kernel(const float* __restrict__ fin, float* __restrict__ fout) {
    int wid  = (blockIdx.x * blockDim.x + threadIdx.x) >> 5;
    int lane = threadIdx.x & 31;
    if (wid >= NN) return;

    int beg = g_ptr[wid], end = g_ptr[wid + 1];
    float acc0 = 0.f, acc1 = 0.f;

    int j = beg;
    for (; j + 4 <= end; j += 4) {
        int s0 = g_csr_src[j + 0], s1 = g_csr_src[j + 1];
        int s2 = g_csr_src[j + 2], s3 = g_csr_src[j + 3];
        float w0 = g_norm_src[s0], w1 = g_norm_src[s1];
        float w2 = g_norm_src[s2], w3 = g_norm_src[s3];
        const float* p0 = &fin[(size_t)s0 * OUT_DIM];
        const float* p1 = &fin[(size_t)s1 * OUT_DIM];
        const float* p2 = &fin[(size_t)s2 * OUT_DIM];
        const float* p3 = &fin[(size_t)s3 * OUT_DIM];
        acc0 += w0 * p0[lane]      + w1 * p1[lane]      + w2 * p2[lane]      + w3 * p3[lane];
        acc1 += w0 * p0[lane + 32] + w1 * p1[lane + 32] + w2 * p2[lane + 32] + w3 * p3[lane + 32];
    }
    for (; j < end; ++j) {
        int s = g_csr_src[j];
        float w = g_norm_src[s];
        const float* p = &fin[(size_t)s * OUT_DIM];
        acc0 += w * p[lane];
        acc1 += w * p[lane + 32];
    }

    float nd = g_norm_dst[wid];
    size_t o = (size_t)wid * OUT_DIM;
    fout[o + lane]      = (1.0f - ALPHA) * nd * acc0 + ALPHA * g_feat0[o + lane];
    fout[o + 32 + lane] = (1.0f - ALPHA) * nd * acc1 + ALPHA * g_feat0[o + 32 + lane];
}

// ---------------- final hop fused with sd + log_softmax ----------------
__global__ void prop_final_kernel(const float* __restrict__ w_src,
                                  const float* __restrict__ w_dst,
                                  float* __restrict__ out) {
    const float* __restrict__ fin = g_featB;

    int wid  = (blockIdx.x * blockDim.x + threadIdx.x) >> 5;
    int lane = threadIdx.x & 31;
    if (wid >= NN) return;

    int beg = g_ptr[wid], end = g_ptr[wid + 1];
    float acc0 = 0.f, acc1 = 0.f;

    int j = beg;
    for (; j + 4 <= end; j += 4) {
        int s0 = g_csr_src[j + 0], s1 = g_csr_src[j + 1];
        int s2 = g_csr_src[j + 2], s3 = g_csr_src[j + 3];
        float w0 = g_norm_src[s0], w1 = g_norm_src[s1];
        float w2 = g_norm_src[s2], w3 = g_norm_src[s3];
        const float* p0 = &fin[(size_t)s0 * OUT_DIM];
        const float* p1 = &fin[(size_t)s1 * OUT_DIM];
        const float* p2 = &fin[(size_t)s2 * OUT_DIM];
        const float* p3 = &fin[(size_t)s3 * OUT_DIM];
        acc0 += w0 * p0[lane]      + w1 * p1[lane]      + w2 * p2[lane]      + w3 * p3[lane];
        acc1 += w0 * p0[lane + 32] + w1 * p1[lane + 32] + w2 * p2[lane + 32] + w3 * p3[lane + 32];
    }
    for (; j < end; ++j) {
        int s = g_csr_src[j];
        float w = g_norm_src[s];
        const float* p = &fin[(size_t)s * OUT_DIM];
        acc0 += w * p[lane];
        acc1 += w * p[lane + 32];
    }

    float nd = g_norm_dst[wid];
    size_t o = (size_t)wid * OUT_DIM;
    float f0 = (1.0f - ALPHA) * nd * acc0 + ALPHA * g_feat0[o + lane];
    float f1 = (1.0f - ALPHA) * nd * acc1 + ALPHA * g_feat0[o + 32 + lane];

    // attention dot products
    float s = f0 * w_src[lane] + f1 * w_src[lane + 32];
    float d = f0 * w_dst[lane] + f1 * w_dst[lane + 32];
    #pragma unroll
    for (int off = 16; off; off >>= 1) {
        s += __shfl_xor_sync(0xFFFFFFFFu, s, off);
        d += __shfl_xor_sync(0xFFFFFFFFu, d, off);
    }
    if (lane == 0) { g_s[wid] = s; g_d[wid] = d; }

    // log_softmax over the 64 features
    float m = fmaxf(f0, f1);
    #pragma unroll
    for (int off = 16; off; off >>= 1)
        m = fmaxf(m, __shfl_xor_sync(0xFFFFFFFFu, m, off));
    float sum = __expf(f0 - m) + __expf(f1 - m);
    #pragma unroll
    for (int off = 16; off; off >>= 1)
        sum += __shfl_xor_sync(0xFFFFFFFFu, sum, off);
    float ls = m + logf(sum);
    out[o + lane]      = f0 - ls;
    out[o + 32 + lane] = f1 - ls;
}

// ---------------- edge-softmax per dst node (exp cached in g_e) ----------------
__global__ void attn_kernel(float* __restrict__ attn_out) {
    int wid  = (blockIdx.x * blockDim.x + threadIdx.x) >> 5;
    int lane = threadIdx.x & 31;
    if (wid >= NN) return;
    int beg = g_ptr[wid], end = g_ptr[wid + 1];
    if (beg == end) return;
    float dn = g_d[wid];

    float m = -2.0f;  // tanh >= -1
    for (int j = beg + lane; j < end; j += 32) {
        float e = tanhf(g_s[g_csr_src[j]] + dn);
        g_e[j] = e;
        m = fmaxf(m, e);
    }
    #pragma unroll
    for (int off = 16; off; off >>= 1)
        m = fmaxf(m, __shfl_xor_sync(0xFFFFFFFFu, m, off));

    float sum = 0.f;
    for (int j = beg + lane; j < end; j += 32) {
        float ex = __expf(g_e[j] - m);
        g_e[j] = ex;                    // cache exp for pass 3
        sum += ex;
    }
    #pragma unroll
    for (int off = 16; off; off >>= 1)
        sum += __shfl_xor_sync(0xFFFFFFFFu, sum, off);

    float inv = 1.0f / sum;
    for (int j = beg + lane; j < end; j += 32)
        attn_out[g_csr_eid[j]] = g_e[j] * inv;
}

// ---------------- launch (single stream, capture-safe) ----------------
extern "C" void kernel_launch(void* const* d_in, const int* in_sizes, int n_in,
                              void* d_out, int out_size) {
    const float* h     = (const float*)d_in[0];
    const int*   src   = (const int*)  d_in[1];
    const int*   dst   = (const int*)  d_in[2];
    const float* W1    = (const float*)d_in[3];
    const float* b1    = (const float*)d_in[4];
    const float* W2    = (const float*)d_in[5];
    const float* b2    = (const float*)d_in[6];
    const float* w_src = (const float*)d_in[7];
    const float* w_dst = (const float*)d_in[8];
    float* out = (float*)d_out;

    float *p_feat0, *p_featA, *p_featB;
    cudaGetSymbolAddress((void**)&p_feat0, g_feat0);
    cudaGetSymbolAddress((void**)&p_featA, g_featA);
    cudaGetSymbolAddress((void**)&p_featB, g_featB);
    __nv_bfloat16 *p_w1hi, *p_w1lo, *p_hidhi, *p_hidlo, *p_w2hi, *p_w2lo;
    cudaGetSymbolAddress((void**)&p_w1hi,  g_W1t_hi);
    cudaGetSymbolAddress((void**)&p_w1lo,  g_W1t_lo);
    cudaGetSymbolAddress((void**)&p_hidhi, g_hid_hi);
    cudaGetSymbolAddress((void**)&p_hidlo, g_hid_lo);
    cudaGetSymbolAddress((void**)&p_w2hi,  g_W2t_hi);
    cudaGetSymbolAddress((void**)&p_w2lo,  g_W2t_lo);

    static bool attrSet = false;
    if (!attrSet) {
        cudaFuncSetAttribute(mma_gemm1_kernel,
                             cudaFuncAttributeMaxDynamicSharedMemorySize, G1_SMEM);
        attrSet = true;
    }

    const int nodeBlocks = (NN + 255) / 256;
    const int edgeBlocks = (NE + 255) / 256;
    const int warpNodeBlocks = (NN + 7) / 8;
    const int nbScan = (NN + 511) / 512;      // 98

    // graph prep
    init_zero_kernel<<<nodeBlocks, 256>>>();
    degree_kernel<<<edgeBlocks, 256>>>(src, dst);
    scan_block_kernel<<<nbScan, 512>>>();
    scan_bsum_kernel<<<1, 128>>>(nbScan);
    scan_add_kernel<<<(NN + 1 + 255) / 256, 256>>>();
    csr_fill_kernel<<<edgeBlocks, 256>>>(src, dst);

    // weight conversions + GEMMs (h conversion fused into GEMM1)
    convert_W1_kernel<<<(IN_DIM * HID_DIM + 255) / 256, 256>>>(W1);
    convert_W2_kernel<<<(HID_DIM * OUT_DIM + 255) / 256, 256>>>(W2);
    {
        dim3 grid(HID_DIM / 128, (NN + 127) / 128);
        mma_gemm1_kernel<<<grid, 256, G1_SMEM>>>(
            h, p_w1hi, p_w1lo, b1, p_hidhi, p_hidlo, NN);
    }
    {
        dim3 grid(1, (NN + 127) / 128);
        mma_gemm2_kernel<<<grid, 256>>>(
            p_hidhi, p_hidlo, p_w2hi, p_w2lo, b2, p_feat0, NN);
    }

    // 4 hops: feat0 -> B -> A -> B -> (fused: sd + log_softmax, writes out)
    prop_kernel<<<warpNodeBlocks, 256>>>(p_feat0, p_featB);
    prop_kernel<<<warpNodeBlocks, 256>>>(p_featB, p_featA);
    prop_kernel<<<warpNodeBlocks, 256>>>(p_featA, p_featB);
    prop_final_kernel<<<warpNodeBlocks, 256>>>(w_src, w_dst, out);

    attn_kernel<<<warpNodeBlocks, 256>>>(out + (size_t)NN * OUT_DIM);
}

// round 15
// speedup vs baseline: 1.6464x; 1.0012x over previous
#include <cuda_runtime.h>
#include <cuda_bf16.h>
#include <math.h>

#define NN      50000
#define NE      1600000
#define IN_DIM  512
#define HID_DIM 256
#define OUT_DIM 64
#define ALPHA   0.1f

// ---------------- static device scratch (no allocations allowed) ----------------
__device__ float g_feat0 [(size_t)NN * OUT_DIM];
__device__ float g_featA [(size_t)NN * OUT_DIM];
__device__ float g_featB [(size_t)NN * OUT_DIM];
__device__ int   g_deg_out[NN];
__device__ int   g_deg_in [NN];
__device__ float g_norm_src[NN];
__device__ float g_norm_dst[NN];
__device__ int   g_ptr [NN + 1];
__device__ int   g_fill[NN];
__device__ int   g_bsum[256];
__device__ int   g_csr_src[NE];
__device__ int   g_csr_eid[NE];
__device__ float g_s[NN];
__device__ float g_d[NN];
__device__ float g_e[NE];

// bf16 split operands (W1 transposed, hidden, W2 transposed)
__device__ __nv_bfloat16 g_W1t_hi[(size_t)HID_DIM * IN_DIM];  // [N][K]
__device__ __nv_bfloat16 g_W1t_lo[(size_t)HID_DIM * IN_DIM];
__device__ __nv_bfloat16 g_hid_hi[(size_t)NN * HID_DIM];
__device__ __nv_bfloat16 g_hid_lo[(size_t)NN * HID_DIM];
__device__ __nv_bfloat16 g_W2t_hi[(size_t)OUT_DIM * HID_DIM]; // [N][K]
__device__ __nv_bfloat16 g_W2t_lo[(size_t)OUT_DIM * HID_DIM];

// ---------------- mma.sync helpers ----------------
__device__ __forceinline__ void ldsm4(unsigned& r0, unsigned& r1, unsigned& r2, unsigned& r3,
                                      unsigned addr) {
    asm volatile("ldmatrix.sync.aligned.m8n8.x4.shared.b16 {%0,%1,%2,%3}, [%4];"
                 : "=r"(r0), "=r"(r1), "=r"(r2), "=r"(r3) : "r"(addr));
}
__device__ __forceinline__ void mma_bf16(float* c, const unsigned* a, const unsigned* b) {
    asm volatile("mma.sync.aligned.m16n8k16.row.col.f32.bf16.bf16.f32 "
                 "{%0,%1,%2,%3}, {%4,%5,%6,%7}, {%8,%9}, {%0,%1,%2,%3};"
                 : "+f"(c[0]), "+f"(c[1]), "+f"(c[2]), "+f"(c[3])
                 : "r"(a[0]), "r"(a[1]), "r"(a[2]), "r"(a[3]), "r"(b[0]), "r"(b[1]));
}
__device__ __forceinline__ void cpa16(unsigned dst, const void* src) {
    asm volatile("cp.async.cg.shared.global [%0], [%1], 16;" :: "r"(dst), "l"(src));
}

// split one float into bf16 hi + lo
__device__ __forceinline__ void bsplit(float v, __nv_bfloat16& hi, __nv_bfloat16& lo) {
    hi = __float2bfloat16(v);
    lo = __float2bfloat16(v - __bfloat162float(hi));
}

// ---------------- weight conversion (W1 + W2 fused, one launch) ----------------
__global__ void convert_W_kernel(const float* __restrict__ W1, const float* __restrict__ W2) {
    int idx = blockIdx.x * blockDim.x + threadIdx.x;
    if (idx < IN_DIM * HID_DIM) {
        int k = idx >> 8;
        int n = idx & 255;
        __nv_bfloat16 hi, lo;
        bsplit(W1[idx], hi, lo);
        g_W1t_hi[(size_t)n * IN_DIM + k] = hi;
        g_W1t_lo[(size_t)n * IN_DIM + k] = lo;
    }
    int idx2 = idx - IN_DIM * HID_DIM;
    if (idx2 >= 0 && idx2 < HID_DIM * OUT_DIM) {
        int k = idx2 >> 6;
        int n = idx2 & 63;
        __nv_bfloat16 hi, lo;
        bsplit(W2[idx2], hi, lo);
        g_W2t_hi[(size_t)n * HID_DIM + k] = hi;
        g_W2t_lo[(size_t)n * HID_DIM + k] = lo;
    }
}

// ---------------- GEMM1: bf16 split-3 MMA, fused A conversion, cp.async B ----
#define SP 40                              // smem row stride (bf16), ldmatrix conflict-free
#define ARR_BYTES (128 * SP * 2)           // 10240 per tile array
#define OFF_AHI 0
#define OFF_ALO (ARR_BYTES)
#define OFF_BHI (2 * ARR_BYTES)
#define OFF_BLO (3 * ARR_BYTES)
#define STAGE_BYTES (4 * ARR_BYTES)        // 40960
#define G1_SMEM (2 * STAGE_BYTES)          // 81920

extern __shared__ __align__(16) char dynsmem[];

__global__ __launch_bounds__(256, 2) void mma_gemm1_kernel(
    const float* __restrict__ A,                                               // h [M][512] fp32
    const __nv_bfloat16* __restrict__ Bhi, const __nv_bfloat16* __restrict__ Blo,  // [N][K]
    const float* __restrict__ bias,
    __nv_bfloat16* __restrict__ Hhi, __nv_bfloat16* __restrict__ Hlo, int M) {
    const int tid = threadIdx.x;
    const int lane = tid & 31;
    const int warp = tid >> 5;
    const int warpM = warp >> 1;        // 0..3 -> 32 rows each
    const int warpN = warp & 1;         // 0..1 -> 64 cols each
    const int aBase = blockIdx.y * 128;
    const int bBase = blockIdx.x * 128;

    float acc[2][8][4] = {};

    const unsigned uBase = (unsigned)__cvta_generic_to_shared(dynsmem);

    const int aoff0 = ((warpM * 32 + (lane & 15)) * SP + (lane >> 4) * 8) * 2;
    const int aoff1 = aoff0 + 16 * SP * 2;
    const int g = lane >> 3, r = lane & 7;
    const int boff = ((warpN * 64 + r + ((g & 2) ? 8 : 0)) * SP + ((g & 1) ? 8 : 0)) * 2;

    const int lrow  = tid >> 1;          // 0..127
    const int lhalf = (tid & 1) * 16;    // col offset 0 or 16
    const bool vA = (aBase + lrow) < M;
    const float* aRow = A + (size_t)(vA ? aBase + lrow : 0) * IN_DIM + lhalf;
    const __nv_bfloat16* bRowHi = Bhi + (size_t)(bBase + lrow) * IN_DIM + lhalf;
    const __nv_bfloat16* bRowLo = Blo + (size_t)(bBase + lrow) * IN_DIM + lhalf;
    const int soff = (lrow * SP + lhalf) * 2;

    float4 a4[4];

    auto ldg_stage = [&](int ks) {
        int k0 = ks * 32;
        if (vA) {
            #pragma unroll
            for (int i = 0; i < 4; i++)
                a4[i] = *reinterpret_cast<const float4*>(aRow + k0 + i * 4);
        } else {
            #pragma unroll
            for (int i = 0; i < 4; i++) a4[i] = make_float4(0.f, 0.f, 0.f, 0.f);
        }
    };

    auto cpa_stage = [&](int ks, int buf) {
        int k0 = ks * 32;
        unsigned sb = uBase + buf * STAGE_BYTES;
        cpa16(sb + OFF_BHI + soff,      bRowHi + k0);
        cpa16(sb + OFF_BHI + soff + 16, bRowHi + k0 + 8);
        cpa16(sb + OFF_BLO + soff,      bRowLo + k0);
        cpa16(sb + OFF_BLO + soff + 16, bRowLo + k0 + 8);
        asm volatile("cp.async.commit_group;");
    };

    auto sts_stage = [&](int buf) {
        char* sb = dynsmem + buf * STAGE_BYTES;
        unsigned hp[8], lp[8];
        #pragma unroll
        for (int i = 0; i < 4; i++) {
            __nv_bfloat16 hx, hy, hz, hw, lx, ly, lz, lw;
            bsplit(a4[i].x, hx, lx); bsplit(a4[i].y, hy, ly);
            bsplit(a4[i].z, hz, lz); bsplit(a4[i].w, hw, lw);
            __nv_bfloat162 h0(hx, hy), h1(hz, hw), l0(lx, ly), l1(lz, lw);
            hp[i * 2]     = *reinterpret_cast<unsigned*>(&h0);
            hp[i * 2 + 1] = *reinterpret_cast<unsigned*>(&h1);
            lp[i * 2]     = *reinterpret_cast<unsigned*>(&l0);
            lp[i * 2 + 1] = *reinterpret_cast<unsigned*>(&l1);
        }
        *reinterpret_cast<uint4*>(sb + OFF_AHI + soff)      = make_uint4(hp[0], hp[1], hp[2], hp[3]);
        *reinterpret_cast<uint4*>(sb + OFF_AHI + soff + 16) = make_uint4(hp[4], hp[5], hp[6], hp[7]);
        *reinterpret_cast<uint4*>(sb + OFF_ALO + soff)      = make_uint4(lp[0], lp[1], lp[2], lp[3]);
        *reinterpret_cast<uint4*>(sb + OFF_ALO + soff + 16) = make_uint4(lp[4], lp[5], lp[6], lp[7]);
    };

    ldg_stage(0);
    cpa_stage(0, 0);
    sts_stage(0);
    asm volatile("cp.async.wait_group 0;");
    __syncthreads();

    const int NSTAGE = IN_DIM / 32;   // 16
    for (int ks = 0; ks < NSTAGE; ks++) {
        int buf = ks & 1;
        if (ks + 1 < NSTAGE) {
            ldg_stage(ks + 1);
            cpa_stage(ks + 1, buf ^ 1);
        }

        unsigned sb = uBase + buf * STAGE_BYTES;
        #pragma unroll
        for (int kk = 0; kk < 32; kk += 16) {
            unsigned ahi[2][4], alo[2][4], bhi[8][2], blo[8][2];
            ldsm4(ahi[0][0], ahi[0][1], ahi[0][2], ahi[0][3], sb + OFF_AHI + aoff0 + kk * 2);
            ldsm4(ahi[1][0], ahi[1][1], ahi[1][2], ahi[1][3], sb + OFF_AHI + aoff1 + kk * 2);
            ldsm4(alo[0][0], alo[0][1], alo[0][2], alo[0][3], sb + OFF_ALO + aoff0 + kk * 2);
            ldsm4(alo[1][0], alo[1][1], alo[1][2], alo[1][3], sb + OFF_ALO + aoff1 + kk * 2);
            #pragma unroll
            for (int n2 = 0; n2 < 4; n2++) {
                int off = boff + n2 * 16 * SP * 2 + kk * 2;
                ldsm4(bhi[2 * n2][0], bhi[2 * n2][1], bhi[2 * n2 + 1][0], bhi[2 * n2 + 1][1],
                      sb + OFF_BHI + off);
                ldsm4(blo[2 * n2][0], blo[2 * n2][1], blo[2 * n2 + 1][0], blo[2 * n2 + 1][1],
                      sb + OFF_BLO + off);
            }
            #pragma unroll
            for (int mi = 0; mi < 2; mi++)
                #pragma unroll
                for (int ni = 0; ni < 8; ni++) {
                    mma_bf16(acc[mi][ni], ahi[mi], bhi[ni]);   // hi*hi
                    mma_bf16(acc[mi][ni], ahi[mi], blo[ni]);   // hi*lo
                    mma_bf16(acc[mi][ni], alo[mi], bhi[ni]);   // lo*hi
                }
        }

        if (ks + 1 < NSTAGE) {
            sts_stage(buf ^ 1);
            asm volatile("cp.async.wait_group 0;");
            __syncthreads();
        }
    }

    // epilogue: bias + relu, split to bf16 hi/lo for GEMM2
    #pragma unroll
    for (int mi = 0; mi < 2; mi++) {
        #pragma unroll
        for (int ni = 0; ni < 8; ni++) {
            int gn = bBase + warpN * 64 + ni * 8 + (lane & 3) * 2;
            float2 bs = *reinterpret_cast<const float2*>(&bias[gn]);
            int gm0 = aBase + warpM * 32 + mi * 16 + (lane >> 2);
            int gm1 = gm0 + 8;
            #pragma unroll
            for (int half = 0; half < 2; half++) {
                int gm = half ? gm1 : gm0;
                if (gm >= M) continue;
                float vx = fmaxf(acc[mi][ni][half * 2 + 0] + bs.x, 0.f);
                float vy = fmaxf(acc[mi][ni][half * 2 + 1] + bs.y, 0.f);
                __nv_bfloat16 hx, hy, lx, ly;
                bsplit(vx, hx, lx);
                bsplit(vy, hy, ly);
                size_t o = (size_t)gm * HID_DIM + gn;
                *reinterpret_cast<__nv_bfloat162*>(&Hhi[o]) = __nv_bfloat162(hx, hy);
                *reinterpret_cast<__nv_bfloat162*>(&Hlo[o]) = __nv_bfloat162(lx, ly);
            }
        }
    }
}

// ---------------- GEMM2: bf16 split-3 mma.sync, 128x64 block, K=256 ----------------
__global__ __launch_bounds__(256, 2) void mma_gemm2_kernel(
    const __nv_bfloat16* __restrict__ Ahi, const __nv_bfloat16* __restrict__ Alo,
    const __nv_bfloat16* __restrict__ Bhi, const __nv_bfloat16* __restrict__ Blo,
    const float* __restrict__ bias, float* __restrict__ C, int M) {
    __shared__ __align__(16) __nv_bfloat16 sAhi[128 * SP];
    __shared__ __align__(16) __nv_bfloat16 sAlo[128 * SP];
    __shared__ __align__(16) __nv_bfloat16 sBhi[64 * SP];
    __shared__ __align__(16) __nv_bfloat16 sBlo[64 * SP];

    const int tid = threadIdx.x;
    const int lane = tid & 31;
    const int warp = tid >> 5;          // 0..7, each 16 rows x 64 cols
    const int aBase = blockIdx.y * 128;

    float acc[8][4] = {};

    const unsigned uAhi = (unsigned)__cvta_generic_to_shared(sAhi);
    const unsigned uAlo = (unsigned)__cvta_generic_to_shared(sAlo);
    const unsigned uBhi = (unsigned)__cvta_generic_to_shared(sBhi);
    const unsigned uBlo = (unsigned)__cvta_generic_to_shared(sBlo);

    const int aoff = ((warp * 16 + (lane & 15)) * SP + (lane >> 4) * 8) * 2;
    const int g = lane >> 3, r = lane & 7;
    const int boff = ((r + ((g & 2) ? 8 : 0)) * SP + ((g & 1) ? 8 : 0)) * 2;

    for (int k0 = 0; k0 < HID_DIM; k0 += 32) {
        #pragma unroll
        for (int i = 0; i < 2; i++) {
            int f = tid + i * 256;
            int row = f >> 2, seg = f & 3;
            int gm = aBase + row;
            uint4 vh = make_uint4(0, 0, 0, 0), vl = make_uint4(0, 0, 0, 0);
            if (gm < M) {
                size_t go = (size_t)gm * HID_DIM + k0 + seg * 8;
                vh = *reinterpret_cast<const uint4*>(&Ahi[go]);
                vl = *reinterpret_cast<const uint4*>(&Alo[go]);
            }
            int so = row * SP + seg * 8;
            *reinterpret_cast<uint4*>(&sAhi[so]) = vh;
            *reinterpret_cast<uint4*>(&sAlo[so]) = vl;
        }
        {
            int row = tid >> 2, seg = tid & 3;
            size_t go = (size_t)row * HID_DIM + k0 + seg * 8;
            int so = row * SP + seg * 8;
            *reinterpret_cast<uint4*>(&sBhi[so]) = *reinterpret_cast<const uint4*>(&Bhi[go]);
            *reinterpret_cast<uint4*>(&sBlo[so]) = *reinterpret_cast<const uint4*>(&Blo[go]);
        }
        __syncthreads();

        #pragma unroll
        for (int kk = 0; kk < 32; kk += 16) {
            unsigned ahi[4], alo[4], bhi[8][2], blo[8][2];
            ldsm4(ahi[0], ahi[1], ahi[2], ahi[3], uAhi + aoff + kk * 2);
            ldsm4(alo[0], alo[1], alo[2], alo[3], uAlo + aoff + kk * 2);
            #pragma unroll
            for (int n2 = 0; n2 < 4; n2++) {
                int off = boff + n2 * 16 * SP * 2 + kk * 2;
                ldsm4(bhi[2 * n2][0], bhi[2 * n2][1], bhi[2 * n2 + 1][0], bhi[2 * n2 + 1][1],
                      uBhi + off);
                ldsm4(blo[2 * n2][0], blo[2 * n2][1], blo[2 * n2 + 1][0], blo[2 * n2 + 1][1],
                      uBlo + off);
            }
            #pragma unroll
            for (int ni = 0; ni < 8; ni++) {
                mma_bf16(acc[ni], ahi, bhi[ni]);
                mma_bf16(acc[ni], ahi, blo[ni]);
                mma_bf16(acc[ni], alo, bhi[ni]);
            }
        }
        __syncthreads();
    }

    #pragma unroll
    for (int ni = 0; ni < 8; ni++) {
        int gn = ni * 8 + (lane & 3) * 2;
        float2 bs = *reinterpret_cast<const float2*>(&bias[gn]);
        int gm0 = aBase + warp * 16 + (lane >> 2);
        int gm1 = gm0 + 8;
        if (gm0 < M) {
            float2 v = make_float2(acc[ni][0] + bs.x, acc[ni][1] + bs.y);
            *reinterpret_cast<float2*>(&C[(size_t)gm0 * OUT_DIM + gn]) = v;
        }
        if (gm1 < M) {
            float2 v = make_float2(acc[ni][2] + bs.x, acc[ni][3] + bs.y);
            *reinterpret_cast<float2*>(&C[(size_t)gm1 * OUT_DIM + gn]) = v;
        }
    }
}

// ---------------- graph prep ----------------
__global__ void init_zero_kernel() {
    int i = blockIdx.x * blockDim.x + threadIdx.x;
    if (i < NN) {
        g_deg_out[i] = 0;
        g_deg_in[i]  = 0;
        g_fill[i]    = 0;
    }
}

// 4 edges/thread, int4 vector loads (NE % 4 == 0)
__global__ void degree_kernel(const int* __restrict__ src, const int* __restrict__ dst) {
    int t = blockIdx.x * blockDim.x + threadIdx.x;
    if (t >= NE / 4) return;
    int4 s4 = *reinterpret_cast<const int4*>(src + t * 4);
    int4 d4 = *reinterpret_cast<const int4*>(dst + t * 4);
    atomicAdd(&g_deg_out[s4.x], 1);
    atomicAdd(&g_deg_out[s4.y], 1);
    atomicAdd(&g_deg_out[s4.z], 1);
    atomicAdd(&g_deg_out[s4.w], 1);
    atomicAdd(&g_deg_in[d4.x], 1);
    atomicAdd(&g_deg_in[d4.y], 1);
    atomicAdd(&g_deg_in[d4.z], 1);
    atomicAdd(&g_deg_in[d4.w], 1);
}

__global__ void scan_block_kernel() {
    __shared__ int s[512];
    int tid = threadIdx.x;
    int i = blockIdx.x * 512 + tid;
    int v = (i < NN) ? g_deg_in[i] : 0;
    s[tid] = v;
    __syncthreads();
    #pragma unroll
    for (int off = 1; off < 512; off <<= 1) {
        int t = (tid >= off) ? s[tid - off] : 0;
        __syncthreads();
        s[tid] += t;
        __syncthreads();
    }
    if (i < NN) g_ptr[i] = s[tid] - v;
    if (tid == 511) g_bsum[blockIdx.x] = s[511];
}

__global__ void scan_bsum_kernel(int nb) {
    __shared__ int s[128];
    int tid = threadIdx.x;
    int v = (tid < nb) ? g_bsum[tid] : 0;
    s[tid] = v;
    __syncthreads();
    #pragma unroll
    for (int off = 1; off < 128; off <<= 1) {
        int t = (tid >= off) ? s[tid - off] : 0;
        __syncthreads();
        s[tid] += t;
        __syncthreads();
    }
    if (tid < nb) g_bsum[tid] = s[tid] - v;
}

// scan finalize + degree norms (fused)
__global__ void scan_add_kernel() {
    int i = blockIdx.x * blockDim.x + threadIdx.x;
    if (i < NN) {
        g_ptr[i] += g_bsum[i >> 9];
        g_norm_src[i] = rsqrtf((float)max(g_deg_out[i], 1));
        g_norm_dst[i] = rsqrtf((float)max(g_deg_in [i], 1));
    } else if (i == NN) {
        g_ptr[NN] = NE;
    }
}

// 4 edges/thread, int4 vector loads
__global__ void csr_fill_kernel(const int* __restrict__ src, const int* __restrict__ dst) {
    int t = blockIdx.x * blockDim.x + threadIdx.x;
    if (t >= NE / 4) return;
    int e0 = t * 4;
    int4 s4 = *reinterpret_cast<const int4*>(src + e0);
    int4 d4 = *reinterpret_cast<const int4*>(dst + e0);
    int p0 = g_ptr[d4.x] + atomicAdd(&g_fill[d4.x], 1);
    int p1 = g_ptr[d4.y] + atomicAdd(&g_fill[d4.y], 1);
    int p2 = g_ptr[d4.z] + atomicAdd(&g_fill[d4.z], 1);
    int p3 = g_ptr[d4.w] + atomicAdd(&g_fill[d4.w], 1);
    g_csr_src[p0] = s4.x; g_csr_eid[p0] = e0;
    g_csr_src[p1] = s4.y; g_csr_eid[p1] = e0 + 1;
    g_csr_src[p2] = s4.z; g_csr_eid[p2] = e0 + 2;
    g_csr_src[p3] = s4.w; g_csr_eid[p3] = e0 + 3;
}

// ---------------- propagation hop: warp per dst node, CSR gather ----------------
__global__ void prop_kernel(const float* __restrict__ fin, float* __restrict__ fout) {
    int wid  = (blockIdx.x * blockDim.x + threadIdx.x) >> 5;
    int lane = threadIdx.x & 31;
    if (wid >= NN) return;

    int beg = g_ptr[wid], end = g_ptr[wid + 1];
    float acc0 = 0.f, acc1 = 0.f;

    int j = beg;
    for (; j + 4 <= end; j += 4) {
        int s0 = g_csr_src[j + 0], s1 = g_csr_src[j + 1];
        int s2 = g_csr_src[j + 2], s3 = g_csr_src[j + 3];
        float w0 = g_norm_src[s0], w1 = g_norm_src[s1];
        float w2 = g_norm_src[s2], w3 = g_norm_src[s3];
        const float* p0 = &fin[(size_t)s0 * OUT_DIM];
        const float* p1 = &fin[(size_t)s1 * OUT_DIM];
        const float* p2 = &fin[(size_t)s2 * OUT_DIM];
        const float* p3 = &fin[(size_t)s3 * OUT_DIM];
        acc0 += w0 * p0[lane]      + w1 * p1[lane]      + w2 * p2[lane]      + w3 * p3[lane];
        acc1 += w0 * p0[lane + 32] + w1 * p1[lane + 32] + w2 * p2[lane + 32] + w3 * p3[lane + 32];
    }
    for (; j < end; ++j) {
        int s = g_csr_src[j];
        float w = g_norm_src[s];
        const float* p = &fin[(size_t)s * OUT_DIM];
        acc0 += w * p[lane];
        acc1 += w * p[lane + 32];
    }

    float nd = g_norm_dst[wid];
    size_t o = (size_t)wid * OUT_DIM;
    fout[o + lane]      = (1.0f - ALPHA) * nd * acc0 + ALPHA * g_feat0[o + lane];
    fout[o + 32 + lane] = (1.0f - ALPHA) * nd * acc1 + ALPHA * g_feat0[o + 32 + lane];
}

// ---------------- final hop fused with sd + log_softmax ----------------
__global__ void prop_final_kernel(const float* __restrict__ w_src,
                                  const float* __restrict__ w_dst,
                                  float* __restrict__ out) {
    const float* __restrict__ fin = g_featB;

    int wid  = (blockIdx.x * blockDim.x + threadIdx.x) >> 5;
    int lane = threadIdx.x & 31;
    if (wid >= NN) return;

    int beg = g_ptr[wid], end = g_ptr[wid + 1];
    float acc0 = 0.f, acc1 = 0.f;

    int j = beg;
    for (; j + 4 <= end; j += 4) {
        int s0 = g_csr_src[j + 0], s1 = g_csr_src[j + 1];
        int s2 = g_csr_src[j + 2], s3 = g_csr_src[j + 3];
        float w0 = g_norm_src[s0], w1 = g_norm_src[s1];
        float w2 = g_norm_src[s2], w3 = g_norm_src[s3];
        const float* p0 = &fin[(size_t)s0 * OUT_DIM];
        const float* p1 = &fin[(size_t)s1 * OUT_DIM];
        const float* p2 = &fin[(size_t)s2 * OUT_DIM];
        const float* p3 = &fin[(size_t)s3 * OUT_DIM];
        acc0 += w0 * p0[lane]      + w1 * p1[lane]      + w2 * p2[lane]      + w3 * p3[lane];
        acc1 += w0 * p0[lane + 32] + w1 * p1[lane + 32] + w2 * p2[lane + 32] + w3 * p3[lane + 32];
    }
    for (; j < end; ++j) {
        int s = g_csr_src[j];
        float w = g_norm_src[s];
        const float* p = &fin[(size_t)s * OUT_DIM];
        acc0 += w * p[lane];
        acc1 += w * p[lane + 32];
    }

    float nd = g_norm_dst[wid];
    size_t o = (size_t)wid * OUT_DIM;
    float f0 = (1.0f - ALPHA) * nd * acc0 + ALPHA * g_feat0[o + lane];
    float f1 = (1.0f - ALPHA) * nd * acc1 + ALPHA * g_feat0[o + 32 + lane];

    // attention dot products
    float s = f0 * w_src[lane] + f1 * w_src[lane + 32];
    float d = f0 * w_dst[lane] + f1 * w_dst[lane + 32];
    #pragma unroll
    for (int off = 16; off; off >>= 1) {
        s += __shfl_xor_sync(0xFFFFFFFFu, s, off);
        d += __shfl_xor_sync(0xFFFFFFFFu, d, off);
    }
    if (lane == 0) { g_s[wid] = s; g_d[wid] = d; }

    // log_softmax over the 64 features
    float m = fmaxf(f0, f1);
    #pragma unroll
    for (int off = 16; off; off >>= 1)
        m = fmaxf(m, __shfl_xor_sync(0xFFFFFFFFu, m, off));
    float sum = __expf(f0 - m) + __expf(f1 - m);
    #pragma unroll
    for (int off = 16; off; off >>= 1)
        sum += __shfl_xor_sync(0xFFFFFFFFu, sum, off);
    float ls = m + logf(sum);
    out[o + lane]      = f0 - ls;
    out[o + 32 + lane] = f1 - ls;
}

// ---------------- edge-softmax per dst node, 2 passes ----------------
// tanh is bounded in [-1,1], so exp(e) is in [0.37, 2.72] — the max-subtraction
// pass is unnecessary for fp32 safety and exp(e)/sum(exp(e)) is mathematically
// identical to the max-shifted form.
__global__ void attn_kernel(float* __restrict__ attn_out) {
    int wid  = (blockIdx.x * blockDim.x + threadIdx.x) >> 5;
    int lane = threadIdx.x & 31;
    if (wid >= NN) return;
    int beg = g_ptr[wid], end = g_ptr[wid + 1];
    if (beg == end) return;
    float dn = g_d[wid];

    float sum = 0.f;
    for (int j = beg + lane; j < end; j += 32) {
        float ex = __expf(tanhf(g_s[g_csr_src[j]] + dn));
        g_e[j] = ex;
        sum += ex;
    }
    #pragma unroll
    for (int off = 16; off; off >>= 1)
        sum += __shfl_xor_sync(0xFFFFFFFFu, sum, off);

    float inv = 1.0f / sum;
    for (int j = beg + lane; j < end; j += 32)
        attn_out[g_csr_eid[j]] = g_e[j] * inv;
}

// ---------------- launch (single stream, capture-safe) ----------------
extern "C" void kernel_launch(void* const* d_in, const int* in_sizes, int n_in,
                              void* d_out, int out_size) {
    const float* h     = (const float*)d_in[0];
    const int*   src   = (const int*)  d_in[1];
    const int*   dst   = (const int*)  d_in[2];
    const float* W1    = (const float*)d_in[3];
    const float* b1    = (const float*)d_in[4];
    const float* W2    = (const float*)d_in[5];
    const float* b2    = (const float*)d_in[6];
    const float* w_src = (const float*)d_in[7];
    const float* w_dst = (const float*)d_in[8];
    float* out = (float*)d_out;

    float *p_feat0, *p_featA, *p_featB;
    cudaGetSymbolAddress((void**)&p_feat0, g_feat0);
    cudaGetSymbolAddress((void**)&p_featA, g_featA);
    cudaGetSymbolAddress((void**)&p_featB, g_featB);
    __nv_bfloat16 *p_w1hi, *p_w1lo, *p_hidhi, *p_hidlo, *p_w2hi, *p_w2lo;
    cudaGetSymbolAddress((void**)&p_w1hi,  g_W1t_hi);
    cudaGetSymbolAddress((void**)&p_w1lo,  g_W1t_lo);
    cudaGetSymbolAddress((void**)&p_hidhi, g_hid_hi);
    cudaGetSymbolAddress((void**)&p_hidlo, g_hid_lo);
    cudaGetSymbolAddress((void**)&p_w2hi,  g_W2t_hi);
    cudaGetSymbolAddress((void**)&p_w2lo,  g_W2t_lo);

    static bool attrSet = false;
    if (!attrSet) {
        cudaFuncSetAttribute(mma_gemm1_kernel,
                             cudaFuncAttributeMaxDynamicSharedMemorySize, G1_SMEM);
        attrSet = true;
    }

    const int nodeBlocks = (NN + 255) / 256;
    const int edge4Blocks = (NE / 4 + 255) / 256;
    const int warpNodeBlocks = (NN + 7) / 8;
    const int nbScan = (NN + 511) / 512;      // 98

    // graph prep
    init_zero_kernel<<<nodeBlocks, 256>>>();
    degree_kernel<<<edge4Blocks, 256>>>(src, dst);
    scan_block_kernel<<<nbScan, 512>>>();
    scan_bsum_kernel<<<1, 128>>>(nbScan);
    scan_add_kernel<<<(NN + 1 + 255) / 256, 256>>>();
    csr_fill_kernel<<<edge4Blocks, 256>>>(src, dst);

    // weight conversion + GEMMs (h conversion fused into GEMM1)
    convert_W_kernel<<<(IN_DIM * HID_DIM + HID_DIM * OUT_DIM + 255) / 256, 256>>>(W1, W2);
    {
        dim3 grid(HID_DIM / 128, (NN + 127) / 128);
        mma_gemm1_kernel<<<grid, 256, G1_SMEM>>>(
            h, p_w1hi, p_w1lo, b1, p_hidhi, p_hidlo, NN);
    }
    {
        dim3 grid(1, (NN + 127) / 128);
        mma_gemm2_kernel<<<grid, 256>>>(
            p_hidhi, p_hidlo, p_w2hi, p_w2lo, b2, p_feat0, NN);
    }

    // 4 hops: feat0 -> B -> A -> B -> (fused: sd + log_softmax, writes out)
    prop_kernel<<<warpNodeBlocks, 256>>>(p_feat0, p_featB);
    prop_kernel<<<warpNodeBlocks, 256>>>(p_featB, p_featA);
    prop_kernel<<<warpNodeBlocks, 256>>>(p_featA, p_featB);
    prop_final_kernel<<<warpNodeBlocks, 256>>>(w_src, w_dst, out);

    attn_kernel<<<warpNodeBlocks, 256>>>(out + (size_t)NN * OUT_DIM);
}

// round 16
// speedup vs baseline: 1.7381x; 1.0557x over previous
#include <cuda_runtime.h>
#include <cuda_bf16.h>
#include <math.h>

#define NN      50000
#define NE      1600000
#define IN_DIM  512
#define HID_DIM 256
#define OUT_DIM 64
#define ALPHA   0.1f

// ---------------- static device scratch (no allocations allowed) ----------------
__device__ float g_feat0 [(size_t)NN * OUT_DIM];
__device__ float g_featA [(size_t)NN * OUT_DIM];
__device__ float g_featB [(size_t)NN * OUT_DIM];
__device__ int   g_deg_out[NN];
__device__ int   g_deg_in [NN];
__device__ float g_norm_src[NN];
__device__ float g_norm_dst[NN];
__device__ int   g_ptr [NN + 1];
__device__ int   g_fill[NN];
__device__ int   g_bsum[256];
__device__ int   g_csr_src[NE];
__device__ int   g_csr_eid[NE];
__device__ float g_s[NN];
__device__ float g_d[NN];
__device__ float g_e[NE];

// bf16 split operands (W1 transposed, hidden, W2 transposed)
__device__ __nv_bfloat16 g_W1t_hi[(size_t)HID_DIM * IN_DIM];  // [N][K]
__device__ __nv_bfloat16 g_W1t_lo[(size_t)HID_DIM * IN_DIM];
__device__ __nv_bfloat16 g_hid_hi[(size_t)NN * HID_DIM];
__device__ __nv_bfloat16 g_hid_lo[(size_t)NN * HID_DIM];
__device__ __nv_bfloat16 g_W2t_hi[(size_t)OUT_DIM * HID_DIM]; // [N][K]
__device__ __nv_bfloat16 g_W2t_lo[(size_t)OUT_DIM * HID_DIM];

// ---------------- mma.sync helpers ----------------
__device__ __forceinline__ void ldsm4(unsigned& r0, unsigned& r1, unsigned& r2, unsigned& r3,
                                      unsigned addr) {
    asm volatile("ldmatrix.sync.aligned.m8n8.x4.shared.b16 {%0,%1,%2,%3}, [%4];"
                 : "=r"(r0), "=r"(r1), "=r"(r2), "=r"(r3) : "r"(addr));
}
__device__ __forceinline__ void mma_bf16(float* c, const unsigned* a, const unsigned* b) {
    asm volatile("mma.sync.aligned.m16n8k16.row.col.f32.bf16.bf16.f32 "
                 "{%0,%1,%2,%3}, {%4,%5,%6,%7}, {%8,%9}, {%0,%1,%2,%3};"
                 : "+f"(c[0]), "+f"(c[1]), "+f"(c[2]), "+f"(c[3])
                 : "r"(a[0]), "r"(a[1]), "r"(a[2]), "r"(a[3]), "r"(b[0]), "r"(b[1]));
}
__device__ __forceinline__ void cpa16(unsigned dst, const void* src) {
    asm volatile("cp.async.cg.shared.global [%0], [%1], 16;" :: "r"(dst), "l"(src));
}

// split one float into bf16 hi + lo
__device__ __forceinline__ void bsplit(float v, __nv_bfloat16& hi, __nv_bfloat16& lo) {
    hi = __float2bfloat16(v);
    lo = __float2bfloat16(v - __bfloat162float(hi));
}

// ---------------- weight conversion (W1 + W2 fused, one launch) ----------------
__global__ void convert_W_kernel(const float* __restrict__ W1, const float* __restrict__ W2) {
    int idx = blockIdx.x * blockDim.x + threadIdx.x;
    if (idx < IN_DIM * HID_DIM) {
        int k = idx >> 8;
        int n = idx & 255;
        __nv_bfloat16 hi, lo;
        bsplit(W1[idx], hi, lo);
        g_W1t_hi[(size_t)n * IN_DIM + k] = hi;
        g_W1t_lo[(size_t)n * IN_DIM + k] = lo;
    }
    int idx2 = idx - IN_DIM * HID_DIM;
    if (idx2 >= 0 && idx2 < HID_DIM * OUT_DIM) {
        int k = idx2 >> 6;
        int n = idx2 & 63;
        __nv_bfloat16 hi, lo;
        bsplit(W2[idx2], hi, lo);
        g_W2t_hi[(size_t)n * HID_DIM + k] = hi;
        g_W2t_lo[(size_t)n * HID_DIM + k] = lo;
    }
}

// ---------------- GEMM1: bf16 split-3 MMA, fused A conversion, cp.async B ----
#define SP 40                              // smem row stride (bf16), ldmatrix conflict-free
#define ARR_BYTES (128 * SP * 2)           // 10240 per tile array
#define OFF_AHI 0
#define OFF_ALO (ARR_BYTES)
#define OFF_BHI (2 * ARR_BYTES)
#define OFF_BLO (3 * ARR_BYTES)
#define STAGE_BYTES (4 * ARR_BYTES)        // 40960
#define G1_SMEM (2 * STAGE_BYTES)          // 81920

extern __shared__ __align__(16) char dynsmem[];

__global__ __launch_bounds__(256, 2) void mma_gemm1_kernel(
    const float* __restrict__ A,                                               // h [M][512] fp32
    const __nv_bfloat16* __restrict__ Bhi, const __nv_bfloat16* __restrict__ Blo,  // [N][K]
    const float* __restrict__ bias,
    __nv_bfloat16* __restrict__ Hhi, __nv_bfloat16* __restrict__ Hlo, int M) {
    const int tid = threadIdx.x;
    const int lane = tid & 31;
    const int warp = tid >> 5;
    const int warpM = warp >> 1;        // 0..3 -> 32 rows each
    const int warpN = warp & 1;         // 0..1 -> 64 cols each
    const int aBase = blockIdx.y * 128;
    const int bBase = blockIdx.x * 128;

    float acc[2][8][4] = {};

    const unsigned uBase = (unsigned)__cvta_generic_to_shared(dynsmem);

    const int aoff0 = ((warpM * 32 + (lane & 15)) * SP + (lane >> 4) * 8) * 2;
    const int aoff1 = aoff0 + 16 * SP * 2;
    const int g = lane >> 3, r = lane & 7;
    const int boff = ((warpN * 64 + r + ((g & 2) ? 8 : 0)) * SP + ((g & 1) ? 8 : 0)) * 2;

    const int lrow  = tid >> 1;          // 0..127
    const int lhalf = (tid & 1) * 16;    // col offset 0 or 16
    const bool vA = (aBase + lrow) < M;
    const float* aRow = A + (size_t)(vA ? aBase + lrow : 0) * IN_DIM + lhalf;
    const __nv_bfloat16* bRowHi = Bhi + (size_t)(bBase + lrow) * IN_DIM + lhalf;
    const __nv_bfloat16* bRowLo = Blo + (size_t)(bBase + lrow) * IN_DIM + lhalf;
    const int soff = (lrow * SP + lhalf) * 2;

    float4 a4[4];

    auto ldg_stage = [&](int ks) {
        int k0 = ks * 32;
        if (vA) {
            #pragma unroll
            for (int i = 0; i < 4; i++)
                a4[i] = *reinterpret_cast<const float4*>(aRow + k0 + i * 4);
        } else {
            #pragma unroll
            for (int i = 0; i < 4; i++) a4[i] = make_float4(0.f, 0.f, 0.f, 0.f);
        }
    };

    auto cpa_stage = [&](int ks, int buf) {
        int k0 = ks * 32;
        unsigned sb = uBase + buf * STAGE_BYTES;
        cpa16(sb + OFF_BHI + soff,      bRowHi + k0);
        cpa16(sb + OFF_BHI + soff + 16, bRowHi + k0 + 8);
        cpa16(sb + OFF_BLO + soff,      bRowLo + k0);
        cpa16(sb + OFF_BLO + soff + 16, bRowLo + k0 + 8);
        asm volatile("cp.async.commit_group;");
    };

    auto sts_stage = [&](int buf) {
        char* sb = dynsmem + buf * STAGE_BYTES;
        unsigned hp[8], lp[8];
        #pragma unroll
        for (int i = 0; i < 4; i++) {
            __nv_bfloat16 hx, hy, hz, hw, lx, ly, lz, lw;
            bsplit(a4[i].x, hx, lx); bsplit(a4[i].y, hy, ly);
            bsplit(a4[i].z, hz, lz); bsplit(a4[i].w, hw, lw);
            __nv_bfloat162 h0(hx, hy), h1(hz, hw), l0(lx, ly), l1(lz, lw);
            hp[i * 2]     = *reinterpret_cast<unsigned*>(&h0);
            hp[i * 2 + 1] = *reinterpret_cast<unsigned*>(&h1);
            lp[i * 2]     = *reinterpret_cast<unsigned*>(&l0);
            lp[i * 2 + 1] = *reinterpret_cast<unsigned*>(&l1);
        }
        *reinterpret_cast<uint4*>(sb + OFF_AHI + soff)      = make_uint4(hp[0], hp[1], hp[2], hp[3]);
        *reinterpret_cast<uint4*>(sb + OFF_AHI + soff + 16) = make_uint4(hp[4], hp[5], hp[6], hp[7]);
        *reinterpret_cast<uint4*>(sb + OFF_ALO + soff)      = make_uint4(lp[0], lp[1], lp[2], lp[3]);
        *reinterpret_cast<uint4*>(sb + OFF_ALO + soff + 16) = make_uint4(lp[4], lp[5], lp[6], lp[7]);
    };

    ldg_stage(0);
    cpa_stage(0, 0);
    sts_stage(0);
    asm volatile("cp.async.wait_group 0;");
    __syncthreads();

    const int NSTAGE = IN_DIM / 32;   // 16
    for (int ks = 0; ks < NSTAGE; ks++) {
        int buf = ks & 1;
        if (ks + 1 < NSTAGE) {
            ldg_stage(ks + 1);
            cpa_stage(ks + 1, buf ^ 1);
        }

        unsigned sb = uBase + buf * STAGE_BYTES;
        #pragma unroll
        for (int kk = 0; kk < 32; kk += 16) {
            unsigned ahi[2][4], alo[2][4], bhi[8][2], blo[8][2];
            ldsm4(ahi[0][0], ahi[0][1], ahi[0][2], ahi[0][3], sb + OFF_AHI + aoff0 + kk * 2);
            ldsm4(ahi[1][0], ahi[1][1], ahi[1][2], ahi[1][3], sb + OFF_AHI + aoff1 + kk * 2);
            ldsm4(alo[0][0], alo[0][1], alo[0][2], alo[0][3], sb + OFF_ALO + aoff0 + kk * 2);
            ldsm4(alo[1][0], alo[1][1], alo[1][2], alo[1][3], sb + OFF_ALO + aoff1 + kk * 2);
            #pragma unroll
            for (int n2 = 0; n2 < 4; n2++) {
                int off = boff + n2 * 16 * SP * 2 + kk * 2;
                ldsm4(bhi[2 * n2][0], bhi[2 * n2][1], bhi[2 * n2 + 1][0], bhi[2 * n2 + 1][1],
                      sb + OFF_BHI + off);
                ldsm4(blo[2 * n2][0], blo[2 * n2][1], blo[2 * n2 + 1][0], blo[2 * n2 + 1][1],
                      sb + OFF_BLO + off);
            }
            #pragma unroll
            for (int mi = 0; mi < 2; mi++)
                #pragma unroll
                for (int ni = 0; ni < 8; ni++) {
                    mma_bf16(acc[mi][ni], ahi[mi], bhi[ni]);   // hi*hi
                    mma_bf16(acc[mi][ni], ahi[mi], blo[ni]);   // hi*lo
                    mma_bf16(acc[mi][ni], alo[mi], bhi[ni]);   // lo*hi
                }
        }

        if (ks + 1 < NSTAGE) {
            sts_stage(buf ^ 1);
            asm volatile("cp.async.wait_group 0;");
            __syncthreads();
        }
    }

    // epilogue: bias + relu, split to bf16 hi/lo for GEMM2
    #pragma unroll
    for (int mi = 0; mi < 2; mi++) {
        #pragma unroll
        for (int ni = 0; ni < 8; ni++) {
            int gn = bBase + warpN * 64 + ni * 8 + (lane & 3) * 2;
            float2 bs = *reinterpret_cast<const float2*>(&bias[gn]);
            int gm0 = aBase + warpM * 32 + mi * 16 + (lane >> 2);
            int gm1 = gm0 + 8;
            #pragma unroll
            for (int half = 0; half < 2; half++) {
                int gm = half ? gm1 : gm0;
                if (gm >= M) continue;
                float vx = fmaxf(acc[mi][ni][half * 2 + 0] + bs.x, 0.f);
                float vy = fmaxf(acc[mi][ni][half * 2 + 1] + bs.y, 0.f);
                __nv_bfloat16 hx, hy, lx, ly;
                bsplit(vx, hx, lx);
                bsplit(vy, hy, ly);
                size_t o = (size_t)gm * HID_DIM + gn;
                *reinterpret_cast<__nv_bfloat162*>(&Hhi[o]) = __nv_bfloat162(hx, hy);
                *reinterpret_cast<__nv_bfloat162*>(&Hlo[o]) = __nv_bfloat162(lx, ly);
            }
        }
    }
}

// ---------------- GEMM2: bf16 split-3 mma.sync, 128x64 block, K=256 ----------------
__global__ __launch_bounds__(256, 2) void mma_gemm2_kernel(
    const __nv_bfloat16* __restrict__ Ahi, const __nv_bfloat16* __restrict__ Alo,
    const __nv_bfloat16* __restrict__ Bhi, const __nv_bfloat16* __restrict__ Blo,
    const float* __restrict__ bias, float* __restrict__ C, int M) {
    __shared__ __align__(16) __nv_bfloat16 sAhi[128 * SP];
    __shared__ __align__(16) __nv_bfloat16 sAlo[128 * SP];
    __shared__ __align__(16) __nv_bfloat16 sBhi[64 * SP];
    __shared__ __align__(16) __nv_bfloat16 sBlo[64 * SP];

    const int tid = threadIdx.x;
    const int lane = tid & 31;
    const int warp = tid >> 5;          // 0..7, each 16 rows x 64 cols
    const int aBase = blockIdx.y * 128;

    float acc[8][4] = {};

    const unsigned uAhi = (unsigned)__cvta_generic_to_shared(sAhi);
    const unsigned uAlo = (unsigned)__cvta_generic_to_shared(sAlo);
    const unsigned uBhi = (unsigned)__cvta_generic_to_shared(sBhi);
    const unsigned uBlo = (unsigned)__cvta_generic_to_shared(sBlo);

    const int aoff = ((warp * 16 + (lane & 15)) * SP + (lane >> 4) * 8) * 2;
    const int g = lane >> 3, r = lane & 7;
    const int boff = ((r + ((g & 2) ? 8 : 0)) * SP + ((g & 1) ? 8 : 0)) * 2;

    for (int k0 = 0; k0 < HID_DIM; k0 += 32) {
        #pragma unroll
        for (int i = 0; i < 2; i++) {
            int f = tid + i * 256;
            int row = f >> 2, seg = f & 3;
            int gm = aBase + row;
            uint4 vh = make_uint4(0, 0, 0, 0), vl = make_uint4(0, 0, 0, 0);
            if (gm < M) {
                size_t go = (size_t)gm * HID_DIM + k0 + seg * 8;
                vh = *reinterpret_cast<const uint4*>(&Ahi[go]);
                vl = *reinterpret_cast<const uint4*>(&Alo[go]);
            }
            int so = row * SP + seg * 8;
            *reinterpret_cast<uint4*>(&sAhi[so]) = vh;
            *reinterpret_cast<uint4*>(&sAlo[so]) = vl;
        }
        {
            int row = tid >> 2, seg = tid & 3;
            size_t go = (size_t)row * HID_DIM + k0 + seg * 8;
            int so = row * SP + seg * 8;
            *reinterpret_cast<uint4*>(&sBhi[so]) = *reinterpret_cast<const uint4*>(&Bhi[go]);
            *reinterpret_cast<uint4*>(&sBlo[so]) = *reinterpret_cast<const uint4*>(&Blo[go]);
        }
        __syncthreads();

        #pragma unroll
        for (int kk = 0; kk < 32; kk += 16) {
            unsigned ahi[4], alo[4], bhi[8][2], blo[8][2];
            ldsm4(ahi[0], ahi[1], ahi[2], ahi[3], uAhi + aoff + kk * 2);
            ldsm4(alo[0], alo[1], alo[2], alo[3], uAlo + aoff + kk * 2);
            #pragma unroll
            for (int n2 = 0; n2 < 4; n2++) {
                int off = boff + n2 * 16 * SP * 2 + kk * 2;
                ldsm4(bhi[2 * n2][0], bhi[2 * n2][1], bhi[2 * n2 + 1][0], bhi[2 * n2 + 1][1],
                      uBhi + off);
                ldsm4(blo[2 * n2][0], blo[2 * n2][1], blo[2 * n2 + 1][0], blo[2 * n2 + 1][1],
                      uBlo + off);
            }
            #pragma unroll
            for (int ni = 0; ni < 8; ni++) {
                mma_bf16(acc[ni], ahi, bhi[ni]);
                mma_bf16(acc[ni], ahi, blo[ni]);
                mma_bf16(acc[ni], alo, bhi[ni]);
            }
        }
        __syncthreads();
    }

    #pragma unroll
    for (int ni = 0; ni < 8; ni++) {
        int gn = ni * 8 + (lane & 3) * 2;
        float2 bs = *reinterpret_cast<const float2*>(&bias[gn]);
        int gm0 = aBase + warp * 16 + (lane >> 2);
        int gm1 = gm0 + 8;
        if (gm0 < M) {
            float2 v = make_float2(acc[ni][0] + bs.x, acc[ni][1] + bs.y);
            *reinterpret_cast<float2*>(&C[(size_t)gm0 * OUT_DIM + gn]) = v;
        }
        if (gm1 < M) {
            float2 v = make_float2(acc[ni][2] + bs.x, acc[ni][3] + bs.y);
            *reinterpret_cast<float2*>(&C[(size_t)gm1 * OUT_DIM + gn]) = v;
        }
    }
}

// ---------------- graph prep ----------------
__global__ void init_zero_kernel() {
    int i = blockIdx.x * blockDim.x + threadIdx.x;
    if (i < NN) {
        g_deg_out[i] = 0;
        g_deg_in[i]  = 0;
        g_fill[i]    = 0;
    }
}

// 4 edges/thread, int4 vector loads (NE % 4 == 0)
__global__ void degree_kernel(const int* __restrict__ src, const int* __restrict__ dst) {
    int t = blockIdx.x * blockDim.x + threadIdx.x;
    if (t >= NE / 4) return;
    int4 s4 = *reinterpret_cast<const int4*>(src + t * 4);
    int4 d4 = *reinterpret_cast<const int4*>(dst + t * 4);
    atomicAdd(&g_deg_out[s4.x], 1);
    atomicAdd(&g_deg_out[s4.y], 1);
    atomicAdd(&g_deg_out[s4.z], 1);
    atomicAdd(&g_deg_out[s4.w], 1);
    atomicAdd(&g_deg_in[d4.x], 1);
    atomicAdd(&g_deg_in[d4.y], 1);
    atomicAdd(&g_deg_in[d4.z], 1);
    atomicAdd(&g_deg_in[d4.w], 1);
}

__global__ void scan_block_kernel() {
    __shared__ int s[512];
    int tid = threadIdx.x;
    int i = blockIdx.x * 512 + tid;
    int v = (i < NN) ? g_deg_in[i] : 0;
    s[tid] = v;
    __syncthreads();
    #pragma unroll
    for (int off = 1; off < 512; off <<= 1) {
        int t = (tid >= off) ? s[tid - off] : 0;
        __syncthreads();
        s[tid] += t;
        __syncthreads();
    }
    if (i < NN) g_ptr[i] = s[tid] - v;
    if (tid == 511) g_bsum[blockIdx.x] = s[511];
}

// scan finalize (block-sum scan recomputed per block) + degree norms, fused
__global__ void scan_add_kernel(int nb) {
    __shared__ int s[128];
    __shared__ int ex[128];
    int tid = threadIdx.x;
    // first 128 threads scan the (<=128) block sums; all threads hit the syncs
    int v = 0;
    if (tid < 128) {
        v = (tid < nb) ? g_bsum[tid] : 0;
        s[tid] = v;
    }
    __syncthreads();
    #pragma unroll
    for (int off = 1; off < 128; off <<= 1) {
        int t = (tid < 128 && tid >= off) ? s[tid - off] : 0;
        __syncthreads();
        if (tid < 128) s[tid] += t;
        __syncthreads();
    }
    if (tid < 128) ex[tid] = s[tid] - v;   // exclusive
    __syncthreads();

    int i = blockIdx.x * blockDim.x + tid;
    if (i < NN) {
        g_ptr[i] += ex[i >> 9];
        g_norm_src[i] = rsqrtf((float)max(g_deg_out[i], 1));
        g_norm_dst[i] = rsqrtf((float)max(g_deg_in [i], 1));
    } else if (i == NN) {
        g_ptr[NN] = NE;
    }
}

// 4 edges/thread, int4 vector loads
__global__ void csr_fill_kernel(const int* __restrict__ src, const int* __restrict__ dst) {
    int t = blockIdx.x * blockDim.x + threadIdx.x;
    if (t >= NE / 4) return;
    int e0 = t * 4;
    int4 s4 = *reinterpret_cast<const int4*>(src + e0);
    int4 d4 = *reinterpret_cast<const int4*>(dst + e0);
    int p0 = g_ptr[d4.x] + atomicAdd(&g_fill[d4.x], 1);
    int p1 = g_ptr[d4.y] + atomicAdd(&g_fill[d4.y], 1);
    int p2 = g_ptr[d4.z] + atomicAdd(&g_fill[d4.z], 1);
    int p3 = g_ptr[d4.w] + atomicAdd(&g_fill[d4.w], 1);
    g_csr_src[p0] = s4.x; g_csr_eid[p0] = e0;
    g_csr_src[p1] = s4.y; g_csr_eid[p1] = e0 + 1;
    g_csr_src[p2] = s4.z; g_csr_eid[p2] = e0 + 2;
    g_csr_src[p3] = s4.w; g_csr_eid[p3] = e0 + 3;
}

// ---------------- propagation hop: warp per dst node, CSR gather ----------------
__global__ void prop_kernel(const float* __restrict__ fin, float* __restrict__ fout) {
    int wid  = (blockIdx.x * blockDim.x + threadIdx.x) >> 5;
    int lane = threadIdx.x & 31;
    if (wid >= NN) return;

    int beg = g_ptr[wid], end = g_ptr[wid + 1];
    float acc0 = 0.f, acc1 = 0.f;

    int j = beg;
    for (; j + 4 <= end; j += 4) {
        int s0 = g_csr_src[j + 0], s1 = g_csr_src[j + 1];
        int s2 = g_csr_src[j + 2], s3 = g_csr_src[j + 3];
        float w0 = g_norm_src[s0], w1 = g_norm_src[s1];
        float w2 = g_norm_src[s2], w3 = g_norm_src[s3];
        const float* p0 = &fin[(size_t)s0 * OUT_DIM];
        const float* p1 = &fin[(size_t)s1 * OUT_DIM];
        const float* p2 = &fin[(size_t)s2 * OUT_DIM];
        const float* p3 = &fin[(size_t)s3 * OUT_DIM];
        acc0 += w0 * p0[lane]      + w1 * p1[lane]      + w2 * p2[lane]      + w3 * p3[lane];
        acc1 += w0 * p0[lane + 32] + w1 * p1[lane + 32] + w2 * p2[lane + 32] + w3 * p3[lane + 32];
    }
    for (; j < end; ++j) {
        int s = g_csr_src[j];
        float w = g_norm_src[s];
        const float* p = &fin[(size_t)s * OUT_DIM];
        acc0 += w * p[lane];
        acc1 += w * p[lane + 32];
    }

    float nd = g_norm_dst[wid];
    size_t o = (size_t)wid * OUT_DIM;
    fout[o + lane]      = (1.0f - ALPHA) * nd * acc0 + ALPHA * g_feat0[o + lane];
    fout[o + 32 + lane] = (1.0f - ALPHA) * nd * acc1 + ALPHA * g_feat0[o + 32 + lane];
}

// ---------------- final hop fused with sd + log_softmax ----------------
__global__ void prop_final_kernel(const float* __restrict__ w_src,
                                  const float* __restrict__ w_dst,
                                  float* __restrict__ out) {
    const float* __restrict__ fin = g_featB;

    int wid  = (blockIdx.x * blockDim.x + threadIdx.x) >> 5;
    int lane = threadIdx.x & 31;
    if (wid >= NN) return;

    int beg = g_ptr[wid], end = g_ptr[wid + 1];
    float acc0 = 0.f, acc1 = 0.f;

    int j = beg;
    for (; j + 4 <= end; j += 4) {
        int s0 = g_csr_src[j + 0], s1 = g_csr_src[j + 1];
        int s2 = g_csr_src[j + 2], s3 = g_csr_src[j + 3];
        float w0 = g_norm_src[s0], w1 = g_norm_src[s1];
        float w2 = g_norm_src[s2], w3 = g_norm_src[s3];
        const float* p0 = &fin[(size_t)s0 * OUT_DIM];
        const float* p1 = &fin[(size_t)s1 * OUT_DIM];
        const float* p2 = &fin[(size_t)s2 * OUT_DIM];
        const float* p3 = &fin[(size_t)s3 * OUT_DIM];
        acc0 += w0 * p0[lane]      + w1 * p1[lane]      + w2 * p2[lane]      + w3 * p3[lane];
        acc1 += w0 * p0[lane + 32] + w1 * p1[lane + 32] + w2 * p2[lane + 32] + w3 * p3[lane + 32];
    }
    for (; j < end; ++j) {
        int s = g_csr_src[j];
        float w = g_norm_src[s];
        const float* p = &fin[(size_t)s * OUT_DIM];
        acc0 += w * p[lane];
        acc1 += w * p[lane + 32];
    }

    float nd = g_norm_dst[wid];
    size_t o = (size_t)wid * OUT_DIM;
    float f0 = (1.0f - ALPHA) * nd * acc0 + ALPHA * g_feat0[o + lane];
    float f1 = (1.0f - ALPHA) * nd * acc1 + ALPHA * g_feat0[o + 32 + lane];

    // attention dot products
    float s = f0 * w_src[lane] + f1 * w_src[lane + 32];
    float d = f0 * w_dst[lane] + f1 * w_dst[lane + 32];
    #pragma unroll
    for (int off = 16; off; off >>= 1) {
        s += __shfl_xor_sync(0xFFFFFFFFu, s, off);
        d += __shfl_xor_sync(0xFFFFFFFFu, d, off);
    }
    if (lane == 0) { g_s[wid] = s; g_d[wid] = d; }

    // log_softmax over the 64 features
    float m = fmaxf(f0, f1);
    #pragma unroll
    for (int off = 16; off; off >>= 1)
        m = fmaxf(m, __shfl_xor_sync(0xFFFFFFFFu, m, off));
    float sum = __expf(f0 - m) + __expf(f1 - m);
    #pragma unroll
    for (int off = 16; off; off >>= 1)
        sum += __shfl_xor_sync(0xFFFFFFFFu, sum, off);
    float ls = m + logf(sum);
    out[o + lane]      = f0 - ls;
    out[o + 32 + lane] = f1 - ls;
}

// ---------------- edge-softmax per dst node, 2 passes ----------------
// tanh bounded in [-1,1] -> exp in [0.37, 2.72]; max-shift pass unnecessary.
__global__ void attn_kernel(float* __restrict__ attn_out) {
    int wid  = (blockIdx.x * blockDim.x + threadIdx.x) >> 5;
    int lane = threadIdx.x & 31;
    if (wid >= NN) return;
    int beg = g_ptr[wid], end = g_ptr[wid + 1];
    if (beg == end) return;
    float dn = g_d[wid];

    float sum = 0.f;
    for (int j = beg + lane; j < end; j += 32) {
        float ex = __expf(tanhf(g_s[g_csr_src[j]] + dn));
        g_e[j] = ex;
        sum += ex;
    }
    #pragma unroll
    for (int off = 16; off; off >>= 1)
        sum += __shfl_xor_sync(0xFFFFFFFFu, sum, off);

    float inv = 1.0f / sum;
    for (int j = beg + lane; j < end; j += 32)
        attn_out[g_csr_eid[j]] = g_e[j] * inv;
}

// ---------------- launch (fork/join: prep chain overlaps GEMM chain) ----------
extern "C" void kernel_launch(void* const* d_in, const int* in_sizes, int n_in,
                              void* d_out, int out_size) {
    const float* h     = (const float*)d_in[0];
    const int*   src   = (const int*)  d_in[1];
    const int*   dst   = (const int*)  d_in[2];
    const float* W1    = (const float*)d_in[3];
    const float* b1    = (const float*)d_in[4];
    const float* W2    = (const float*)d_in[5];
    const float* b2    = (const float*)d_in[6];
    const float* w_src = (const float*)d_in[7];
    const float* w_dst = (const float*)d_in[8];
    float* out = (float*)d_out;

    float *p_feat0, *p_featA, *p_featB;
    cudaGetSymbolAddress((void**)&p_feat0, g_feat0);
    cudaGetSymbolAddress((void**)&p_featA, g_featA);
    cudaGetSymbolAddress((void**)&p_featB, g_featB);
    __nv_bfloat16 *p_w1hi, *p_w1lo, *p_hidhi, *p_hidlo, *p_w2hi, *p_w2lo;
    cudaGetSymbolAddress((void**)&p_w1hi,  g_W1t_hi);
    cudaGetSymbolAddress((void**)&p_w1lo,  g_W1t_lo);
    cudaGetSymbolAddress((void**)&p_hidhi, g_hid_hi);
    cudaGetSymbolAddress((void**)&p_hidlo, g_hid_lo);
    cudaGetSymbolAddress((void**)&p_w2hi,  g_W2t_hi);
    cudaGetSymbolAddress((void**)&p_w2lo,  g_W2t_lo);

    // One-time setup: smem attr + side stream/events. Created on the FIRST
    // (uncaptured correctness) call and cached; during graph capture they are
    // only USED (event record/wait = capturable cross-stream dependency).
    static cudaStream_t sPrep = nullptr;
    static cudaEvent_t evFork = nullptr, evJoin = nullptr;
    if (!sPrep) {
        cudaFuncSetAttribute(mma_gemm1_kernel,
                             cudaFuncAttributeMaxDynamicSharedMemorySize, G1_SMEM);
        cudaStreamCreateWithFlags(&sPrep, cudaStreamNonBlocking);
        cudaEventCreateWithFlags(&evFork, cudaEventDisableTiming);
        cudaEventCreateWithFlags(&evJoin, cudaEventDisableTiming);
    }

    const int nodeBlocks = (NN + 255) / 256;
    const int edge4Blocks = (NE / 4 + 255) / 256;
    const int warpNodeBlocks = (NN + 7) / 8;
    const int nbScan = (NN + 511) / 512;      // 98

    // fork: graph prep on sPrep (L2/atomic-bound; overlaps tensor-bound GEMMs)
    cudaEventRecord(evFork, 0);
    cudaStreamWaitEvent(sPrep, evFork, 0);
    init_zero_kernel<<<nodeBlocks, 256, 0, sPrep>>>();
    degree_kernel<<<edge4Blocks, 256, 0, sPrep>>>(src, dst);
    scan_block_kernel<<<nbScan, 512, 0, sPrep>>>();
    scan_add_kernel<<<(NN + 1 + 255) / 256, 256, 0, sPrep>>>(nbScan);
    csr_fill_kernel<<<edge4Blocks, 256, 0, sPrep>>>(src, dst);
    cudaEventRecord(evJoin, sPrep);

    // main stream: weight conversion + GEMMs (h conversion fused into GEMM1)
    convert_W_kernel<<<(IN_DIM * HID_DIM + HID_DIM * OUT_DIM + 255) / 256, 256>>>(W1, W2);
    {
        dim3 grid(HID_DIM / 128, (NN + 127) / 128);
        mma_gemm1_kernel<<<grid, 256, G1_SMEM>>>(
            h, p_w1hi, p_w1lo, b1, p_hidhi, p_hidlo, NN);
    }
    {
        dim3 grid(1, (NN + 127) / 128);
        mma_gemm2_kernel<<<grid, 256>>>(
            p_hidhi, p_hidlo, p_w2hi, p_w2lo, b2, p_feat0, NN);
    }

    // join: props need both feat0 and the CSR
    cudaStreamWaitEvent(0, evJoin, 0);

    // 4 hops: feat0 -> B -> A -> B -> (fused: sd + log_softmax, writes out)
    prop_kernel<<<warpNodeBlocks, 256>>>(p_feat0, p_featB);
    prop_kernel<<<warpNodeBlocks, 256>>>(p_featB, p_featA);
    prop_kernel<<<warpNodeBlocks, 256>>>(p_featA, p_featB);
    prop_final_kernel<<<warpNodeBlocks, 256>>>(w_src, w_dst, out);

    attn_kernel<<<warpNodeBlocks, 256>>>(out + (size_t)NN * OUT_DIM);
}

// round 17
// speedup vs baseline: 1.7829x; 1.0257x over previous
#include <cuda_runtime.h>
#include <cuda_bf16.h>
#include <cuda_fp16.h>
#include <math.h>

#define NN      50000
#define NE      1600000
#define IN_DIM  512
#define HID_DIM 256
#define OUT_DIM 64
#define ALPHA   0.1f

// ---------------- static device scratch (no allocations allowed) ----------------
__device__ float  g_feat0 [(size_t)NN * OUT_DIM];      // fp32 (alpha re-injection)
__device__ __half g_featH0[(size_t)NN * OUT_DIM];      // fp16 copies for gathers
__device__ __half g_featHA[(size_t)NN * OUT_DIM];
__device__ __half g_featHB[(size_t)NN * OUT_DIM];
__device__ int   g_deg_out[NN];
__device__ int   g_deg_in [NN];
__device__ float g_norm_src[NN];
__device__ float g_norm_dst[NN];
__device__ int   g_ptr [NN + 1];
__device__ int   g_fill[NN];
__device__ int   g_bsum[256];
__device__ int   g_csr_src[NE];
__device__ int   g_csr_eid[NE];
__device__ float g_s[NN];
__device__ float g_d[NN];
__device__ float g_e[NE];

// bf16 split operands (W1 transposed, hidden, W2 transposed)
__device__ __nv_bfloat16 g_W1t_hi[(size_t)HID_DIM * IN_DIM];  // [N][K]
__device__ __nv_bfloat16 g_W1t_lo[(size_t)HID_DIM * IN_DIM];
__device__ __nv_bfloat16 g_hid_hi[(size_t)NN * HID_DIM];
__device__ __nv_bfloat16 g_hid_lo[(size_t)NN * HID_DIM];
__device__ __nv_bfloat16 g_W2t_hi[(size_t)OUT_DIM * HID_DIM]; // [N][K]
__device__ __nv_bfloat16 g_W2t_lo[(size_t)OUT_DIM * HID_DIM];

// ---------------- mma.sync helpers ----------------
__device__ __forceinline__ void ldsm4(unsigned& r0, unsigned& r1, unsigned& r2, unsigned& r3,
                                      unsigned addr) {
    asm volatile("ldmatrix.sync.aligned.m8n8.x4.shared.b16 {%0,%1,%2,%3}, [%4];"
                 : "=r"(r0), "=r"(r1), "=r"(r2), "=r"(r3) : "r"(addr));
}
__device__ __forceinline__ void mma_bf16(float* c, const unsigned* a, const unsigned* b) {
    asm volatile("mma.sync.aligned.m16n8k16.row.col.f32.bf16.bf16.f32 "
                 "{%0,%1,%2,%3}, {%4,%5,%6,%7}, {%8,%9}, {%0,%1,%2,%3};"
                 : "+f"(c[0]), "+f"(c[1]), "+f"(c[2]), "+f"(c[3])
                 : "r"(a[0]), "r"(a[1]), "r"(a[2]), "r"(a[3]), "r"(b[0]), "r"(b[1]));
}
__device__ __forceinline__ void cpa16(unsigned dst, const void* src) {
    asm volatile("cp.async.cg.shared.global [%0], [%1], 16;" :: "r"(dst), "l"(src));
}

// split one float into bf16 hi + lo
__device__ __forceinline__ void bsplit(float v, __nv_bfloat16& hi, __nv_bfloat16& lo) {
    hi = __float2bfloat16(v);
    lo = __float2bfloat16(v - __bfloat162float(hi));
}

// ---------------- weight conversion (W1 + W2 fused, one launch) ----------------
__global__ void convert_W_kernel(const float* __restrict__ W1, const float* __restrict__ W2) {
    int idx = blockIdx.x * blockDim.x + threadIdx.x;
    if (idx < IN_DIM * HID_DIM) {
        int k = idx >> 8;
        int n = idx & 255;
        __nv_bfloat16 hi, lo;
        bsplit(W1[idx], hi, lo);
        g_W1t_hi[(size_t)n * IN_DIM + k] = hi;
        g_W1t_lo[(size_t)n * IN_DIM + k] = lo;
    }
    int idx2 = idx - IN_DIM * HID_DIM;
    if (idx2 >= 0 && idx2 < HID_DIM * OUT_DIM) {
        int k = idx2 >> 6;
        int n = idx2 & 63;
        __nv_bfloat16 hi, lo;
        bsplit(W2[idx2], hi, lo);
        g_W2t_hi[(size_t)n * HID_DIM + k] = hi;
        g_W2t_lo[(size_t)n * HID_DIM + k] = lo;
    }
}

// ---------------- GEMM1: bf16 split-3 MMA, fused A conversion, cp.async B ----
#define SP 40                              // smem row stride (bf16), ldmatrix conflict-free
#define ARR_BYTES (128 * SP * 2)           // 10240 per tile array
#define OFF_AHI 0
#define OFF_ALO (ARR_BYTES)
#define OFF_BHI (2 * ARR_BYTES)
#define OFF_BLO (3 * ARR_BYTES)
#define STAGE_BYTES (4 * ARR_BYTES)        // 40960
#define G1_SMEM (2 * STAGE_BYTES)          // 81920

extern __shared__ __align__(16) char dynsmem[];

__global__ __launch_bounds__(256, 2) void mma_gemm1_kernel(
    const float* __restrict__ A,                                               // h [M][512] fp32
    const __nv_bfloat16* __restrict__ Bhi, const __nv_bfloat16* __restrict__ Blo,  // [N][K]
    const float* __restrict__ bias,
    __nv_bfloat16* __restrict__ Hhi, __nv_bfloat16* __restrict__ Hlo, int M) {
    const int tid = threadIdx.x;
    const int lane = tid & 31;
    const int warp = tid >> 5;
    const int warpM = warp >> 1;        // 0..3 -> 32 rows each
    const int warpN = warp & 1;         // 0..1 -> 64 cols each
    const int aBase = blockIdx.y * 128;
    const int bBase = blockIdx.x * 128;

    float acc[2][8][4] = {};

    const unsigned uBase = (unsigned)__cvta_generic_to_shared(dynsmem);

    const int aoff0 = ((warpM * 32 + (lane & 15)) * SP + (lane >> 4) * 8) * 2;
    const int aoff1 = aoff0 + 16 * SP * 2;
    const int g = lane >> 3, r = lane & 7;
    const int boff = ((warpN * 64 + r + ((g & 2) ? 8 : 0)) * SP + ((g & 1) ? 8 : 0)) * 2;

    const int lrow  = tid >> 1;          // 0..127
    const int lhalf = (tid & 1) * 16;    // col offset 0 or 16
    const bool vA = (aBase + lrow) < M;
    const float* aRow = A + (size_t)(vA ? aBase + lrow : 0) * IN_DIM + lhalf;
    const __nv_bfloat16* bRowHi = Bhi + (size_t)(bBase + lrow) * IN_DIM + lhalf;
    const __nv_bfloat16* bRowLo = Blo + (size_t)(bBase + lrow) * IN_DIM + lhalf;
    const int soff = (lrow * SP + lhalf) * 2;

    float4 a4[4];

    auto ldg_stage = [&](int ks) {
        int k0 = ks * 32;
        if (vA) {
            #pragma unroll
            for (int i = 0; i < 4; i++)
                a4[i] = *reinterpret_cast<const float4*>(aRow + k0 + i * 4);
        } else {
            #pragma unroll
            for (int i = 0; i < 4; i++) a4[i] = make_float4(0.f, 0.f, 0.f, 0.f);
        }
    };

    auto cpa_stage = [&](int ks, int buf) {
        int k0 = ks * 32;
        unsigned sb = uBase + buf * STAGE_BYTES;
        cpa16(sb + OFF_BHI + soff,      bRowHi + k0);
        cpa16(sb + OFF_BHI + soff + 16, bRowHi + k0 + 8);
        cpa16(sb + OFF_BLO + soff,      bRowLo + k0);
        cpa16(sb + OFF_BLO + soff + 16, bRowLo + k0 + 8);
        asm volatile("cp.async.commit_group;");
    };

    auto sts_stage = [&](int buf) {
        char* sb = dynsmem + buf * STAGE_BYTES;
        unsigned hp[8], lp[8];
        #pragma unroll
        for (int i = 0; i < 4; i++) {
            __nv_bfloat16 hx, hy, hz, hw, lx, ly, lz, lw;
            bsplit(a4[i].x, hx, lx); bsplit(a4[i].y, hy, ly);
            bsplit(a4[i].z, hz, lz); bsplit(a4[i].w, hw, lw);
            __nv_bfloat162 h0(hx, hy), h1(hz, hw), l0(lx, ly), l1(lz, lw);
            hp[i * 2]     = *reinterpret_cast<unsigned*>(&h0);
            hp[i * 2 + 1] = *reinterpret_cast<unsigned*>(&h1);
            lp[i * 2]     = *reinterpret_cast<unsigned*>(&l0);
            lp[i * 2 + 1] = *reinterpret_cast<unsigned*>(&l1);
        }
        *reinterpret_cast<uint4*>(sb + OFF_AHI + soff)      = make_uint4(hp[0], hp[1], hp[2], hp[3]);
        *reinterpret_cast<uint4*>(sb + OFF_AHI + soff + 16) = make_uint4(hp[4], hp[5], hp[6], hp[7]);
        *reinterpret_cast<uint4*>(sb + OFF_ALO + soff)      = make_uint4(lp[0], lp[1], lp[2], lp[3]);
        *reinterpret_cast<uint4*>(sb + OFF_ALO + soff + 16) = make_uint4(lp[4], lp[5], lp[6], lp[7]);
    };

    ldg_stage(0);
    cpa_stage(0, 0);
    sts_stage(0);
    asm volatile("cp.async.wait_group 0;");
    __syncthreads();

    const int NSTAGE = IN_DIM / 32;   // 16
    for (int ks = 0; ks < NSTAGE; ks++) {
        int buf = ks & 1;
        if (ks + 1 < NSTAGE) {
            ldg_stage(ks + 1);
            cpa_stage(ks + 1, buf ^ 1);
        }

        unsigned sb = uBase + buf * STAGE_BYTES;
        #pragma unroll
        for (int kk = 0; kk < 32; kk += 16) {
            unsigned ahi[2][4], alo[2][4], bhi[8][2], blo[8][2];
            ldsm4(ahi[0][0], ahi[0][1], ahi[0][2], ahi[0][3], sb + OFF_AHI + aoff0 + kk * 2);
            ldsm4(ahi[1][0], ahi[1][1], ahi[1][2], ahi[1][3], sb + OFF_AHI + aoff1 + kk * 2);
            ldsm4(alo[0][0], alo[0][1], alo[0][2], alo[0][3], sb + OFF_ALO + aoff0 + kk * 2);
            ldsm4(alo[1][0], alo[1][1], alo[1][2], alo[1][3], sb + OFF_ALO + aoff1 + kk * 2);
            #pragma unroll
            for (int n2 = 0; n2 < 4; n2++) {
                int off = boff + n2 * 16 * SP * 2 + kk * 2;
                ldsm4(bhi[2 * n2][0], bhi[2 * n2][1], bhi[2 * n2 + 1][0], bhi[2 * n2 + 1][1],
                      sb + OFF_BHI + off);
                ldsm4(blo[2 * n2][0], blo[2 * n2][1], blo[2 * n2 + 1][0], blo[2 * n2 + 1][1],
                      sb + OFF_BLO + off);
            }
            #pragma unroll
            for (int mi = 0; mi < 2; mi++)
                #pragma unroll
                for (int ni = 0; ni < 8; ni++) {
                    mma_bf16(acc[mi][ni], ahi[mi], bhi[ni]);   // hi*hi
                    mma_bf16(acc[mi][ni], ahi[mi], blo[ni]);   // hi*lo
                    mma_bf16(acc[mi][ni], alo[mi], bhi[ni]);   // lo*hi
                }
        }

        if (ks + 1 < NSTAGE) {
            sts_stage(buf ^ 1);
            asm volatile("cp.async.wait_group 0;");
            __syncthreads();
        }
    }

    // epilogue: bias + relu, split to bf16 hi/lo for GEMM2
    #pragma unroll
    for (int mi = 0; mi < 2; mi++) {
        #pragma unroll
        for (int ni = 0; ni < 8; ni++) {
            int gn = bBase + warpN * 64 + ni * 8 + (lane & 3) * 2;
            float2 bs = *reinterpret_cast<const float2*>(&bias[gn]);
            int gm0 = aBase + warpM * 32 + mi * 16 + (lane >> 2);
            int gm1 = gm0 + 8;
            #pragma unroll
            for (int half = 0; half < 2; half++) {
                int gm = half ? gm1 : gm0;
                if (gm >= M) continue;
                float vx = fmaxf(acc[mi][ni][half * 2 + 0] + bs.x, 0.f);
                float vy = fmaxf(acc[mi][ni][half * 2 + 1] + bs.y, 0.f);
                __nv_bfloat16 hx, hy, lx, ly;
                bsplit(vx, hx, lx);
                bsplit(vy, hy, ly);
                size_t o = (size_t)gm * HID_DIM + gn;
                *reinterpret_cast<__nv_bfloat162*>(&Hhi[o]) = __nv_bfloat162(hx, hy);
                *reinterpret_cast<__nv_bfloat162*>(&Hlo[o]) = __nv_bfloat162(lx, ly);
            }
        }
    }
}

// ---------------- GEMM2: bf16 split-3 mma.sync; writes fp32 feat0 + fp16 copy --
__global__ __launch_bounds__(256, 2) void mma_gemm2_kernel(
    const __nv_bfloat16* __restrict__ Ahi, const __nv_bfloat16* __restrict__ Alo,
    const __nv_bfloat16* __restrict__ Bhi, const __nv_bfloat16* __restrict__ Blo,
    const float* __restrict__ bias, float* __restrict__ C, __half* __restrict__ CH, int M) {
    __shared__ __align__(16) __nv_bfloat16 sAhi[128 * SP];
    __shared__ __align__(16) __nv_bfloat16 sAlo[128 * SP];
    __shared__ __align__(16) __nv_bfloat16 sBhi[64 * SP];
    __shared__ __align__(16) __nv_bfloat16 sBlo[64 * SP];

    const int tid = threadIdx.x;
    const int lane = tid & 31;
    const int warp = tid >> 5;          // 0..7, each 16 rows x 64 cols
    const int aBase = blockIdx.y * 128;

    float acc[8][4] = {};

    const unsigned uAhi = (unsigned)__cvta_generic_to_shared(sAhi);
    const unsigned uAlo = (unsigned)__cvta_generic_to_shared(sAlo);
    const unsigned uBhi = (unsigned)__cvta_generic_to_shared(sBhi);
    const unsigned uBlo = (unsigned)__cvta_generic_to_shared(sBlo);

    const int aoff = ((warp * 16 + (lane & 15)) * SP + (lane >> 4) * 8) * 2;
    const int g = lane >> 3, r = lane & 7;
    const int boff = ((r + ((g & 2) ? 8 : 0)) * SP + ((g & 1) ? 8 : 0)) * 2;

    for (int k0 = 0; k0 < HID_DIM; k0 += 32) {
        #pragma unroll
        for (int i = 0; i < 2; i++) {
            int f = tid + i * 256;
            int row = f >> 2, seg = f & 3;
            int gm = aBase + row;
            uint4 vh = make_uint4(0, 0, 0, 0), vl = make_uint4(0, 0, 0, 0);
            if (gm < M) {
                size_t go = (size_t)gm * HID_DIM + k0 + seg * 8;
                vh = *reinterpret_cast<const uint4*>(&Ahi[go]);
                vl = *reinterpret_cast<const uint4*>(&Alo[go]);
            }
            int so = row * SP + seg * 8;
            *reinterpret_cast<uint4*>(&sAhi[so]) = vh;
            *reinterpret_cast<uint4*>(&sAlo[so]) = vl;
        }
        {
            int row = tid >> 2, seg = tid & 3;
            size_t go = (size_t)row * HID_DIM + k0 + seg * 8;
            int so = row * SP + seg * 8;
            *reinterpret_cast<uint4*>(&sBhi[so]) = *reinterpret_cast<const uint4*>(&Bhi[go]);
            *reinterpret_cast<uint4*>(&sBlo[so]) = *reinterpret_cast<const uint4*>(&Blo[go]);
        }
        __syncthreads();

        #pragma unroll
        for (int kk = 0; kk < 32; kk += 16) {
            unsigned ahi[4], alo[4], bhi[8][2], blo[8][2];
            ldsm4(ahi[0], ahi[1], ahi[2], ahi[3], uAhi + aoff + kk * 2);
            ldsm4(alo[0], alo[1], alo[2], alo[3], uAlo + aoff + kk * 2);
            #pragma unroll
            for (int n2 = 0; n2 < 4; n2++) {
                int off = boff + n2 * 16 * SP * 2 + kk * 2;
                ldsm4(bhi[2 * n2][0], bhi[2 * n2][1], bhi[2 * n2 + 1][0], bhi[2 * n2 + 1][1],
                      uBhi + off);
                ldsm4(blo[2 * n2][0], blo[2 * n2][1], blo[2 * n2 + 1][0], blo[2 * n2 + 1][1],
                      uBlo + off);
            }
            #pragma unroll
            for (int ni = 0; ni < 8; ni++) {
                mma_bf16(acc[ni], ahi, bhi[ni]);
                mma_bf16(acc[ni], ahi, blo[ni]);
                mma_bf16(acc[ni], alo, bhi[ni]);
            }
        }
        __syncthreads();
    }

    #pragma unroll
    for (int ni = 0; ni < 8; ni++) {
        int gn = ni * 8 + (lane & 3) * 2;
        float2 bs = *reinterpret_cast<const float2*>(&bias[gn]);
        int gm0 = aBase + warp * 16 + (lane >> 2);
        int gm1 = gm0 + 8;
        if (gm0 < M) {
            float2 v = make_float2(acc[ni][0] + bs.x, acc[ni][1] + bs.y);
            size_t o = (size_t)gm0 * OUT_DIM + gn;
            *reinterpret_cast<float2*>(&C[o]) = v;
            *reinterpret_cast<__half2*>(&CH[o]) = __floats2half2_rn(v.x, v.y);
        }
        if (gm1 < M) {
            float2 v = make_float2(acc[ni][2] + bs.x, acc[ni][3] + bs.y);
            size_t o = (size_t)gm1 * OUT_DIM + gn;
            *reinterpret_cast<float2*>(&C[o]) = v;
            *reinterpret_cast<__half2*>(&CH[o]) = __floats2half2_rn(v.x, v.y);
        }
    }
}

// ---------------- graph prep ----------------
__global__ void init_zero_kernel() {
    int i = blockIdx.x * blockDim.x + threadIdx.x;
    if (i < NN) {
        g_deg_out[i] = 0;
        g_deg_in[i]  = 0;
        g_fill[i]    = 0;
    }
}

// 4 edges/thread, int4 vector loads (NE % 4 == 0)
__global__ void degree_kernel(const int* __restrict__ src, const int* __restrict__ dst) {
    int t = blockIdx.x * blockDim.x + threadIdx.x;
    if (t >= NE / 4) return;
    int4 s4 = *reinterpret_cast<const int4*>(src + t * 4);
    int4 d4 = *reinterpret_cast<const int4*>(dst + t * 4);
    atomicAdd(&g_deg_out[s4.x], 1);
    atomicAdd(&g_deg_out[s4.y], 1);
    atomicAdd(&g_deg_out[s4.z], 1);
    atomicAdd(&g_deg_out[s4.w], 1);
    atomicAdd(&g_deg_in[d4.x], 1);
    atomicAdd(&g_deg_in[d4.y], 1);
    atomicAdd(&g_deg_in[d4.z], 1);
    atomicAdd(&g_deg_in[d4.w], 1);
}

__global__ void scan_block_kernel() {
    __shared__ int s[512];
    int tid = threadIdx.x;
    int i = blockIdx.x * 512 + tid;
    int v = (i < NN) ? g_deg_in[i] : 0;
    s[tid] = v;
    __syncthreads();
    #pragma unroll
    for (int off = 1; off < 512; off <<= 1) {
        int t = (tid >= off) ? s[tid - off] : 0;
        __syncthreads();
        s[tid] += t;
        __syncthreads();
    }
    if (i < NN) g_ptr[i] = s[tid] - v;
    if (tid == 511) g_bsum[blockIdx.x] = s[511];
}

// scan finalize (block-sum scan recomputed per block) + degree norms, fused
__global__ void scan_add_kernel(int nb) {
    __shared__ int s[128];
    __shared__ int ex[128];
    int tid = threadIdx.x;
    int v = 0;
    if (tid < 128) {
        v = (tid < nb) ? g_bsum[tid] : 0;
        s[tid] = v;
    }
    __syncthreads();
    #pragma unroll
    for (int off = 1; off < 128; off <<= 1) {
        int t = (tid < 128 && tid >= off) ? s[tid - off] : 0;
        __syncthreads();
        if (tid < 128) s[tid] += t;
        __syncthreads();
    }
    if (tid < 128) ex[tid] = s[tid] - v;   // exclusive
    __syncthreads();

    int i = blockIdx.x * blockDim.x + tid;
    if (i < NN) {
        g_ptr[i] += ex[i >> 9];
        g_norm_src[i] = rsqrtf((float)max(g_deg_out[i], 1));
        g_norm_dst[i] = rsqrtf((float)max(g_deg_in [i], 1));
    } else if (i == NN) {
        g_ptr[NN] = NE;
    }
}

// 4 edges/thread, int4 vector loads
__global__ void csr_fill_kernel(const int* __restrict__ src, const int* __restrict__ dst) {
    int t = blockIdx.x * blockDim.x + threadIdx.x;
    if (t >= NE / 4) return;
    int e0 = t * 4;
    int4 s4 = *reinterpret_cast<const int4*>(src + e0);
    int4 d4 = *reinterpret_cast<const int4*>(dst + e0);
    int p0 = g_ptr[d4.x] + atomicAdd(&g_fill[d4.x], 1);
    int p1 = g_ptr[d4.y] + atomicAdd(&g_fill[d4.y], 1);
    int p2 = g_ptr[d4.z] + atomicAdd(&g_fill[d4.z], 1);
    int p3 = g_ptr[d4.w] + atomicAdd(&g_fill[d4.w], 1);
    g_csr_src[p0] = s4.x; g_csr_eid[p0] = e0;
    g_csr_src[p1] = s4.y; g_csr_eid[p1] = e0 + 1;
    g_csr_src[p2] = s4.z; g_csr_eid[p2] = e0 + 2;
    g_csr_src[p3] = s4.w; g_csr_eid[p3] = e0 + 3;
}

// ---------------- propagation hop: warp per dst node, fp16 CSR gather --------
// lane covers dims (2*lane, 2*lane+1) via one __half2 load per src row.
__global__ void prop_kernel(const __half* __restrict__ fin, __half* __restrict__ fout) {
    int wid  = (blockIdx.x * blockDim.x + threadIdx.x) >> 5;
    int lane = threadIdx.x & 31;
    if (wid >= NN) return;

    int beg = g_ptr[wid], end = g_ptr[wid + 1];
    float acc0 = 0.f, acc1 = 0.f;

    int j = beg;
    for (; j + 4 <= end; j += 4) {
        int s0 = g_csr_src[j + 0], s1 = g_csr_src[j + 1];
        int s2 = g_csr_src[j + 2], s3 = g_csr_src[j + 3];
        float w0 = g_norm_src[s0], w1 = g_norm_src[s1];
        float w2 = g_norm_src[s2], w3 = g_norm_src[s3];
        float2 f0 = __half22float2(reinterpret_cast<const __half2*>(fin + (size_t)s0 * OUT_DIM)[lane]);
        float2 f1 = __half22float2(reinterpret_cast<const __half2*>(fin + (size_t)s1 * OUT_DIM)[lane]);
        float2 f2 = __half22float2(reinterpret_cast<const __half2*>(fin + (size_t)s2 * OUT_DIM)[lane]);
        float2 f3 = __half22float2(reinterpret_cast<const __half2*>(fin + (size_t)s3 * OUT_DIM)[lane]);
        acc0 += w0 * f0.x + w1 * f1.x + w2 * f2.x + w3 * f3.x;
        acc1 += w0 * f0.y + w1 * f1.y + w2 * f2.y + w3 * f3.y;
    }
    for (; j < end; ++j) {
        int s = g_csr_src[j];
        float w = g_norm_src[s];
        float2 f = __half22float2(reinterpret_cast<const __half2*>(fin + (size_t)s * OUT_DIM)[lane]);
        acc0 += w * f.x;
        acc1 += w * f.y;
    }

    float nd = g_norm_dst[wid];
    size_t o = (size_t)wid * OUT_DIM;
    float2 base = *reinterpret_cast<const float2*>(g_feat0 + o + 2 * lane);
    float r0 = (1.0f - ALPHA) * nd * acc0 + ALPHA * base.x;
    float r1 = (1.0f - ALPHA) * nd * acc1 + ALPHA * base.y;
    reinterpret_cast<__half2*>(fout + o)[lane] = __floats2half2_rn(r0, r1);
}

// ---------------- final hop fused with sd + log_softmax (fp16 gather) --------
__global__ void prop_final_kernel(const float* __restrict__ w_src,
                                  const float* __restrict__ w_dst,
                                  float* __restrict__ out) {
    const __half* __restrict__ fin = g_featHB;

    int wid  = (blockIdx.x * blockDim.x + threadIdx.x) >> 5;
    int lane = threadIdx.x & 31;
    if (wid >= NN) return;

    int beg = g_ptr[wid], end = g_ptr[wid + 1];
    float acc0 = 0.f, acc1 = 0.f;

    int j = beg;
    for (; j + 4 <= end; j += 4) {
        int s0 = g_csr_src[j + 0], s1 = g_csr_src[j + 1];
        int s2 = g_csr_src[j + 2], s3 = g_csr_src[j + 3];
        float w0 = g_norm_src[s0], w1 = g_norm_src[s1];
        float w2 = g_norm_src[s2], w3 = g_norm_src[s3];
        float2 f0 = __half22float2(reinterpret_cast<const __half2*>(fin + (size_t)s0 * OUT_DIM)[lane]);
        float2 f1 = __half22float2(reinterpret_cast<const __half2*>(fin + (size_t)s1 * OUT_DIM)[lane]);
        float2 f2 = __half22float2(reinterpret_cast<const __half2*>(fin + (size_t)s2 * OUT_DIM)[lane]);
        float2 f3 = __half22float2(reinterpret_cast<const __half2*>(fin + (size_t)s3 * OUT_DIM)[lane]);
        acc0 += w0 * f0.x + w1 * f1.x + w2 * f2.x + w3 * f3.x;
        acc1 += w0 * f0.y + w1 * f1.y + w2 * f2.y + w3 * f3.y;
    }
    for (; j < end; ++j) {
        int s = g_csr_src[j];
        float w = g_norm_src[s];
        float2 f = __half22float2(reinterpret_cast<const __half2*>(fin + (size_t)s * OUT_DIM)[lane]);
        acc0 += w * f.x;
        acc1 += w * f.y;
    }

    float nd = g_norm_dst[wid];
    size_t o = (size_t)wid * OUT_DIM;
    float2 base = *reinterpret_cast<const float2*>(g_feat0 + o + 2 * lane);
    float f0 = (1.0f - ALPHA) * nd * acc0 + ALPHA * base.x;   // dim 2*lane
    float f1 = (1.0f - ALPHA) * nd * acc1 + ALPHA * base.y;   // dim 2*lane+1

    // attention dot products
    float2 ws = *reinterpret_cast<const float2*>(w_src + 2 * lane);
    float2 wd = *reinterpret_cast<const float2*>(w_dst + 2 * lane);
    float s = f0 * ws.x + f1 * ws.y;
    float d = f0 * wd.x + f1 * wd.y;
    #pragma unroll
    for (int off = 16; off; off >>= 1) {
        s += __shfl_xor_sync(0xFFFFFFFFu, s, off);
        d += __shfl_xor_sync(0xFFFFFFFFu, d, off);
    }
    if (lane == 0) { g_s[wid] = s; g_d[wid] = d; }

    // log_softmax over the 64 features
    float m = fmaxf(f0, f1);
    #pragma unroll
    for (int off = 16; off; off >>= 1)
        m = fmaxf(m, __shfl_xor_sync(0xFFFFFFFFu, m, off));
    float sum = __expf(f0 - m) + __expf(f1 - m);
    #pragma unroll
    for (int off = 16; off; off >>= 1)
        sum += __shfl_xor_sync(0xFFFFFFFFu, sum, off);
    float ls = m + logf(sum);
    float2 res = make_float2(f0 - ls, f1 - ls);
    *reinterpret_cast<float2*>(out + o + 2 * lane) = res;
}

// ---------------- edge-softmax per dst node, 2 passes ----------------
// tanh bounded in [-1,1] -> exp in [0.37, 2.72]; max-shift pass unnecessary.
__global__ void attn_kernel(float* __restrict__ attn_out) {
    int wid  = (blockIdx.x * blockDim.x + threadIdx.x) >> 5;
    int lane = threadIdx.x & 31;
    if (wid >= NN) return;
    int beg = g_ptr[wid], end = g_ptr[wid + 1];
    if (beg == end) return;
    float dn = g_d[wid];

    float sum = 0.f;
    for (int j = beg + lane; j < end; j += 32) {
        float ex = __expf(tanhf(g_s[g_csr_src[j]] + dn));
        g_e[j] = ex;
        sum += ex;
    }
    #pragma unroll
    for (int off = 16; off; off >>= 1)
        sum += __shfl_xor_sync(0xFFFFFFFFu, sum, off);

    float inv = 1.0f / sum;
    for (int j = beg + lane; j < end; j += 32)
        attn_out[g_csr_eid[j]] = g_e[j] * inv;
}

// ---------------- launch (fork/join: prep chain overlaps GEMM chain) ----------
extern "C" void kernel_launch(void* const* d_in, const int* in_sizes, int n_in,
                              void* d_out, int out_size) {
    const float* h     = (const float*)d_in[0];
    const int*   src   = (const int*)  d_in[1];
    const int*   dst   = (const int*)  d_in[2];
    const float* W1    = (const float*)d_in[3];
    const float* b1    = (const float*)d_in[4];
    const float* W2    = (const float*)d_in[5];
    const float* b2    = (const float*)d_in[6];
    const float* w_src = (const float*)d_in[7];
    const float* w_dst = (const float*)d_in[8];
    float* out = (float*)d_out;

    float *p_feat0;
    __half *p_featH0, *p_featHA, *p_featHB;
    cudaGetSymbolAddress((void**)&p_feat0,  g_feat0);
    cudaGetSymbolAddress((void**)&p_featH0, g_featH0);
    cudaGetSymbolAddress((void**)&p_featHA, g_featHA);
    cudaGetSymbolAddress((void**)&p_featHB, g_featHB);
    __nv_bfloat16 *p_w1hi, *p_w1lo, *p_hidhi, *p_hidlo, *p_w2hi, *p_w2lo;
    cudaGetSymbolAddress((void**)&p_w1hi,  g_W1t_hi);
    cudaGetSymbolAddress((void**)&p_w1lo,  g_W1t_lo);
    cudaGetSymbolAddress((void**)&p_hidhi, g_hid_hi);
    cudaGetSymbolAddress((void**)&p_hidlo, g_hid_lo);
    cudaGetSymbolAddress((void**)&p_w2hi,  g_W2t_hi);
    cudaGetSymbolAddress((void**)&p_w2lo,  g_W2t_lo);

    // One-time setup: smem attr + side stream/events (created on the first,
    // uncaptured call; only USED during capture).
    static cudaStream_t sPrep = nullptr;
    static cudaEvent_t evFork = nullptr, evJoin = nullptr;
    if (!sPrep) {
        cudaFuncSetAttribute(mma_gemm1_kernel,
                             cudaFuncAttributeMaxDynamicSharedMemorySize, G1_SMEM);
        cudaStreamCreateWithFlags(&sPrep, cudaStreamNonBlocking);
        cudaEventCreateWithFlags(&evFork, cudaEventDisableTiming);
        cudaEventCreateWithFlags(&evJoin, cudaEventDisableTiming);
    }

    const int nodeBlocks = (NN + 255) / 256;
    const int edge4Blocks = (NE / 4 + 255) / 256;
    const int warpNodeBlocks = (NN + 7) / 8;
    const int nbScan = (NN + 511) / 512;      // 98

    // fork: graph prep on sPrep (L2/atomic-bound; overlaps tensor-bound GEMMs)
    cudaEventRecord(evFork, 0);
    cudaStreamWaitEvent(sPrep, evFork, 0);
    init_zero_kernel<<<nodeBlocks, 256, 0, sPrep>>>();
    degree_kernel<<<edge4Blocks, 256, 0, sPrep>>>(src, dst);
    scan_block_kernel<<<nbScan, 512, 0, sPrep>>>();
    scan_add_kernel<<<(NN + 1 + 255) / 256, 256, 0, sPrep>>>(nbScan);
    csr_fill_kernel<<<edge4Blocks, 256, 0, sPrep>>>(src, dst);
    cudaEventRecord(evJoin, sPrep);

    // main stream: weight conversion + GEMMs (h conversion fused into GEMM1)
    convert_W_kernel<<<(IN_DIM * HID_DIM + HID_DIM * OUT_DIM + 255) / 256, 256>>>(W1, W2);
    {
        dim3 grid(HID_DIM / 128, (NN + 127) / 128);
        mma_gemm1_kernel<<<grid, 256, G1_SMEM>>>(
            h, p_w1hi, p_w1lo, b1, p_hidhi, p_hidlo, NN);
    }
    {
        dim3 grid(1, (NN + 127) / 128);
        mma_gemm2_kernel<<<grid, 256>>>(
            p_hidhi, p_hidlo, p_w2hi, p_w2lo, b2, p_feat0, p_featH0, NN);
    }

    // join: props need both feat0/featH0 and the CSR
    cudaStreamWaitEvent(0, evJoin, 0);

    // 4 hops: H0 -> HB -> HA -> HB -> (fused final: sd + log_softmax, writes out)
    prop_kernel<<<warpNodeBlocks, 256>>>(p_featH0, p_featHB);
    prop_kernel<<<warpNodeBlocks, 256>>>(p_featHB, p_featHA);
    prop_kernel<<<warpNodeBlocks, 256>>>(p_featHA, p_featHB);
    prop_final_kernel<<<warpNodeBlocks, 256>>>(w_src, w_dst, out);

    attn_kernel<<<warpNodeBlocks, 256>>>(out + (size_t)NN * OUT_DIM);
}